// round 7
// baseline (speedup 1.0000x reference)
#include <cuda_runtime.h>
#include <cuda_bf16.h>
#include <stdint.h>
#include <math.h>

// x: [B=4, 2048, 2048] fp32.
// out[b,u,v] = sum_{p,q} x[b,p,q] * sin(pi*(2u+1)*p/4096) * cos(pi*(2v+1)*q/4096)
//
// Parity fold (one butterfly level):
//   C[2047-v, q] = (-1)^q C[v,q],  S[2047-u, p] = -(-1)^p S[u,p]
// Stage 1: E1[v',p] = sum_{qe} Ce[v',qe] Xe[p,qe],  O1[v',p] = sum_{qo} Co[v',qo] Xo[p,qo]
//          T'[v',p] = E1+O1,  T'[2047-v',p] = E1-O1      (v' in [0,1024))
// Stage 2: E2[u',v] = sum_{pe} Se[u',pe] Te[v,pe],  O2 = sum So[u',po] To[v,po]
//          out[u',v] = E2+O2,  out[2047-u',v] = O2-E2
// fp32 operands split into bf16 hi+lo; 3 HMMA terms per k16 (hh + hl + lh).
// E and O accumulate in two register accumulator sets (no SMEM stash);
// 3-stage cp.async pipeline, one __syncthreads per chunk.

#define NQ 2048
#define KH 1024
#define NB 4
typedef __nv_bfloat16 bf16;

// ---------------- device scratch (allocation-free rule) ----------------
__device__ __align__(256) bf16 g_Ce_h[KH * KH];
__device__ __align__(256) bf16 g_Ce_l[KH * KH];
__device__ __align__(256) bf16 g_Co_h[KH * KH];
__device__ __align__(256) bf16 g_Co_l[KH * KH];
__device__ __align__(256) bf16 g_Se_h[KH * KH];
__device__ __align__(256) bf16 g_Se_l[KH * KH];
__device__ __align__(256) bf16 g_So_h[KH * KH];
__device__ __align__(256) bf16 g_So_l[KH * KH];
__device__ __align__(256) bf16 g_Xe_h[(size_t)NB * NQ * KH];
__device__ __align__(256) bf16 g_Xe_l[(size_t)NB * NQ * KH];
__device__ __align__(256) bf16 g_Xo_h[(size_t)NB * NQ * KH];
__device__ __align__(256) bf16 g_Xo_l[(size_t)NB * NQ * KH];
__device__ __align__(256) bf16 g_Te_h[(size_t)NB * NQ * KH];
__device__ __align__(256) bf16 g_Te_l[(size_t)NB * NQ * KH];
__device__ __align__(256) bf16 g_To_h[(size_t)NB * NQ * KH];
__device__ __align__(256) bf16 g_To_l[(size_t)NB * NQ * KH];

// ---------------- helpers ----------------
__device__ __forceinline__ uint32_t smem_u32(const void* p) {
    uint32_t a;
    asm("{ .reg .u64 t; cvta.to.shared.u64 t, %1; cvt.u32.u64 %0, t; }"
        : "=r"(a) : "l"(p));
    return a;
}
__device__ __forceinline__ uint32_t sw128(uint32_t off) { return off ^ ((off >> 3) & 0x70); }

#define CP16(saddr, gptr) \
    asm volatile("cp.async.cg.shared.global [%0], [%1], 16;" \
                 :: "r"(saddr), "l"(gptr) : "memory")
#define CP_COMMIT() asm volatile("cp.async.commit_group;" ::: "memory")
#define CP_WAIT1() asm volatile("cp.async.wait_group 1;" ::: "memory")
#define CP_WAIT0() asm volatile("cp.async.wait_group 0;" ::: "memory")

#define LDM4(d, addr) \
    asm volatile("ldmatrix.sync.aligned.m8n8.x4.shared.b16 {%0,%1,%2,%3}, [%4];" \
                 : "=r"((d)[0]), "=r"((d)[1]), "=r"((d)[2]), "=r"((d)[3]) : "r"(addr))

#define MMA16816(c, a, b0v, b1v) \
    asm volatile("mma.sync.aligned.m16n8k16.row.col.f32.bf16.bf16.f32 " \
                 "{%0,%1,%2,%3}, {%4,%5,%6,%7}, {%8,%9}, {%0,%1,%2,%3};" \
                 : "+f"((c)[0]), "+f"((c)[1]), "+f"((c)[2]), "+f"((c)[3]) \
                 : "r"((a)[0]), "r"((a)[1]), "r"((a)[2]), "r"((a)[3]), \
                   "r"(b0v), "r"(b1v))

__device__ __forceinline__ void put_split(bf16* __restrict__ H, bf16* __restrict__ L,
                                          size_t off, float v) {
    bf16 h = __float2bfloat16(v);
    H[off] = h;
    L[off] = __float2bfloat16(v - __bfloat162float(h));
}

// ---------------- prologue kernels ----------------
__global__ void gen_basis_split() {
    int idx = blockIdx.x * blockDim.x + threadIdx.x;
    if (idx >= KH * KH) return;
    int v = idx >> 10, k = idx & 1023;
    // (2v+1)*(2k+1) <= 2047*2047 < 2^22: exact in fp32
    float ae = (float)((2 * v + 1) * (2 * k)) * (1.0f / 4096.0f);
    float ao = (float)((2 * v + 1) * (2 * k + 1)) * (1.0f / 4096.0f);
    float ce, se, co, so;
    sincospif(ae, &se, &ce);
    sincospif(ao, &so, &co);
    put_split(g_Ce_h, g_Ce_l, idx, ce);
    put_split(g_Co_h, g_Co_l, idx, co);
    put_split(g_Se_h, g_Se_l, idx, se);
    put_split(g_So_h, g_So_l, idx, so);
}

__global__ void split_x(const float* __restrict__ x) {
    size_t i = (size_t)blockIdx.x * blockDim.x + threadIdx.x;  // 8 floats / thread
    const size_t total = (size_t)NB * NQ * NQ / 8;
    if (i >= total) return;
    float4 v0 = ((const float4*)x)[2 * i];
    float4 v1 = ((const float4*)x)[2 * i + 1];
    float ev[4] = {v0.x, v0.z, v1.x, v1.z};
    float od[4] = {v0.y, v0.w, v1.y, v1.w};
    bf16 eh[4], el[4], oh[4], ol[4];
#pragma unroll
    for (int k = 0; k < 4; ++k) {
        eh[k] = __float2bfloat16(ev[k]);
        el[k] = __float2bfloat16(ev[k] - __bfloat162float(eh[k]));
        oh[k] = __float2bfloat16(od[k]);
        ol[k] = __float2bfloat16(od[k] - __bfloat162float(oh[k]));
    }
    uint2 ueh, uel, uoh, uol;
    { __nv_bfloat162 p0 = __halves2bfloat162(eh[0], eh[1]), p1 = __halves2bfloat162(eh[2], eh[3]);
      ueh.x = *(uint32_t*)&p0; ueh.y = *(uint32_t*)&p1; }
    { __nv_bfloat162 p0 = __halves2bfloat162(el[0], el[1]), p1 = __halves2bfloat162(el[2], el[3]);
      uel.x = *(uint32_t*)&p0; uel.y = *(uint32_t*)&p1; }
    { __nv_bfloat162 p0 = __halves2bfloat162(oh[0], oh[1]), p1 = __halves2bfloat162(oh[2], oh[3]);
      uoh.x = *(uint32_t*)&p0; uoh.y = *(uint32_t*)&p1; }
    { __nv_bfloat162 p0 = __halves2bfloat162(ol[0], ol[1]), p1 = __halves2bfloat162(ol[2], ol[3]);
      uol.x = *(uint32_t*)&p0; uol.y = *(uint32_t*)&p1; }
    ((uint2*)g_Xe_h)[i] = ueh;
    ((uint2*)g_Xe_l)[i] = uel;
    ((uint2*)g_Xo_h)[i] = uoh;
    ((uint2*)g_Xo_l)[i] = uol;
}

// ---------------- main GEMM kernel ----------------
// Block tile 128x128, BK=64, lda=ldb=KH. SMEM: 3 buffers x 64KB
// (Ahi|Alo|Bhi|Blo tiles, each 128 x 64 bf16, 128B rows, SW128).
// Chunks 0-15: even operands -> acc_e; 16-31: odd operands -> acc_o.
#define TILE_BYTES 16384
#define BUF_BYTES  (4 * TILE_BYTES)                // 65536
#define SMEM_TOTAL (3 * BUF_BYTES)                 // 196608
#define NCHUNK     32

__device__ __forceinline__ void load_chunk(uint32_t sbuf,
                                           const bf16* __restrict__ Ah,
                                           const bf16* __restrict__ Al,
                                           const bf16* __restrict__ Bh,
                                           const bf16* __restrict__ Bl,
                                           int m0, int n0, int k0, int tid) {
#pragma unroll
    for (int j = 0; j < 4; ++j) {
        int e = tid + 256 * j;           // 0..1023
        int r = e >> 3, c = e & 7;       // row 0..127, 16B chunk 0..7
        uint32_t soff = sw128((uint32_t)(r * 128 + c * 16));
        size_t gA = (size_t)(m0 + r) * KH + k0 + c * 8;
        size_t gB = (size_t)(n0 + r) * KH + k0 + c * 8;
        CP16(sbuf + soff,                  Ah + gA);
        CP16(sbuf + TILE_BYTES + soff,     Al + gA);
        CP16(sbuf + 2 * TILE_BYTES + soff, Bh + gB);
        CP16(sbuf + 3 * TILE_BYTES + soff, Bl + gB);
    }
}

__device__ __forceinline__ uint32_t a_addr(uint32_t buf, int mt, int s, int lane) {
    int sub = lane >> 3;
    int r = mt + ((sub & 1) << 3) + (lane & 7);
    int c = 2 * s + (sub >> 1);
    return buf + sw128((uint32_t)(r * 128 + c * 16));
}
__device__ __forceinline__ uint32_t b_addr(uint32_t buf, int nt, int s, int lane) {
    int sub = lane >> 3;
    int r = nt + ((sub >> 1) << 3) + (lane & 7);
    int c = 2 * s + (sub & 1);
    return buf + sw128((uint32_t)(r * 128 + c * 16));
}

// 4 k16 steps of the 3-term split-bf16 MMA from buffer bAh.., into ACC.
#define COMPUTE_CHUNK(ACC, bAh, bAl, bBh, bBl)                                    \
    _Pragma("unroll")                                                             \
    for (int s = 0; s < 4; ++s) {                                                 \
        uint32_t ah[4][4], al[4][4], bh[2][4], bl[2][4];                          \
        _Pragma("unroll")                                                         \
        for (int mi = 0; mi < 4; ++mi) {                                          \
            LDM4(ah[mi], a_addr(bAh, wm * 64 + mi * 16, s, lane));                \
            LDM4(al[mi], a_addr(bAl, wm * 64 + mi * 16, s, lane));                \
        }                                                                         \
        _Pragma("unroll")                                                         \
        for (int nj = 0; nj < 2; ++nj) {                                          \
            LDM4(bh[nj], b_addr(bBh, wn * 32 + nj * 16, s, lane));                \
            LDM4(bl[nj], b_addr(bBl, wn * 32 + nj * 16, s, lane));                \
        }                                                                         \
        _Pragma("unroll")                                                         \
        for (int mi = 0; mi < 4; ++mi)                                            \
            _Pragma("unroll")                                                     \
            for (int ni = 0; ni < 4; ++ni) {                                      \
                const int nj = ni >> 1, nh = (ni & 1) * 2;                        \
                MMA16816(ACC[mi][ni], ah[mi], bh[nj][nh], bh[nj][nh + 1]);        \
                MMA16816(ACC[mi][ni], ah[mi], bl[nj][nh], bl[nj][nh + 1]);        \
                MMA16816(ACC[mi][ni], al[mi], bh[nj][nh], bh[nj][nh + 1]);        \
            }                                                                     \
    }

template <int STAGE>
__global__ void __launch_bounds__(256, 1)
idsct_fold_kernel(const bf16* __restrict__ Aeh, const bf16* __restrict__ Ael,
                  const bf16* __restrict__ Aoh, const bf16* __restrict__ Aol,
                  const bf16* __restrict__ Beh, const bf16* __restrict__ Bel,
                  const bf16* __restrict__ Boh, const bf16* __restrict__ Bol,
                  bf16* __restrict__ Teh, bf16* __restrict__ Tel,
                  bf16* __restrict__ Toh, bf16* __restrict__ Tol,
                  float* __restrict__ OutF) {
    extern __shared__ char smem[];
    const uint32_t sbase = smem_u32(smem);
    const int tid = threadIdx.x, wid = tid >> 5, lane = tid & 31;
    const int wm = wid & 1;          // 2 warp rows  -> 64 M each
    const int wn = wid >> 1;         // 4 warp cols  -> 32 N each
    const int m0 = blockIdx.y * 128; // [0,1024)
    const int n0 = blockIdx.x * 128; // [0,2048)
    const int b  = blockIdx.z;
    const size_t plane = (size_t)NQ * KH;
    const bf16* pBeh = Beh + (size_t)b * plane;
    const bf16* pBel = Bel + (size_t)b * plane;
    const bf16* pBoh = Boh + (size_t)b * plane;
    const bf16* pBol = Bol + (size_t)b * plane;

    float acc_e[4][4][4], acc_o[4][4][4];
#pragma unroll
    for (int i = 0; i < 4; ++i)
#pragma unroll
        for (int j = 0; j < 4; ++j)
#pragma unroll
            for (int q = 0; q < 4; ++q) { acc_e[i][j][q] = 0.0f; acc_o[i][j][q] = 0.0f; }

    // 3-stage pipeline prologue: chunks 0,1 (both even-pass)
    load_chunk(sbase,             Aeh, Ael, pBeh, pBel, m0, n0, 0,  tid);
    CP_COMMIT();
    load_chunk(sbase + BUF_BYTES, Aeh, Ael, pBeh, pBel, m0, n0, 64, tid);
    CP_COMMIT();

    for (int ci = 0; ci < NCHUNK; ++ci) {
        if (ci == NCHUNK - 1) { CP_WAIT0(); } else { CP_WAIT1(); }
        __syncthreads();

        // issue chunk ci+2 into buffer (ci+2)%3 (read last at iter ci-1; the
        // barrier above orders those reads before these writes)
        const int nc = ci + 2;
        if (nc < NCHUNK) {
            const uint32_t nbuf = sbase + (uint32_t)(nc % 3) * BUF_BYTES;
            const int k0n = (nc & 15) * 64;
            if (nc < 16)
                load_chunk(nbuf, Aeh, Ael, pBeh, pBel, m0, n0, k0n, tid);
            else
                load_chunk(nbuf, Aoh, Aol, pBoh, pBol, m0, n0, k0n, tid);
            CP_COMMIT();
        }

        const uint32_t bAh = sbase + (uint32_t)(ci % 3) * BUF_BYTES;
        const uint32_t bAl = bAh + TILE_BYTES;
        const uint32_t bBh = bAh + 2 * TILE_BYTES;
        const uint32_t bBl = bAh + 3 * TILE_BYTES;

        if (ci < 16) {
            COMPUTE_CHUNK(acc_e, bAh, bAl, bBh, bBl);
        } else {
            COMPUTE_CHUNK(acc_o, bAh, bAl, bBh, bBl);
        }
    }

    // epilogue. quad mapping: c0,c1 = (row rq, cols cq,cq+1); c2,c3 = (rq+8, same)
    const int rq = lane >> 2, cq = (lane & 3) * 2;
    const int rbase = m0 + wm * 64;   // row in [0,1024)
    const int cbase = n0 + wn * 32;
#pragma unroll
    for (int mi = 0; mi < 4; ++mi)
#pragma unroll
        for (int ni = 0; ni < 4; ++ni) {
            const float e0 = acc_e[mi][ni][0], e1 = acc_e[mi][ni][1];
            const float e2 = acc_e[mi][ni][2], e3 = acc_e[mi][ni][3];
            const float o0 = acc_o[mi][ni][0], o1 = acc_o[mi][ni][1];
            const float o2 = acc_o[mi][ni][2], o3 = acc_o[mi][ni][3];
            const int r0 = rbase + mi * 16 + rq;   // [0,1024)
            const int r1 = r0 + 8;
            const int p0 = cbase + ni * 8 + cq;    // even column index
            if (STAGE == 1) {
                // T'[v,p]: top v=r, bottom v=2047-r; parity-pack over p.
                const size_t pe = (size_t)(p0 >> 1);
                const size_t tb = (size_t)b * plane;
                const size_t t0 = tb + (size_t)r0 * KH + pe;
                const size_t b0 = tb + (size_t)(2047 - r0) * KH + pe;
                const size_t t1 = tb + (size_t)r1 * KH + pe;
                const size_t b1 = tb + (size_t)(2047 - r1) * KH + pe;
                put_split(Teh, Tel, t0, e0 + o0);   // (r0, p even) top
                put_split(Toh, Tol, t0, e1 + o1);   // (r0, p odd)  top
                put_split(Teh, Tel, b0, e0 - o0);   // bottom
                put_split(Toh, Tol, b0, e1 - o1);
                put_split(Teh, Tel, t1, e2 + o2);
                put_split(Toh, Tol, t1, e3 + o3);
                put_split(Teh, Tel, b1, e2 - o2);
                put_split(Toh, Tol, b1, e3 - o3);
            } else {
                // out[u,v]: top u=r -> E+O; bottom u=2047-r -> O-E. cols v.
                const size_t ob = (size_t)b * NQ * NQ;
                const size_t c = (size_t)p0;
                float2 vt0 = make_float2(e0 + o0, e1 + o1);
                float2 vb0 = make_float2(o0 - e0, o1 - e1);
                float2 vt1 = make_float2(e2 + o2, e3 + o3);
                float2 vb1 = make_float2(o2 - e2, o3 - e3);
                *(float2*)(OutF + ob + (size_t)r0 * NQ + c) = vt0;
                *(float2*)(OutF + ob + (size_t)(2047 - r0) * NQ + c) = vb0;
                *(float2*)(OutF + ob + (size_t)r1 * NQ + c) = vt1;
                *(float2*)(OutF + ob + (size_t)(2047 - r1) * NQ + c) = vb1;
            }
        }
}

// ---------------- launch ----------------
extern "C" void kernel_launch(void* const* d_in, const int* in_sizes, int n_in,
                              void* d_out, int out_size) {
    const float* x = (const float*)d_in[0];
    float* out = (float*)d_out;

    bf16 *pCeh, *pCel, *pCoh, *pCol, *pSeh, *pSel, *pSoh, *pSol;
    bf16 *pXeh, *pXel, *pXoh, *pXol, *pTeh, *pTel, *pToh, *pTol;
    cudaGetSymbolAddress((void**)&pCeh, g_Ce_h);
    cudaGetSymbolAddress((void**)&pCel, g_Ce_l);
    cudaGetSymbolAddress((void**)&pCoh, g_Co_h);
    cudaGetSymbolAddress((void**)&pCol, g_Co_l);
    cudaGetSymbolAddress((void**)&pSeh, g_Se_h);
    cudaGetSymbolAddress((void**)&pSel, g_Se_l);
    cudaGetSymbolAddress((void**)&pSoh, g_So_h);
    cudaGetSymbolAddress((void**)&pSol, g_So_l);
    cudaGetSymbolAddress((void**)&pXeh, g_Xe_h);
    cudaGetSymbolAddress((void**)&pXel, g_Xe_l);
    cudaGetSymbolAddress((void**)&pXoh, g_Xo_h);
    cudaGetSymbolAddress((void**)&pXol, g_Xo_l);
    cudaGetSymbolAddress((void**)&pTeh, g_Te_h);
    cudaGetSymbolAddress((void**)&pTel, g_Te_l);
    cudaGetSymbolAddress((void**)&pToh, g_To_h);
    cudaGetSymbolAddress((void**)&pTol, g_To_l);

    cudaFuncSetAttribute(idsct_fold_kernel<1>, cudaFuncAttributeMaxDynamicSharedMemorySize, SMEM_TOTAL);
    cudaFuncSetAttribute(idsct_fold_kernel<2>, cudaFuncAttributeMaxDynamicSharedMemorySize, SMEM_TOTAL);

    // 1) parity-packed basis + input split
    gen_basis_split<<<(KH * KH + 255) / 256, 256>>>();
    split_x<<<(int)(((size_t)NB * NQ * NQ / 8 + 255) / 256), 256>>>(x);

    // 2) Stage 1: A = Ce/Co [1024x1024], B = Xe/Xo [b,2048,1024] -> Te/To
    idsct_fold_kernel<1><<<dim3(16, 8, NB), 256, SMEM_TOTAL>>>(
        pCeh, pCel, pCoh, pCol, pXeh, pXel, pXoh, pXol,
        pTeh, pTel, pToh, pTol, nullptr);

    // 3) Stage 2: A = Se/So, B = Te/To -> out fp32
    idsct_fold_kernel<2><<<dim3(16, 8, NB), 256, SMEM_TOTAL>>>(
        pSeh, pSel, pSoh, pSol, pTeh, pTel, pToh, pTol,
        nullptr, nullptr, nullptr, nullptr, out);
}

// round 8
// speedup vs baseline: 1.0016x; 1.0016x over previous
#include <cuda_runtime.h>
#include <cuda_bf16.h>
#include <stdint.h>
#include <math.h>

// x: [B=4, 2048, 2048] fp32.
// out[b,u,v] = sum_{p,q} x[b,p,q] * sin(pi*(2u+1)*p/4096) * cos(pi*(2v+1)*q/4096)
//
// Parity fold (one butterfly level):
//   C[2047-v, q] = (-1)^q C[v,q],  S[2047-u, p] = -(-1)^p S[u,p]
// Stage 1: E1[v',p] = sum_{qe} Ce[v',qe] Xe[p,qe],  O1[v',p] = sum_{qo} Co[v',qo] Xo[p,qo]
//          T'[v',p] = E1+O1,  T'[2047-v',p] = E1-O1      (v' in [0,1024))
// Stage 2: E2[u',v] = sum_{pe} Se[u',pe] Te[v,pe],  O2 = sum So[u',po] To[v,po]
//          out[u',v] = E2+O2,  out[2047-u',v] = O2-E2
// fp32 operands split into bf16 hi+lo; 3 HMMA terms per k16 (hh + hl + lh).
// E and O accumulate in two register accumulator sets (no SMEM stash);
// 3-stage cp.async pipeline, one __syncthreads per chunk.

#define NQ 2048
#define KH 1024
#define NB 4
typedef __nv_bfloat16 bf16;

// ---------------- device scratch (allocation-free rule) ----------------
__device__ __align__(256) bf16 g_Ce_h[KH * KH];
__device__ __align__(256) bf16 g_Ce_l[KH * KH];
__device__ __align__(256) bf16 g_Co_h[KH * KH];
__device__ __align__(256) bf16 g_Co_l[KH * KH];
__device__ __align__(256) bf16 g_Se_h[KH * KH];
__device__ __align__(256) bf16 g_Se_l[KH * KH];
__device__ __align__(256) bf16 g_So_h[KH * KH];
__device__ __align__(256) bf16 g_So_l[KH * KH];
__device__ __align__(256) bf16 g_Xe_h[(size_t)NB * NQ * KH];
__device__ __align__(256) bf16 g_Xe_l[(size_t)NB * NQ * KH];
__device__ __align__(256) bf16 g_Xo_h[(size_t)NB * NQ * KH];
__device__ __align__(256) bf16 g_Xo_l[(size_t)NB * NQ * KH];
__device__ __align__(256) bf16 g_Te_h[(size_t)NB * NQ * KH];
__device__ __align__(256) bf16 g_Te_l[(size_t)NB * NQ * KH];
__device__ __align__(256) bf16 g_To_h[(size_t)NB * NQ * KH];
__device__ __align__(256) bf16 g_To_l[(size_t)NB * NQ * KH];

// ---------------- helpers ----------------
__device__ __forceinline__ uint32_t smem_u32(const void* p) {
    uint32_t a;
    asm("{ .reg .u64 t; cvta.to.shared.u64 t, %1; cvt.u32.u64 %0, t; }"
        : "=r"(a) : "l"(p));
    return a;
}
__device__ __forceinline__ uint32_t sw128(uint32_t off) { return off ^ ((off >> 3) & 0x70); }

#define CP16(saddr, gptr) \
    asm volatile("cp.async.cg.shared.global [%0], [%1], 16;" \
                 :: "r"(saddr), "l"(gptr) : "memory")
#define CP_COMMIT() asm volatile("cp.async.commit_group;" ::: "memory")
#define CP_WAIT1() asm volatile("cp.async.wait_group 1;" ::: "memory")
#define CP_WAIT0() asm volatile("cp.async.wait_group 0;" ::: "memory")

#define LDM4(d, addr) \
    asm volatile("ldmatrix.sync.aligned.m8n8.x4.shared.b16 {%0,%1,%2,%3}, [%4];" \
                 : "=r"((d)[0]), "=r"((d)[1]), "=r"((d)[2]), "=r"((d)[3]) : "r"(addr))

#define MMA16816(c, a, b0v, b1v) \
    asm volatile("mma.sync.aligned.m16n8k16.row.col.f32.bf16.bf16.f32 " \
                 "{%0,%1,%2,%3}, {%4,%5,%6,%7}, {%8,%9}, {%0,%1,%2,%3};" \
                 : "+f"((c)[0]), "+f"((c)[1]), "+f"((c)[2]), "+f"((c)[3]) \
                 : "r"((a)[0]), "r"((a)[1]), "r"((a)[2]), "r"((a)[3]), \
                   "r"(b0v), "r"(b1v))

__device__ __forceinline__ void put_split(bf16* __restrict__ H, bf16* __restrict__ L,
                                          size_t off, float v) {
    bf16 h = __float2bfloat16(v);
    H[off] = h;
    L[off] = __float2bfloat16(v - __bfloat162float(h));
}

// ---------------- prologue kernels ----------------
__global__ void gen_basis_split() {
    int idx = blockIdx.x * blockDim.x + threadIdx.x;
    if (idx >= KH * KH) return;
    int v = idx >> 10, k = idx & 1023;
    // (2v+1)*(2k+1) <= 2047*2047 < 2^22: exact in fp32
    float ae = (float)((2 * v + 1) * (2 * k)) * (1.0f / 4096.0f);
    float ao = (float)((2 * v + 1) * (2 * k + 1)) * (1.0f / 4096.0f);
    float ce, se, co, so;
    sincospif(ae, &se, &ce);
    sincospif(ao, &so, &co);
    put_split(g_Ce_h, g_Ce_l, idx, ce);
    put_split(g_Co_h, g_Co_l, idx, co);
    put_split(g_Se_h, g_Se_l, idx, se);
    put_split(g_So_h, g_So_l, idx, so);
}

__global__ void split_x(const float* __restrict__ x) {
    size_t i = (size_t)blockIdx.x * blockDim.x + threadIdx.x;  // 8 floats / thread
    const size_t total = (size_t)NB * NQ * NQ / 8;
    if (i >= total) return;
    float4 v0 = ((const float4*)x)[2 * i];
    float4 v1 = ((const float4*)x)[2 * i + 1];
    float ev[4] = {v0.x, v0.z, v1.x, v1.z};
    float od[4] = {v0.y, v0.w, v1.y, v1.w};
    bf16 eh[4], el[4], oh[4], ol[4];
#pragma unroll
    for (int k = 0; k < 4; ++k) {
        eh[k] = __float2bfloat16(ev[k]);
        el[k] = __float2bfloat16(ev[k] - __bfloat162float(eh[k]));
        oh[k] = __float2bfloat16(od[k]);
        ol[k] = __float2bfloat16(od[k] - __bfloat162float(oh[k]));
    }
    uint2 ueh, uel, uoh, uol;
    { __nv_bfloat162 p0 = __halves2bfloat162(eh[0], eh[1]), p1 = __halves2bfloat162(eh[2], eh[3]);
      ueh.x = *(uint32_t*)&p0; ueh.y = *(uint32_t*)&p1; }
    { __nv_bfloat162 p0 = __halves2bfloat162(el[0], el[1]), p1 = __halves2bfloat162(el[2], el[3]);
      uel.x = *(uint32_t*)&p0; uel.y = *(uint32_t*)&p1; }
    { __nv_bfloat162 p0 = __halves2bfloat162(oh[0], oh[1]), p1 = __halves2bfloat162(oh[2], oh[3]);
      uoh.x = *(uint32_t*)&p0; uoh.y = *(uint32_t*)&p1; }
    { __nv_bfloat162 p0 = __halves2bfloat162(ol[0], ol[1]), p1 = __halves2bfloat162(ol[2], ol[3]);
      uol.x = *(uint32_t*)&p0; uol.y = *(uint32_t*)&p1; }
    ((uint2*)g_Xe_h)[i] = ueh;
    ((uint2*)g_Xe_l)[i] = uel;
    ((uint2*)g_Xo_h)[i] = uoh;
    ((uint2*)g_Xo_l)[i] = uol;
}

// ---------------- main GEMM kernel ----------------
// Block tile 128x128, BK=64, lda=ldb=KH. SMEM: 3 buffers x 64KB
// (Ahi|Alo|Bhi|Blo tiles, each 128 x 64 bf16, 128B rows, SW128).
// Chunks 0-15: even operands -> acc_e; 16-31: odd operands -> acc_o.
#define TILE_BYTES 16384
#define BUF_BYTES  (4 * TILE_BYTES)                // 65536
#define SMEM_TOTAL (3 * BUF_BYTES)                 // 196608
#define NCHUNK     32

__device__ __forceinline__ void load_chunk(uint32_t sbuf,
                                           const bf16* __restrict__ Ah,
                                           const bf16* __restrict__ Al,
                                           const bf16* __restrict__ Bh,
                                           const bf16* __restrict__ Bl,
                                           int m0, int n0, int k0, int tid) {
#pragma unroll
    for (int j = 0; j < 4; ++j) {
        int e = tid + 256 * j;           // 0..1023
        int r = e >> 3, c = e & 7;       // row 0..127, 16B chunk 0..7
        uint32_t soff = sw128((uint32_t)(r * 128 + c * 16));
        size_t gA = (size_t)(m0 + r) * KH + k0 + c * 8;
        size_t gB = (size_t)(n0 + r) * KH + k0 + c * 8;
        CP16(sbuf + soff,                  Ah + gA);
        CP16(sbuf + TILE_BYTES + soff,     Al + gA);
        CP16(sbuf + 2 * TILE_BYTES + soff, Bh + gB);
        CP16(sbuf + 3 * TILE_BYTES + soff, Bl + gB);
    }
}

__device__ __forceinline__ uint32_t a_addr(uint32_t buf, int mt, int s, int lane) {
    int sub = lane >> 3;
    int r = mt + ((sub & 1) << 3) + (lane & 7);
    int c = 2 * s + (sub >> 1);
    return buf + sw128((uint32_t)(r * 128 + c * 16));
}
__device__ __forceinline__ uint32_t b_addr(uint32_t buf, int nt, int s, int lane) {
    int sub = lane >> 3;
    int r = nt + ((sub >> 1) << 3) + (lane & 7);
    int c = 2 * s + (sub & 1);
    return buf + sw128((uint32_t)(r * 128 + c * 16));
}

// 4 k16 steps of the 3-term split-bf16 MMA from buffer bAh.., into ACC.
#define COMPUTE_CHUNK(ACC, bAh, bAl, bBh, bBl)                                    \
    _Pragma("unroll")                                                             \
    for (int s = 0; s < 4; ++s) {                                                 \
        uint32_t ah[4][4], al[4][4], bh[2][4], bl[2][4];                          \
        _Pragma("unroll")                                                         \
        for (int mi = 0; mi < 4; ++mi) {                                          \
            LDM4(ah[mi], a_addr(bAh, wm * 64 + mi * 16, s, lane));                \
            LDM4(al[mi], a_addr(bAl, wm * 64 + mi * 16, s, lane));                \
        }                                                                         \
        _Pragma("unroll")                                                         \
        for (int nj = 0; nj < 2; ++nj) {                                          \
            LDM4(bh[nj], b_addr(bBh, wn * 32 + nj * 16, s, lane));                \
            LDM4(bl[nj], b_addr(bBl, wn * 32 + nj * 16, s, lane));                \
        }                                                                         \
        _Pragma("unroll")                                                         \
        for (int mi = 0; mi < 4; ++mi)                                            \
            _Pragma("unroll")                                                     \
            for (int ni = 0; ni < 4; ++ni) {                                      \
                const int nj = ni >> 1, nh = (ni & 1) * 2;                        \
                MMA16816(ACC[mi][ni], ah[mi], bh[nj][nh], bh[nj][nh + 1]);        \
                MMA16816(ACC[mi][ni], ah[mi], bl[nj][nh], bl[nj][nh + 1]);        \
                MMA16816(ACC[mi][ni], al[mi], bh[nj][nh], bh[nj][nh + 1]);        \
            }                                                                     \
    }

template <int STAGE>
__global__ void __launch_bounds__(256, 1)
idsct_fold_kernel(const bf16* __restrict__ Aeh, const bf16* __restrict__ Ael,
                  const bf16* __restrict__ Aoh, const bf16* __restrict__ Aol,
                  const bf16* __restrict__ Beh, const bf16* __restrict__ Bel,
                  const bf16* __restrict__ Boh, const bf16* __restrict__ Bol,
                  bf16* __restrict__ Teh, bf16* __restrict__ Tel,
                  bf16* __restrict__ Toh, bf16* __restrict__ Tol,
                  float* __restrict__ OutF) {
    extern __shared__ char smem[];
    const uint32_t sbase = smem_u32(smem);
    const int tid = threadIdx.x, wid = tid >> 5, lane = tid & 31;
    const int wm = wid & 1;          // 2 warp rows  -> 64 M each
    const int wn = wid >> 1;         // 4 warp cols  -> 32 N each
    const int m0 = blockIdx.y * 128; // [0,1024)
    const int n0 = blockIdx.x * 128; // [0,2048)
    const int b  = blockIdx.z;
    const size_t plane = (size_t)NQ * KH;
    const bf16* pBeh = Beh + (size_t)b * plane;
    const bf16* pBel = Bel + (size_t)b * plane;
    const bf16* pBoh = Boh + (size_t)b * plane;
    const bf16* pBol = Bol + (size_t)b * plane;

    float acc_e[4][4][4], acc_o[4][4][4];
#pragma unroll
    for (int i = 0; i < 4; ++i)
#pragma unroll
        for (int j = 0; j < 4; ++j)
#pragma unroll
            for (int q = 0; q < 4; ++q) { acc_e[i][j][q] = 0.0f; acc_o[i][j][q] = 0.0f; }

    // 3-stage pipeline prologue: chunks 0,1 (both even-pass)
    load_chunk(sbase,             Aeh, Ael, pBeh, pBel, m0, n0, 0,  tid);
    CP_COMMIT();
    load_chunk(sbase + BUF_BYTES, Aeh, Ael, pBeh, pBel, m0, n0, 64, tid);
    CP_COMMIT();

    for (int ci = 0; ci < NCHUNK; ++ci) {
        if (ci == NCHUNK - 1) { CP_WAIT0(); } else { CP_WAIT1(); }
        __syncthreads();

        // issue chunk ci+2 into buffer (ci+2)%3 (read last at iter ci-1; the
        // barrier above orders those reads before these writes)
        const int nc = ci + 2;
        if (nc < NCHUNK) {
            const uint32_t nbuf = sbase + (uint32_t)(nc % 3) * BUF_BYTES;
            const int k0n = (nc & 15) * 64;
            if (nc < 16)
                load_chunk(nbuf, Aeh, Ael, pBeh, pBel, m0, n0, k0n, tid);
            else
                load_chunk(nbuf, Aoh, Aol, pBoh, pBol, m0, n0, k0n, tid);
            CP_COMMIT();
        }

        const uint32_t bAh = sbase + (uint32_t)(ci % 3) * BUF_BYTES;
        const uint32_t bAl = bAh + TILE_BYTES;
        const uint32_t bBh = bAh + 2 * TILE_BYTES;
        const uint32_t bBl = bAh + 3 * TILE_BYTES;

        if (ci < 16) {
            COMPUTE_CHUNK(acc_e, bAh, bAl, bBh, bBl);
        } else {
            COMPUTE_CHUNK(acc_o, bAh, bAl, bBh, bBl);
        }
    }

    // epilogue. quad mapping: c0,c1 = (row rq, cols cq,cq+1); c2,c3 = (rq+8, same)
    const int rq = lane >> 2, cq = (lane & 3) * 2;
    const int rbase = m0 + wm * 64;   // row in [0,1024)
    const int cbase = n0 + wn * 32;
#pragma unroll
    for (int mi = 0; mi < 4; ++mi)
#pragma unroll
        for (int ni = 0; ni < 4; ++ni) {
            const float e0 = acc_e[mi][ni][0], e1 = acc_e[mi][ni][1];
            const float e2 = acc_e[mi][ni][2], e3 = acc_e[mi][ni][3];
            const float o0 = acc_o[mi][ni][0], o1 = acc_o[mi][ni][1];
            const float o2 = acc_o[mi][ni][2], o3 = acc_o[mi][ni][3];
            const int r0 = rbase + mi * 16 + rq;   // [0,1024)
            const int r1 = r0 + 8;
            const int p0 = cbase + ni * 8 + cq;    // even column index
            if (STAGE == 1) {
                // T'[v,p]: top v=r, bottom v=2047-r; parity-pack over p.
                const size_t pe = (size_t)(p0 >> 1);
                const size_t tb = (size_t)b * plane;
                const size_t t0 = tb + (size_t)r0 * KH + pe;
                const size_t b0 = tb + (size_t)(2047 - r0) * KH + pe;
                const size_t t1 = tb + (size_t)r1 * KH + pe;
                const size_t b1 = tb + (size_t)(2047 - r1) * KH + pe;
                put_split(Teh, Tel, t0, e0 + o0);   // (r0, p even) top
                put_split(Toh, Tol, t0, e1 + o1);   // (r0, p odd)  top
                put_split(Teh, Tel, b0, e0 - o0);   // bottom
                put_split(Toh, Tol, b0, e1 - o1);
                put_split(Teh, Tel, t1, e2 + o2);
                put_split(Toh, Tol, t1, e3 + o3);
                put_split(Teh, Tel, b1, e2 - o2);
                put_split(Toh, Tol, b1, e3 - o3);
            } else {
                // out[u,v]: top u=r -> E+O; bottom u=2047-r -> O-E. cols v.
                const size_t ob = (size_t)b * NQ * NQ;
                const size_t c = (size_t)p0;
                float2 vt0 = make_float2(e0 + o0, e1 + o1);
                float2 vb0 = make_float2(o0 - e0, o1 - e1);
                float2 vt1 = make_float2(e2 + o2, e3 + o3);
                float2 vb1 = make_float2(o2 - e2, o3 - e3);
                *(float2*)(OutF + ob + (size_t)r0 * NQ + c) = vt0;
                *(float2*)(OutF + ob + (size_t)(2047 - r0) * NQ + c) = vb0;
                *(float2*)(OutF + ob + (size_t)r1 * NQ + c) = vt1;
                *(float2*)(OutF + ob + (size_t)(2047 - r1) * NQ + c) = vb1;
            }
        }
}

// ---------------- launch ----------------
extern "C" void kernel_launch(void* const* d_in, const int* in_sizes, int n_in,
                              void* d_out, int out_size) {
    const float* x = (const float*)d_in[0];
    float* out = (float*)d_out;

    bf16 *pCeh, *pCel, *pCoh, *pCol, *pSeh, *pSel, *pSoh, *pSol;
    bf16 *pXeh, *pXel, *pXoh, *pXol, *pTeh, *pTel, *pToh, *pTol;
    cudaGetSymbolAddress((void**)&pCeh, g_Ce_h);
    cudaGetSymbolAddress((void**)&pCel, g_Ce_l);
    cudaGetSymbolAddress((void**)&pCoh, g_Co_h);
    cudaGetSymbolAddress((void**)&pCol, g_Co_l);
    cudaGetSymbolAddress((void**)&pSeh, g_Se_h);
    cudaGetSymbolAddress((void**)&pSel, g_Se_l);
    cudaGetSymbolAddress((void**)&pSoh, g_So_h);
    cudaGetSymbolAddress((void**)&pSol, g_So_l);
    cudaGetSymbolAddress((void**)&pXeh, g_Xe_h);
    cudaGetSymbolAddress((void**)&pXel, g_Xe_l);
    cudaGetSymbolAddress((void**)&pXoh, g_Xo_h);
    cudaGetSymbolAddress((void**)&pXol, g_Xo_l);
    cudaGetSymbolAddress((void**)&pTeh, g_Te_h);
    cudaGetSymbolAddress((void**)&pTel, g_Te_l);
    cudaGetSymbolAddress((void**)&pToh, g_To_h);
    cudaGetSymbolAddress((void**)&pTol, g_To_l);

    cudaFuncSetAttribute(idsct_fold_kernel<1>, cudaFuncAttributeMaxDynamicSharedMemorySize, SMEM_TOTAL);
    cudaFuncSetAttribute(idsct_fold_kernel<2>, cudaFuncAttributeMaxDynamicSharedMemorySize, SMEM_TOTAL);

    // 1) parity-packed basis + input split
    gen_basis_split<<<(KH * KH + 255) / 256, 256>>>();
    split_x<<<(int)(((size_t)NB * NQ * NQ / 8 + 255) / 256), 256>>>(x);

    // 2) Stage 1: A = Ce/Co [1024x1024], B = Xe/Xo [b,2048,1024] -> Te/To
    idsct_fold_kernel<1><<<dim3(16, 8, NB), 256, SMEM_TOTAL>>>(
        pCeh, pCel, pCoh, pCol, pXeh, pXel, pXoh, pXol,
        pTeh, pTel, pToh, pTol, nullptr);

    // 3) Stage 2: A = Se/So, B = Te/To -> out fp32
    idsct_fold_kernel<2><<<dim3(16, 8, NB), 256, SMEM_TOTAL>>>(
        pSeh, pSel, pSoh, pSol, pTeh, pTel, pToh, pTol,
        nullptr, nullptr, nullptr, nullptr, out);
}

// round 9
// speedup vs baseline: 1.4545x; 1.4522x over previous
#include <cuda_runtime.h>
#include <cuda_fp16.h>
#include <stdint.h>
#include <math.h>

// x: [B=4, 2048, 2048] fp32.
// out[b,u,v] = sum_{p,q} x[b,p,q] * sin(pi*(2u+1)*p/4096) * cos(pi*(2v+1)*q/4096)
//
// Parity fold (one butterfly level):
//   C[2047-v, q] = (-1)^q C[v,q],  S[2047-u, p] = -(-1)^p S[u,p]
// Stage 1: E1[v',p] = sum_{qe} Ce[v',qe] Xe[p,qe],  O1[v',p] = sum_{qo} Co[v',qo] Xo[p,qo]
//          T'[v',p] = E1+O1,  T'[2047-v',p] = E1-O1      (v' in [0,1024))
// Stage 2: E2[u',v] = sum_{pe} Se[u',pe] Te[v,pe],  O2 = sum So[u',po] To[v,po]
//          out[u',v] = E2+O2,  out[2047-u',v] = O2-E2
//
// Precision: fp16. Basis (A side) split hi+lo; x / T (B side) fp16-hi only.
// 2 HMMA terms per k16: A_hi*B + A_lo*B. Dropped B_lo residual ~1.6e-4/stage.

#define NQ 2048
#define KH 1024
#define NB 4
typedef __half h16;

// ---------------- device scratch (allocation-free rule) ----------------
__device__ __align__(256) h16 g_Ce_h[KH * KH];
__device__ __align__(256) h16 g_Ce_l[KH * KH];
__device__ __align__(256) h16 g_Co_h[KH * KH];
__device__ __align__(256) h16 g_Co_l[KH * KH];
__device__ __align__(256) h16 g_Se_h[KH * KH];
__device__ __align__(256) h16 g_Se_l[KH * KH];
__device__ __align__(256) h16 g_So_h[KH * KH];
__device__ __align__(256) h16 g_So_l[KH * KH];
__device__ __align__(256) h16 g_Xe[(size_t)NB * NQ * KH];
__device__ __align__(256) h16 g_Xo[(size_t)NB * NQ * KH];
__device__ __align__(256) h16 g_Te[(size_t)NB * NQ * KH];
__device__ __align__(256) h16 g_To[(size_t)NB * NQ * KH];

// ---------------- helpers ----------------
__device__ __forceinline__ uint32_t smem_u32(const void* p) {
    uint32_t a;
    asm("{ .reg .u64 t; cvta.to.shared.u64 t, %1; cvt.u32.u64 %0, t; }"
        : "=r"(a) : "l"(p));
    return a;
}
__device__ __forceinline__ uint32_t sw128(uint32_t off) { return off ^ ((off >> 3) & 0x70); }

#define CP16(saddr, gptr) \
    asm volatile("cp.async.cg.shared.global [%0], [%1], 16;" \
                 :: "r"(saddr), "l"(gptr) : "memory")
#define CP_COMMIT() asm volatile("cp.async.commit_group;" ::: "memory")
#define CP_WAIT1() asm volatile("cp.async.wait_group 1;" ::: "memory")
#define CP_WAIT0() asm volatile("cp.async.wait_group 0;" ::: "memory")

#define LDM4(d, addr) \
    asm volatile("ldmatrix.sync.aligned.m8n8.x4.shared.b16 {%0,%1,%2,%3}, [%4];" \
                 : "=r"((d)[0]), "=r"((d)[1]), "=r"((d)[2]), "=r"((d)[3]) : "r"(addr))

#define MMA16816(c, a, b0v, b1v) \
    asm volatile("mma.sync.aligned.m16n8k16.row.col.f32.f16.f16.f32 " \
                 "{%0,%1,%2,%3}, {%4,%5,%6,%7}, {%8,%9}, {%0,%1,%2,%3};" \
                 : "+f"((c)[0]), "+f"((c)[1]), "+f"((c)[2]), "+f"((c)[3]) \
                 : "r"((a)[0]), "r"((a)[1]), "r"((a)[2]), "r"((a)[3]), \
                   "r"(b0v), "r"(b1v))

__device__ __forceinline__ void put_split(h16* __restrict__ H, h16* __restrict__ L,
                                          size_t off, float v) {
    h16 h = __float2half(v);
    H[off] = h;
    L[off] = __float2half(v - __half2float(h));
}

// ---------------- prologue kernels ----------------
__global__ void gen_basis_split() {
    int idx = blockIdx.x * blockDim.x + threadIdx.x;
    if (idx >= KH * KH) return;
    int v = idx >> 10, k = idx & 1023;
    // (2v+1)*(2k+1) <= 2047*2047 < 2^22: exact in fp32
    float ae = (float)((2 * v + 1) * (2 * k)) * (1.0f / 4096.0f);
    float ao = (float)((2 * v + 1) * (2 * k + 1)) * (1.0f / 4096.0f);
    float ce, se, co, so;
    sincospif(ae, &se, &ce);
    sincospif(ao, &so, &co);
    put_split(g_Ce_h, g_Ce_l, idx, ce);
    put_split(g_Co_h, g_Co_l, idx, co);
    put_split(g_Se_h, g_Se_l, idx, se);
    put_split(g_So_h, g_So_l, idx, so);
}

__global__ void split_x(const float* __restrict__ x) {
    size_t i = (size_t)blockIdx.x * blockDim.x + threadIdx.x;  // 8 floats / thread
    const size_t total = (size_t)NB * NQ * NQ / 8;
    if (i >= total) return;
    float4 v0 = ((const float4*)x)[2 * i];
    float4 v1 = ((const float4*)x)[2 * i + 1];
    __half2 e01 = __floats2half2_rn(v0.x, v0.z);
    __half2 e23 = __floats2half2_rn(v1.x, v1.z);
    __half2 o01 = __floats2half2_rn(v0.y, v0.w);
    __half2 o23 = __floats2half2_rn(v1.y, v1.w);
    uint2 ue, uo;
    ue.x = *(uint32_t*)&e01; ue.y = *(uint32_t*)&e23;
    uo.x = *(uint32_t*)&o01; uo.y = *(uint32_t*)&o23;
    ((uint2*)g_Xe)[i] = ue;
    ((uint2*)g_Xo)[i] = uo;
}

// ---------------- main GEMM kernel ----------------
// Block tile 128x128, BK=64, lda=ldb=KH. SMEM: 3 buffers x 48KB
// (Ahi | Alo | B tiles, each 128 x 64 fp16, 128B rows, SW128).
// Chunks 0-15: even operands -> acc_e; 16-31: odd operands -> acc_o.
#define TILE_BYTES 16384
#define BUF_BYTES  (3 * TILE_BYTES)                // 49152
#define SMEM_TOTAL (3 * BUF_BYTES)                 // 147456
#define NCHUNK     32

__device__ __forceinline__ void load_chunk(uint32_t sbuf,
                                           const h16* __restrict__ Ah,
                                           const h16* __restrict__ Al,
                                           const h16* __restrict__ B,
                                           int m0, int n0, int k0, int tid) {
#pragma unroll
    for (int j = 0; j < 4; ++j) {
        int e = tid + 256 * j;           // 0..1023
        int r = e >> 3, c = e & 7;       // row 0..127, 16B chunk 0..7
        uint32_t soff = sw128((uint32_t)(r * 128 + c * 16));
        size_t gA = (size_t)(m0 + r) * KH + k0 + c * 8;
        size_t gB = (size_t)(n0 + r) * KH + k0 + c * 8;
        CP16(sbuf + soff,                  Ah + gA);
        CP16(sbuf + TILE_BYTES + soff,     Al + gA);
        CP16(sbuf + 2 * TILE_BYTES + soff, B + gB);
    }
}

__device__ __forceinline__ uint32_t a_addr(uint32_t buf, int mt, int s, int lane) {
    int sub = lane >> 3;
    int r = mt + ((sub & 1) << 3) + (lane & 7);
    int c = 2 * s + (sub >> 1);
    return buf + sw128((uint32_t)(r * 128 + c * 16));
}
__device__ __forceinline__ uint32_t b_addr(uint32_t buf, int nt, int s, int lane) {
    int sub = lane >> 3;
    int r = nt + ((sub >> 1) << 3) + (lane & 7);
    int c = 2 * s + (sub & 1);
    return buf + sw128((uint32_t)(r * 128 + c * 16));
}

// 4 k16 steps of the 2-term split-fp16 MMA from buffer bAh.., into ACC.
#define COMPUTE_CHUNK(ACC, bAh, bAl, bB)                                          \
    _Pragma("unroll")                                                             \
    for (int s = 0; s < 4; ++s) {                                                 \
        uint32_t ah[4][4], al[4][4], bb[2][4];                                    \
        _Pragma("unroll")                                                         \
        for (int mi = 0; mi < 4; ++mi) {                                          \
            LDM4(ah[mi], a_addr(bAh, wm * 64 + mi * 16, s, lane));                \
            LDM4(al[mi], a_addr(bAl, wm * 64 + mi * 16, s, lane));                \
        }                                                                         \
        _Pragma("unroll")                                                         \
        for (int nj = 0; nj < 2; ++nj)                                            \
            LDM4(bb[nj], b_addr(bB, wn * 32 + nj * 16, s, lane));                 \
        _Pragma("unroll")                                                         \
        for (int mi = 0; mi < 4; ++mi)                                            \
            _Pragma("unroll")                                                     \
            for (int ni = 0; ni < 4; ++ni) {                                      \
                const int nj = ni >> 1, nh = (ni & 1) * 2;                        \
                MMA16816(ACC[mi][ni], ah[mi], bb[nj][nh], bb[nj][nh + 1]);        \
                MMA16816(ACC[mi][ni], al[mi], bb[nj][nh], bb[nj][nh + 1]);        \
            }                                                                     \
    }

template <int STAGE>
__global__ void __launch_bounds__(256, 1)
idsct_fold_kernel(const h16* __restrict__ Aeh, const h16* __restrict__ Ael,
                  const h16* __restrict__ Aoh, const h16* __restrict__ Aol,
                  const h16* __restrict__ Be,  const h16* __restrict__ Bo,
                  h16* __restrict__ Te, h16* __restrict__ To,
                  float* __restrict__ OutF) {
    extern __shared__ char smem[];
    const uint32_t sbase = smem_u32(smem);
    const int tid = threadIdx.x, wid = tid >> 5, lane = tid & 31;
    const int wm = wid & 1;          // 2 warp rows  -> 64 M each
    const int wn = wid >> 1;         // 4 warp cols  -> 32 N each
    const int m0 = blockIdx.y * 128; // [0,1024)
    const int n0 = blockIdx.x * 128; // [0,2048)
    const int b  = blockIdx.z;
    const size_t plane = (size_t)NQ * KH;
    const h16* pBe = Be + (size_t)b * plane;
    const h16* pBo = Bo + (size_t)b * plane;

    float acc_e[4][4][4], acc_o[4][4][4];
#pragma unroll
    for (int i = 0; i < 4; ++i)
#pragma unroll
        for (int j = 0; j < 4; ++j)
#pragma unroll
            for (int q = 0; q < 4; ++q) { acc_e[i][j][q] = 0.0f; acc_o[i][j][q] = 0.0f; }

    // 3-stage pipeline prologue: chunks 0,1 (both even-pass)
    load_chunk(sbase,             Aeh, Ael, pBe, m0, n0, 0,  tid);
    CP_COMMIT();
    load_chunk(sbase + BUF_BYTES, Aeh, Ael, pBe, m0, n0, 64, tid);
    CP_COMMIT();

    for (int ci = 0; ci < NCHUNK; ++ci) {
        if (ci == NCHUNK - 1) { CP_WAIT0(); } else { CP_WAIT1(); }
        __syncthreads();

        // issue chunk ci+2 into buffer (ci+2)%3 (read last at iter ci-1; the
        // barrier above orders those reads before these writes)
        const int nc = ci + 2;
        if (nc < NCHUNK) {
            const uint32_t nbuf = sbase + (uint32_t)(nc % 3) * BUF_BYTES;
            const int k0n = (nc & 15) * 64;
            if (nc < 16)
                load_chunk(nbuf, Aeh, Ael, pBe, m0, n0, k0n, tid);
            else
                load_chunk(nbuf, Aoh, Aol, pBo, m0, n0, k0n, tid);
            CP_COMMIT();
        }

        const uint32_t bAh = sbase + (uint32_t)(ci % 3) * BUF_BYTES;
        const uint32_t bAl = bAh + TILE_BYTES;
        const uint32_t bB  = bAh + 2 * TILE_BYTES;

        if (ci < 16) {
            COMPUTE_CHUNK(acc_e, bAh, bAl, bB);
        } else {
            COMPUTE_CHUNK(acc_o, bAh, bAl, bB);
        }
    }

    // epilogue. quad mapping: c0,c1 = (row rq, cols cq,cq+1); c2,c3 = (rq+8, same)
    const int rq = lane >> 2, cq = (lane & 3) * 2;
    const int rbase = m0 + wm * 64;   // row in [0,1024)
    const int cbase = n0 + wn * 32;
#pragma unroll
    for (int mi = 0; mi < 4; ++mi)
#pragma unroll
        for (int ni = 0; ni < 4; ++ni) {
            const float e0 = acc_e[mi][ni][0], e1 = acc_e[mi][ni][1];
            const float e2 = acc_e[mi][ni][2], e3 = acc_e[mi][ni][3];
            const float o0 = acc_o[mi][ni][0], o1 = acc_o[mi][ni][1];
            const float o2 = acc_o[mi][ni][2], o3 = acc_o[mi][ni][3];
            const int r0 = rbase + mi * 16 + rq;   // [0,1024)
            const int r1 = r0 + 8;
            const int p0 = cbase + ni * 8 + cq;    // even column index
            if (STAGE == 1) {
                // T'[v,p]: top v=r, bottom v=2047-r; parity-pack over p. fp16-hi.
                const size_t pe = (size_t)(p0 >> 1);
                const size_t tb = (size_t)b * plane;
                const size_t t0 = tb + (size_t)r0 * KH + pe;
                const size_t b0 = tb + (size_t)(2047 - r0) * KH + pe;
                const size_t t1 = tb + (size_t)r1 * KH + pe;
                const size_t b1 = tb + (size_t)(2047 - r1) * KH + pe;
                Te[t0] = __float2half(e0 + o0);   // (r0, p even) top
                To[t0] = __float2half(e1 + o1);   // (r0, p odd)  top
                Te[b0] = __float2half(e0 - o0);   // bottom
                To[b0] = __float2half(e1 - o1);
                Te[t1] = __float2half(e2 + o2);
                To[t1] = __float2half(e3 + o3);
                Te[b1] = __float2half(e2 - o2);
                To[b1] = __float2half(e3 - o3);
            } else {
                // out[u,v]: top u=r -> E+O; bottom u=2047-r -> O-E. cols v.
                const size_t ob = (size_t)b * NQ * NQ;
                const size_t c = (size_t)p0;
                float2 vt0 = make_float2(e0 + o0, e1 + o1);
                float2 vb0 = make_float2(o0 - e0, o1 - e1);
                float2 vt1 = make_float2(e2 + o2, e3 + o3);
                float2 vb1 = make_float2(o2 - e2, o3 - e3);
                *(float2*)(OutF + ob + (size_t)r0 * NQ + c) = vt0;
                *(float2*)(OutF + ob + (size_t)(2047 - r0) * NQ + c) = vb0;
                *(float2*)(OutF + ob + (size_t)r1 * NQ + c) = vt1;
                *(float2*)(OutF + ob + (size_t)(2047 - r1) * NQ + c) = vb1;
            }
        }
}

// ---------------- launch ----------------
extern "C" void kernel_launch(void* const* d_in, const int* in_sizes, int n_in,
                              void* d_out, int out_size) {
    const float* x = (const float*)d_in[0];
    float* out = (float*)d_out;

    h16 *pCeh, *pCel, *pCoh, *pCol, *pSeh, *pSel, *pSoh, *pSol;
    h16 *pXe, *pXo, *pTe, *pTo;
    cudaGetSymbolAddress((void**)&pCeh, g_Ce_h);
    cudaGetSymbolAddress((void**)&pCel, g_Ce_l);
    cudaGetSymbolAddress((void**)&pCoh, g_Co_h);
    cudaGetSymbolAddress((void**)&pCol, g_Co_l);
    cudaGetSymbolAddress((void**)&pSeh, g_Se_h);
    cudaGetSymbolAddress((void**)&pSel, g_Se_l);
    cudaGetSymbolAddress((void**)&pSoh, g_So_h);
    cudaGetSymbolAddress((void**)&pSol, g_So_l);
    cudaGetSymbolAddress((void**)&pXe, g_Xe);
    cudaGetSymbolAddress((void**)&pXo, g_Xo);
    cudaGetSymbolAddress((void**)&pTe, g_Te);
    cudaGetSymbolAddress((void**)&pTo, g_To);

    cudaFuncSetAttribute(idsct_fold_kernel<1>, cudaFuncAttributeMaxDynamicSharedMemorySize, SMEM_TOTAL);
    cudaFuncSetAttribute(idsct_fold_kernel<2>, cudaFuncAttributeMaxDynamicSharedMemorySize, SMEM_TOTAL);

    // 1) parity-packed basis + input split
    gen_basis_split<<<(KH * KH + 255) / 256, 256>>>();
    split_x<<<(int)(((size_t)NB * NQ * NQ / 8 + 255) / 256), 256>>>(x);

    // 2) Stage 1: A = Ce/Co [1024x1024] (hi+lo), B = Xe/Xo [b,2048,1024] -> Te/To
    idsct_fold_kernel<1><<<dim3(16, 8, NB), 256, SMEM_TOTAL>>>(
        pCeh, pCel, pCoh, pCol, pXe, pXo, pTe, pTo, nullptr);

    // 3) Stage 2: A = Se/So (hi+lo), B = Te/To -> out fp32
    idsct_fold_kernel<2><<<dim3(16, 8, NB), 256, SMEM_TOTAL>>>(
        pSeh, pSel, pSoh, pSol, pTe, pTo, nullptr, nullptr, out);
}

// round 10
// speedup vs baseline: 2.1870x; 1.5036x over previous
#include <cuda_runtime.h>
#include <cuda_fp16.h>
#include <stdint.h>
#include <math.h>

// x: [B=4, 2048, 2048] fp32.
// out[b,u,v] = sum_{p,q} x[b,p,q] * sin(pi*(2u+1)*p/4096) * cos(pi*(2v+1)*q/4096)
//
// Parity fold (one butterfly level):
//   C[2047-v, q] = (-1)^q C[v,q],  S[2047-u, p] = -(-1)^p S[u,p]
// Stage 1: E1[v',p] = sum_{qe} Ce[v',qe] Xe[p,qe],  O1[v',p] = sum_{qo} Co[v',qo] Xo[p,qo]
//          T'[v',p] = E1+O1,  T'[2047-v',p] = E1-O1      (v' in [0,1024))
// Stage 2: E2[u',v] = sum_{pe} Se[u',pe] Te[v,pe],  O2 = sum So[u',po] To[v,po]
//          out[u',v] = E2+O2,  out[2047-u',v] = O2-E2
//
// Precision: pure fp16 operands (single HMMA term), fp32 accumulate.
// Basis + x + T all fp16-rounded; measured-error budget ~4-5e-4 < 1e-3.

#define NQ 2048
#define KH 1024
#define NB 4
typedef __half h16;

// ---------------- device scratch (allocation-free rule) ----------------
__device__ __align__(256) h16 g_Ce[KH * KH];
__device__ __align__(256) h16 g_Co[KH * KH];
__device__ __align__(256) h16 g_Se[KH * KH];
__device__ __align__(256) h16 g_So[KH * KH];
__device__ __align__(256) h16 g_Xe[(size_t)NB * NQ * KH];
__device__ __align__(256) h16 g_Xo[(size_t)NB * NQ * KH];
__device__ __align__(256) h16 g_Te[(size_t)NB * NQ * KH];
__device__ __align__(256) h16 g_To[(size_t)NB * NQ * KH];

// ---------------- helpers ----------------
__device__ __forceinline__ uint32_t smem_u32(const void* p) {
    uint32_t a;
    asm("{ .reg .u64 t; cvta.to.shared.u64 t, %1; cvt.u32.u64 %0, t; }"
        : "=r"(a) : "l"(p));
    return a;
}
__device__ __forceinline__ uint32_t sw128(uint32_t off) { return off ^ ((off >> 3) & 0x70); }

#define CP16(saddr, gptr) \
    asm volatile("cp.async.cg.shared.global [%0], [%1], 16;" \
                 :: "r"(saddr), "l"(gptr) : "memory")
#define CP_COMMIT() asm volatile("cp.async.commit_group;" ::: "memory")
#define CP_WAIT1() asm volatile("cp.async.wait_group 1;" ::: "memory")
#define CP_WAIT0() asm volatile("cp.async.wait_group 0;" ::: "memory")

#define LDM4(d, addr) \
    asm volatile("ldmatrix.sync.aligned.m8n8.x4.shared.b16 {%0,%1,%2,%3}, [%4];" \
                 : "=r"((d)[0]), "=r"((d)[1]), "=r"((d)[2]), "=r"((d)[3]) : "r"(addr))

#define MMA16816(c, a, b0v, b1v) \
    asm volatile("mma.sync.aligned.m16n8k16.row.col.f32.f16.f16.f32 " \
                 "{%0,%1,%2,%3}, {%4,%5,%6,%7}, {%8,%9}, {%0,%1,%2,%3};" \
                 : "+f"((c)[0]), "+f"((c)[1]), "+f"((c)[2]), "+f"((c)[3]) \
                 : "r"((a)[0]), "r"((a)[1]), "r"((a)[2]), "r"((a)[3]), \
                   "r"(b0v), "r"(b1v))

// ---------------- prologue kernels ----------------
__global__ void gen_basis() {
    int idx = blockIdx.x * blockDim.x + threadIdx.x;
    if (idx >= KH * KH) return;
    int v = idx >> 10, k = idx & 1023;
    // (2v+1)*(2k+1) <= 2047*2047 < 2^22: exact in fp32
    float ae = (float)((2 * v + 1) * (2 * k)) * (1.0f / 4096.0f);
    float ao = (float)((2 * v + 1) * (2 * k + 1)) * (1.0f / 4096.0f);
    float ce, se, co, so;
    sincospif(ae, &se, &ce);
    sincospif(ao, &so, &co);
    g_Ce[idx] = __float2half(ce);
    g_Co[idx] = __float2half(co);
    g_Se[idx] = __float2half(se);
    g_So[idx] = __float2half(so);
}

__global__ void split_x(const float* __restrict__ x) {
    size_t i = (size_t)blockIdx.x * blockDim.x + threadIdx.x;  // 8 floats / thread
    const size_t total = (size_t)NB * NQ * NQ / 8;
    if (i >= total) return;
    float4 v0 = ((const float4*)x)[2 * i];
    float4 v1 = ((const float4*)x)[2 * i + 1];
    __half2 e01 = __floats2half2_rn(v0.x, v0.z);
    __half2 e23 = __floats2half2_rn(v1.x, v1.z);
    __half2 o01 = __floats2half2_rn(v0.y, v0.w);
    __half2 o23 = __floats2half2_rn(v1.y, v1.w);
    uint2 ue, uo;
    ue.x = *(uint32_t*)&e01; ue.y = *(uint32_t*)&e23;
    uo.x = *(uint32_t*)&o01; uo.y = *(uint32_t*)&o23;
    ((uint2*)g_Xe)[i] = ue;
    ((uint2*)g_Xo)[i] = uo;
}

// ---------------- main GEMM kernel ----------------
// Block tile 128x128, BK=64, lda=ldb=KH. SMEM: 3 buffers x 32KB
// (A | B tiles, each 128 x 64 fp16, 128B rows, SW128).
// Chunks 0-15: even operands -> acc_e; 16-31: odd operands -> acc_o.
#define TILE_BYTES 16384
#define BUF_BYTES  (2 * TILE_BYTES)                // 32768
#define SMEM_TOTAL (3 * BUF_BYTES)                 // 98304
#define NCHUNK     32

__device__ __forceinline__ void load_chunk(uint32_t sbuf,
                                           const h16* __restrict__ A,
                                           const h16* __restrict__ B,
                                           int m0, int n0, int k0, int tid) {
#pragma unroll
    for (int j = 0; j < 4; ++j) {
        int e = tid + 256 * j;           // 0..1023
        int r = e >> 3, c = e & 7;       // row 0..127, 16B chunk 0..7
        uint32_t soff = sw128((uint32_t)(r * 128 + c * 16));
        size_t gA = (size_t)(m0 + r) * KH + k0 + c * 8;
        size_t gB = (size_t)(n0 + r) * KH + k0 + c * 8;
        CP16(sbuf + soff,              A + gA);
        CP16(sbuf + TILE_BYTES + soff, B + gB);
    }
}

__device__ __forceinline__ uint32_t a_addr(uint32_t buf, int mt, int s, int lane) {
    int sub = lane >> 3;
    int r = mt + ((sub & 1) << 3) + (lane & 7);
    int c = 2 * s + (sub >> 1);
    return buf + sw128((uint32_t)(r * 128 + c * 16));
}
__device__ __forceinline__ uint32_t b_addr(uint32_t buf, int nt, int s, int lane) {
    int sub = lane >> 3;
    int r = nt + ((sub >> 1) << 3) + (lane & 7);
    int c = 2 * s + (sub & 1);
    return buf + sw128((uint32_t)(r * 128 + c * 16));
}

// 4 k16 steps of single-term fp16 MMA from buffer bA/bB into ACC.
#define COMPUTE_CHUNK(ACC, bA, bB)                                                \
    _Pragma("unroll")                                                             \
    for (int s = 0; s < 4; ++s) {                                                 \
        uint32_t ah[4][4], bb[2][4];                                              \
        _Pragma("unroll")                                                         \
        for (int mi = 0; mi < 4; ++mi)                                            \
            LDM4(ah[mi], a_addr(bA, wm * 64 + mi * 16, s, lane));                 \
        _Pragma("unroll")                                                         \
        for (int nj = 0; nj < 2; ++nj)                                            \
            LDM4(bb[nj], b_addr(bB, wn * 32 + nj * 16, s, lane));                 \
        _Pragma("unroll")                                                         \
        for (int mi = 0; mi < 4; ++mi)                                            \
            _Pragma("unroll")                                                     \
            for (int ni = 0; ni < 4; ++ni) {                                      \
                const int nj = ni >> 1, nh = (ni & 1) * 2;                        \
                MMA16816(ACC[mi][ni], ah[mi], bb[nj][nh], bb[nj][nh + 1]);        \
            }                                                                     \
    }

template <int STAGE>
__global__ void __launch_bounds__(256, 1)
idsct_fold_kernel(const h16* __restrict__ Ae, const h16* __restrict__ Ao,
                  const h16* __restrict__ Be, const h16* __restrict__ Bo,
                  h16* __restrict__ Te, h16* __restrict__ To,
                  float* __restrict__ OutF) {
    extern __shared__ char smem[];
    const uint32_t sbase = smem_u32(smem);
    const int tid = threadIdx.x, wid = tid >> 5, lane = tid & 31;
    const int wm = wid & 1;          // 2 warp rows  -> 64 M each
    const int wn = wid >> 1;         // 4 warp cols  -> 32 N each
    const int m0 = blockIdx.y * 128; // [0,1024)
    const int n0 = blockIdx.x * 128; // [0,2048)
    const int b  = blockIdx.z;
    const size_t plane = (size_t)NQ * KH;
    const h16* pBe = Be + (size_t)b * plane;
    const h16* pBo = Bo + (size_t)b * plane;

    float acc_e[4][4][4], acc_o[4][4][4];
#pragma unroll
    for (int i = 0; i < 4; ++i)
#pragma unroll
        for (int j = 0; j < 4; ++j)
#pragma unroll
            for (int q = 0; q < 4; ++q) { acc_e[i][j][q] = 0.0f; acc_o[i][j][q] = 0.0f; }

    // 3-stage pipeline prologue: chunks 0,1 (both even-pass)
    load_chunk(sbase,             Ae, pBe, m0, n0, 0,  tid);
    CP_COMMIT();
    load_chunk(sbase + BUF_BYTES, Ae, pBe, m0, n0, 64, tid);
    CP_COMMIT();

    for (int ci = 0; ci < NCHUNK; ++ci) {
        if (ci == NCHUNK - 1) { CP_WAIT0(); } else { CP_WAIT1(); }
        __syncthreads();

        // issue chunk ci+2 into buffer (ci+2)%3 (read last at iter ci-1; the
        // barrier above orders those reads before these writes)
        const int nc = ci + 2;
        if (nc < NCHUNK) {
            const uint32_t nbuf = sbase + (uint32_t)(nc % 3) * BUF_BYTES;
            const int k0n = (nc & 15) * 64;
            if (nc < 16)
                load_chunk(nbuf, Ae, pBe, m0, n0, k0n, tid);
            else
                load_chunk(nbuf, Ao, pBo, m0, n0, k0n, tid);
            CP_COMMIT();
        }

        const uint32_t bA = sbase + (uint32_t)(ci % 3) * BUF_BYTES;
        const uint32_t bB = bA + TILE_BYTES;

        if (ci < 16) {
            COMPUTE_CHUNK(acc_e, bA, bB);
        } else {
            COMPUTE_CHUNK(acc_o, bA, bB);
        }
    }

    // epilogue. quad mapping: c0,c1 = (row rq, cols cq,cq+1); c2,c3 = (rq+8, same)
    const int rq = lane >> 2, cq = (lane & 3) * 2;
    const int rbase = m0 + wm * 64;   // row in [0,1024)
    const int cbase = n0 + wn * 32;
#pragma unroll
    for (int mi = 0; mi < 4; ++mi)
#pragma unroll
        for (int ni = 0; ni < 4; ++ni) {
            const float e0 = acc_e[mi][ni][0], e1 = acc_e[mi][ni][1];
            const float e2 = acc_e[mi][ni][2], e3 = acc_e[mi][ni][3];
            const float o0 = acc_o[mi][ni][0], o1 = acc_o[mi][ni][1];
            const float o2 = acc_o[mi][ni][2], o3 = acc_o[mi][ni][3];
            const int r0 = rbase + mi * 16 + rq;   // [0,1024)
            const int r1 = r0 + 8;
            const int p0 = cbase + ni * 8 + cq;    // even column index
            if (STAGE == 1) {
                // T'[v,p]: top v=r, bottom v=2047-r; parity-pack over p. fp16.
                const size_t pe = (size_t)(p0 >> 1);
                const size_t tb = (size_t)b * plane;
                const size_t t0 = tb + (size_t)r0 * KH + pe;
                const size_t b0 = tb + (size_t)(2047 - r0) * KH + pe;
                const size_t t1 = tb + (size_t)r1 * KH + pe;
                const size_t b1 = tb + (size_t)(2047 - r1) * KH + pe;
                Te[t0] = __float2half(e0 + o0);   // (r0, p even) top
                To[t0] = __float2half(e1 + o1);   // (r0, p odd)  top
                Te[b0] = __float2half(e0 - o0);   // bottom
                To[b0] = __float2half(e1 - o1);
                Te[t1] = __float2half(e2 + o2);
                To[t1] = __float2half(e3 + o3);
                Te[b1] = __float2half(e2 - o2);
                To[b1] = __float2half(e3 - o3);
            } else {
                // out[u,v]: top u=r -> E+O; bottom u=2047-r -> O-E. cols v.
                const size_t ob = (size_t)b * NQ * NQ;
                const size_t c = (size_t)p0;
                float2 vt0 = make_float2(e0 + o0, e1 + o1);
                float2 vb0 = make_float2(o0 - e0, o1 - e1);
                float2 vt1 = make_float2(e2 + o2, e3 + o3);
                float2 vb1 = make_float2(o2 - e2, o3 - e3);
                *(float2*)(OutF + ob + (size_t)r0 * NQ + c) = vt0;
                *(float2*)(OutF + ob + (size_t)(2047 - r0) * NQ + c) = vb0;
                *(float2*)(OutF + ob + (size_t)r1 * NQ + c) = vt1;
                *(float2*)(OutF + ob + (size_t)(2047 - r1) * NQ + c) = vb1;
            }
        }
}

// ---------------- launch ----------------
extern "C" void kernel_launch(void* const* d_in, const int* in_sizes, int n_in,
                              void* d_out, int out_size) {
    const float* x = (const float*)d_in[0];
    float* out = (float*)d_out;

    h16 *pCe, *pCo, *pSe, *pSo, *pXe, *pXo, *pTe, *pTo;
    cudaGetSymbolAddress((void**)&pCe, g_Ce);
    cudaGetSymbolAddress((void**)&pCo, g_Co);
    cudaGetSymbolAddress((void**)&pSe, g_Se);
    cudaGetSymbolAddress((void**)&pSo, g_So);
    cudaGetSymbolAddress((void**)&pXe, g_Xe);
    cudaGetSymbolAddress((void**)&pXo, g_Xo);
    cudaGetSymbolAddress((void**)&pTe, g_Te);
    cudaGetSymbolAddress((void**)&pTo, g_To);

    cudaFuncSetAttribute(idsct_fold_kernel<1>, cudaFuncAttributeMaxDynamicSharedMemorySize, SMEM_TOTAL);
    cudaFuncSetAttribute(idsct_fold_kernel<2>, cudaFuncAttributeMaxDynamicSharedMemorySize, SMEM_TOTAL);

    // 1) parity-packed basis + input split
    gen_basis<<<(KH * KH + 255) / 256, 256>>>();
    split_x<<<(int)(((size_t)NB * NQ * NQ / 8 + 255) / 256), 256>>>(x);

    // 2) Stage 1: A = Ce/Co [1024x1024], B = Xe/Xo [b,2048,1024] -> Te/To
    idsct_fold_kernel<1><<<dim3(16, 8, NB), 256, SMEM_TOTAL>>>(
        pCe, pCo, pXe, pXo, pTe, pTo, nullptr);

    // 3) Stage 2: A = Se/So, B = Te/To -> out fp32
    idsct_fold_kernel<2><<<dim3(16, 8, NB), 256, SMEM_TOTAL>>>(
        pSe, pSo, pTe, pTo, nullptr, nullptr, out);
}

// round 11
// speedup vs baseline: 2.3169x; 1.0594x over previous
#include <cuda_runtime.h>
#include <cuda_fp16.h>
#include <stdint.h>
#include <math.h>

// x: [B=4, 2048, 2048] fp32.
// out[b,u,v] = sum_{p,q} x[b,p,q] * sin(pi*(2u+1)*p/4096) * cos(pi*(2v+1)*q/4096)
//
// Parity fold: C[2047-v,q] = (-1)^q C[v,q],  S[2047-u,p] = -(-1)^p S[u,p]
// Stage 1: E1 = Ce.Xe^T, O1 = Co.Xo^T; T'[v']=E1+O1, T'[2047-v']=E1-O1
// Stage 2: E2 = Se.Te^T, O2 = So.To^T; out[u']=E2+O2, out[2047-u']=O2-E2
// Pure fp16 operands, fp32 accumulate (single HMMA term).
//
// R11: 512 threads. Warps 0-7 compute the E-GEMM, warps 8-15 the O-GEMM,
// concurrently (one acc set per warp -> ~half the registers -> 4 warps/SMSP).
// E tile crosses to O warps through an SMEM stash at the end.

#define NQ 2048
#define KH 1024
#define NB 4
typedef __half h16;

// ---------------- device scratch (allocation-free rule) ----------------
__device__ __align__(256) h16 g_Ce[KH * KH];
__device__ __align__(256) h16 g_Co[KH * KH];
__device__ __align__(256) h16 g_Se[KH * KH];
__device__ __align__(256) h16 g_So[KH * KH];
__device__ __align__(256) h16 g_Xe[(size_t)NB * NQ * KH];
__device__ __align__(256) h16 g_Xo[(size_t)NB * NQ * KH];
__device__ __align__(256) h16 g_Te[(size_t)NB * NQ * KH];
__device__ __align__(256) h16 g_To[(size_t)NB * NQ * KH];

// ---------------- helpers ----------------
__device__ __forceinline__ uint32_t smem_u32(const void* p) {
    uint32_t a;
    asm("{ .reg .u64 t; cvta.to.shared.u64 t, %1; cvt.u32.u64 %0, t; }"
        : "=r"(a) : "l"(p));
    return a;
}
__device__ __forceinline__ uint32_t sw128(uint32_t off) { return off ^ ((off >> 3) & 0x70); }

#define CP16(saddr, gptr) \
    asm volatile("cp.async.cg.shared.global [%0], [%1], 16;" \
                 :: "r"(saddr), "l"(gptr) : "memory")
#define CP_COMMIT() asm volatile("cp.async.commit_group;" ::: "memory")
#define CP_WAIT1() asm volatile("cp.async.wait_group 1;" ::: "memory")
#define CP_WAIT0() asm volatile("cp.async.wait_group 0;" ::: "memory")

#define LDM4(d, addr) \
    asm volatile("ldmatrix.sync.aligned.m8n8.x4.shared.b16 {%0,%1,%2,%3}, [%4];" \
                 : "=r"((d)[0]), "=r"((d)[1]), "=r"((d)[2]), "=r"((d)[3]) : "r"(addr))

#define MMA16816(c, a, b0v, b1v) \
    asm volatile("mma.sync.aligned.m16n8k16.row.col.f32.f16.f16.f32 " \
                 "{%0,%1,%2,%3}, {%4,%5,%6,%7}, {%8,%9}, {%0,%1,%2,%3};" \
                 : "+f"((c)[0]), "+f"((c)[1]), "+f"((c)[2]), "+f"((c)[3]) \
                 : "r"((a)[0]), "r"((a)[1]), "r"((a)[2]), "r"((a)[3]), \
                   "r"(b0v), "r"(b1v))

// ---------------- prologue kernels ----------------
__global__ void gen_basis() {
    int idx = blockIdx.x * blockDim.x + threadIdx.x;
    if (idx >= KH * KH) return;
    int v = idx >> 10, k = idx & 1023;
    // (2v+1)*(2k+1) <= 2047*2047 < 2^22: exact in fp32
    float ae = (float)((2 * v + 1) * (2 * k)) * (1.0f / 4096.0f);
    float ao = (float)((2 * v + 1) * (2 * k + 1)) * (1.0f / 4096.0f);
    float ce, se, co, so;
    sincospif(ae, &se, &ce);
    sincospif(ao, &so, &co);
    g_Ce[idx] = __float2half(ce);
    g_Co[idx] = __float2half(co);
    g_Se[idx] = __float2half(se);
    g_So[idx] = __float2half(so);
}

__global__ void split_x(const float* __restrict__ x) {
    size_t i = (size_t)blockIdx.x * blockDim.x + threadIdx.x;  // 8 floats / thread
    const size_t total = (size_t)NB * NQ * NQ / 8;
    if (i >= total) return;
    float4 v0 = ((const float4*)x)[2 * i];
    float4 v1 = ((const float4*)x)[2 * i + 1];
    __half2 e01 = __floats2half2_rn(v0.x, v0.z);
    __half2 e23 = __floats2half2_rn(v1.x, v1.z);
    __half2 o01 = __floats2half2_rn(v0.y, v0.w);
    __half2 o23 = __floats2half2_rn(v1.y, v1.w);
    uint2 ue, uo;
    ue.x = *(uint32_t*)&e01; ue.y = *(uint32_t*)&e23;
    uo.x = *(uint32_t*)&o01; uo.y = *(uint32_t*)&o23;
    ((uint2*)g_Xe)[i] = ue;
    ((uint2*)g_Xo)[i] = uo;
}

// ---------------- main GEMM kernel ----------------
// Block tile 128x128, BK=64 per parity per iteration.
// SMEM stage (64KB) = [A_e | B_e | A_o | B_o], each 128x64 fp16 SW128.
// 3 stages = 192KB. 16 iterations. E-stash (64KB fp32) aliases stage buffer 1
// (dead by then: last compute reads stage 0; stage 1 last read at iter 13).
#define TILE_BYTES 16384
#define PAIR_BYTES (4 * TILE_BYTES)                // 65536
#define SMEM_TOTAL (3 * PAIR_BYTES)                // 196608
#define STASH_OFF  PAIR_BYTES
#define NITER      16

__device__ __forceinline__ uint32_t a_addr(uint32_t buf, int mt, int s, int lane) {
    int sub = lane >> 3;
    int r = mt + ((sub & 1) << 3) + (lane & 7);
    int c = 2 * s + (sub >> 1);
    return buf + sw128((uint32_t)(r * 128 + c * 16));
}
__device__ __forceinline__ uint32_t b_addr(uint32_t buf, int nt, int s, int lane) {
    int sub = lane >> 3;
    int r = nt + ((sub >> 1) << 3) + (lane & 7);
    int c = 2 * s + (sub & 1);
    return buf + sw128((uint32_t)(r * 128 + c * 16));
}

template <int STAGE>
__global__ void __launch_bounds__(512, 1)
idsct_fold_kernel(const h16* __restrict__ Ae, const h16* __restrict__ Ao,
                  const h16* __restrict__ Be, const h16* __restrict__ Bo,
                  h16* __restrict__ Te, h16* __restrict__ To,
                  float* __restrict__ OutF) {
    extern __shared__ char smem[];
    const uint32_t sbase = smem_u32(smem);
    const int tid = threadIdx.x, wid = tid >> 5, lane = tid & 31;
    const int grp = wid >> 3;        // 0 = E-GEMM warps, 1 = O-GEMM warps
    const int gw  = wid & 7;         // warp within group: 2x4 grid
    const int wm  = gw & 1;          // 64 M rows per warp
    const int wn  = gw >> 1;         // 32 N cols per warp
    const int m0 = blockIdx.y * 128; // [0,1024)
    const int n0 = blockIdx.x * 128; // [0,2048)
    const int b  = blockIdx.z;
    const size_t plane = (size_t)NQ * KH;
    const h16* pBe = Be + (size_t)b * plane;
    const h16* pBo = Bo + (size_t)b * plane;

    float acc[4][4][4];
#pragma unroll
    for (int i = 0; i < 4; ++i)
#pragma unroll
        for (int j = 0; j < 4; ++j)
#pragma unroll
            for (int q = 0; q < 4; ++q) acc[i][j][q] = 0.0f;

    // 64KB pair load: 4096 16B chunks, 8 per thread. For unrolled j,
    // tile index = j>>1 is compile-time (tid < 512 spans half a tile).
#define LOAD_PAIR(SBUF, K0)                                                     \
    do {                                                                        \
        _Pragma("unroll")                                                       \
        for (int j = 0; j < 8; ++j) {                                           \
            const int within = tid + (j & 1) * 512;                             \
            const int r = within >> 3, c = within & 7;                          \
            const uint32_t soff = (uint32_t)((j >> 1) * TILE_BYTES) +           \
                                  sw128((uint32_t)(r * 128 + c * 16));          \
            const h16* g;                                                       \
            if ((j >> 1) == 0)      g = Ae  + (size_t)(m0 + r) * KH + (K0) + c * 8; \
            else if ((j >> 1) == 1) g = pBe + (size_t)(n0 + r) * KH + (K0) + c * 8; \
            else if ((j >> 1) == 2) g = Ao  + (size_t)(m0 + r) * KH + (K0) + c * 8; \
            else                    g = pBo + (size_t)(n0 + r) * KH + (K0) + c * 8; \
            CP16((SBUF) + soff, g);                                             \
        }                                                                       \
    } while (0)

    LOAD_PAIR(sbase, 0);
    CP_COMMIT();
    LOAD_PAIR(sbase + PAIR_BYTES, 64);
    CP_COMMIT();

    for (int ci = 0; ci < NITER; ++ci) {
        if (ci == NITER - 1) { CP_WAIT0(); } else { CP_WAIT1(); }
        __syncthreads();

        const int nc = ci + 2;
        if (nc < NITER) {
            LOAD_PAIR(sbase + (uint32_t)(nc % 3) * PAIR_BYTES, nc * 64);
            CP_COMMIT();
        }

        // this group's operand tiles within the current stage
        const uint32_t bA = sbase + (uint32_t)(ci % 3) * PAIR_BYTES
                          + (uint32_t)grp * (2 * TILE_BYTES);
        const uint32_t bB = bA + TILE_BYTES;

#pragma unroll
        for (int s = 0; s < 4; ++s) {
            uint32_t ah[4][4], bb[2][4];
#pragma unroll
            for (int mi = 0; mi < 4; ++mi)
                LDM4(ah[mi], a_addr(bA, wm * 64 + mi * 16, s, lane));
#pragma unroll
            for (int nj = 0; nj < 2; ++nj)
                LDM4(bb[nj], b_addr(bB, wn * 32 + nj * 16, s, lane));
#pragma unroll
            for (int mi = 0; mi < 4; ++mi)
#pragma unroll
                for (int ni = 0; ni < 4; ++ni) {
                    const int nj = ni >> 1, nh = (ni & 1) * 2;
                    MMA16816(acc[mi][ni], ah[mi], bb[nj][nh], bb[nj][nh + 1]);
                }
        }
    }

    // ---- combine: E warps stash, O warps read + store ----
    float4* stash4 = (float4*)(smem + STASH_OFF);
    const int slot = gw * 32 + lane;     // 0..255, matched across groups
    if (grp == 0) {
#pragma unroll
        for (int mi = 0; mi < 4; ++mi)
#pragma unroll
            for (int ni = 0; ni < 4; ++ni)
                stash4[(mi * 4 + ni) * 256 + slot] =
                    make_float4(acc[mi][ni][0], acc[mi][ni][1],
                                acc[mi][ni][2], acc[mi][ni][3]);
    }
    __syncthreads();
    if (grp == 1) {
        const int rq = lane >> 2, cq = (lane & 3) * 2;
        const int rbase = m0 + wm * 64;   // row in [0,1024)
        const int cbase = n0 + wn * 32;
#pragma unroll
        for (int mi = 0; mi < 4; ++mi)
#pragma unroll
            for (int ni = 0; ni < 4; ++ni) {
                const float4 e4 = stash4[(mi * 4 + ni) * 256 + slot];
                const float o0 = acc[mi][ni][0], o1 = acc[mi][ni][1];
                const float o2 = acc[mi][ni][2], o3 = acc[mi][ni][3];
                const int r0 = rbase + mi * 16 + rq;
                const int r1 = r0 + 8;
                const int p0 = cbase + ni * 8 + cq;
                if (STAGE == 1) {
                    // T'[v,p]: top v=r, bottom v=2047-r; parity-pack over p.
                    const size_t pe = (size_t)(p0 >> 1);
                    const size_t tb = (size_t)b * plane;
                    const size_t t0 = tb + (size_t)r0 * KH + pe;
                    const size_t b0 = tb + (size_t)(2047 - r0) * KH + pe;
                    const size_t t1 = tb + (size_t)r1 * KH + pe;
                    const size_t b1 = tb + (size_t)(2047 - r1) * KH + pe;
                    Te[t0] = __float2half(e4.x + o0);
                    To[t0] = __float2half(e4.y + o1);
                    Te[b0] = __float2half(e4.x - o0);
                    To[b0] = __float2half(e4.y - o1);
                    Te[t1] = __float2half(e4.z + o2);
                    To[t1] = __float2half(e4.w + o3);
                    Te[b1] = __float2half(e4.z - o2);
                    To[b1] = __float2half(e4.w - o3);
                } else {
                    // out[u,v]: top u=r -> E+O; bottom u=2047-r -> O-E.
                    const size_t ob = (size_t)b * NQ * NQ;
                    const size_t c = (size_t)p0;
                    float2 vt0 = make_float2(e4.x + o0, e4.y + o1);
                    float2 vb0 = make_float2(o0 - e4.x, o1 - e4.y);
                    float2 vt1 = make_float2(e4.z + o2, e4.w + o3);
                    float2 vb1 = make_float2(o2 - e4.z, o3 - e4.w);
                    *(float2*)(OutF + ob + (size_t)r0 * NQ + c) = vt0;
                    *(float2*)(OutF + ob + (size_t)(2047 - r0) * NQ + c) = vb0;
                    *(float2*)(OutF + ob + (size_t)r1 * NQ + c) = vt1;
                    *(float2*)(OutF + ob + (size_t)(2047 - r1) * NQ + c) = vb1;
                }
            }
    }
#undef LOAD_PAIR
}

// ---------------- launch ----------------
extern "C" void kernel_launch(void* const* d_in, const int* in_sizes, int n_in,
                              void* d_out, int out_size) {
    const float* x = (const float*)d_in[0];
    float* out = (float*)d_out;

    h16 *pCe, *pCo, *pSe, *pSo, *pXe, *pXo, *pTe, *pTo;
    cudaGetSymbolAddress((void**)&pCe, g_Ce);
    cudaGetSymbolAddress((void**)&pCo, g_Co);
    cudaGetSymbolAddress((void**)&pSe, g_Se);
    cudaGetSymbolAddress((void**)&pSo, g_So);
    cudaGetSymbolAddress((void**)&pXe, g_Xe);
    cudaGetSymbolAddress((void**)&pXo, g_Xo);
    cudaGetSymbolAddress((void**)&pTe, g_Te);
    cudaGetSymbolAddress((void**)&pTo, g_To);

    cudaFuncSetAttribute(idsct_fold_kernel<1>, cudaFuncAttributeMaxDynamicSharedMemorySize, SMEM_TOTAL);
    cudaFuncSetAttribute(idsct_fold_kernel<2>, cudaFuncAttributeMaxDynamicSharedMemorySize, SMEM_TOTAL);

    // 1) parity-packed basis + input split
    gen_basis<<<(KH * KH + 255) / 256, 256>>>();
    split_x<<<(int)(((size_t)NB * NQ * NQ / 8 + 255) / 256), 256>>>(x);

    // 2) Stage 1: A = Ce/Co [1024x1024], B = Xe/Xo [b,2048,1024] -> Te/To
    idsct_fold_kernel<1><<<dim3(16, 8, NB), 512, SMEM_TOTAL>>>(
        pCe, pCo, pXe, pXo, pTe, pTo, nullptr);

    // 3) Stage 2: A = Se/So, B = Te/To -> out fp32
    idsct_fold_kernel<2><<<dim3(16, 8, NB), 512, SMEM_TOTAL>>>(
        pSe, pSo, pTe, pTo, nullptr, nullptr, out);
}

// round 12
// speedup vs baseline: 2.3296x; 1.0055x over previous
#include <cuda_runtime.h>
#include <cuda_fp16.h>
#include <stdint.h>
#include <math.h>

// x: [B=4, 2048, 2048] fp32.
// out[b,u,v] = sum_{p,q} x[b,p,q] * sin(pi*(2u+1)*p/4096) * cos(pi*(2v+1)*q/4096)
//
// Parity fold: C[2047-v,q] = (-1)^q C[v,q],  S[2047-u,p] = -(-1)^p S[u,p]
// Stage 1: E1 = Ce.Xe^T, O1 = Co.Xo^T; T'[v']=E1+O1, T'[2047-v']=E1-O1
// Stage 2: E2 = Se.Te^T, O2 = So.To^T; out[u']=E2+O2, out[2047-u']=O2-E2
// Pure fp16 operands, fp32 accumulate (single HMMA term).
//
// R12: 256 threads. Warps 0-3 = E-GEMM, warps 4-7 = O-GEMM, each warp a
// 64x64 tile (2x2 grid) -> 16 MAC per smem byte (vs 10.7 with 64x32),
// cutting the smem-crossbar floor that caps the tensor pipe.

#define NQ 2048
#define KH 1024
#define NB 4
typedef __half h16;

// ---------------- device scratch (allocation-free rule) ----------------
__device__ __align__(256) h16 g_Ce[KH * KH];
__device__ __align__(256) h16 g_Co[KH * KH];
__device__ __align__(256) h16 g_Se[KH * KH];
__device__ __align__(256) h16 g_So[KH * KH];
__device__ __align__(256) h16 g_Xe[(size_t)NB * NQ * KH];
__device__ __align__(256) h16 g_Xo[(size_t)NB * NQ * KH];
__device__ __align__(256) h16 g_Te[(size_t)NB * NQ * KH];
__device__ __align__(256) h16 g_To[(size_t)NB * NQ * KH];

// ---------------- helpers ----------------
__device__ __forceinline__ uint32_t smem_u32(const void* p) {
    uint32_t a;
    asm("{ .reg .u64 t; cvta.to.shared.u64 t, %1; cvt.u32.u64 %0, t; }"
        : "=r"(a) : "l"(p));
    return a;
}
__device__ __forceinline__ uint32_t sw128(uint32_t off) { return off ^ ((off >> 3) & 0x70); }

#define CP16(saddr, gptr) \
    asm volatile("cp.async.cg.shared.global [%0], [%1], 16;" \
                 :: "r"(saddr), "l"(gptr) : "memory")
#define CP_COMMIT() asm volatile("cp.async.commit_group;" ::: "memory")
#define CP_WAIT1() asm volatile("cp.async.wait_group 1;" ::: "memory")
#define CP_WAIT0() asm volatile("cp.async.wait_group 0;" ::: "memory")

#define LDM4(d, addr) \
    asm volatile("ldmatrix.sync.aligned.m8n8.x4.shared.b16 {%0,%1,%2,%3}, [%4];" \
                 : "=r"((d)[0]), "=r"((d)[1]), "=r"((d)[2]), "=r"((d)[3]) : "r"(addr))

#define MMA16816(c, a, b0v, b1v) \
    asm volatile("mma.sync.aligned.m16n8k16.row.col.f32.f16.f16.f32 " \
                 "{%0,%1,%2,%3}, {%4,%5,%6,%7}, {%8,%9}, {%0,%1,%2,%3};" \
                 : "+f"((c)[0]), "+f"((c)[1]), "+f"((c)[2]), "+f"((c)[3]) \
                 : "r"((a)[0]), "r"((a)[1]), "r"((a)[2]), "r"((a)[3]), \
                   "r"(b0v), "r"(b1v))

// ---------------- prologue kernels ----------------
__global__ void gen_basis() {
    int idx = blockIdx.x * blockDim.x + threadIdx.x;
    if (idx >= KH * KH) return;
    int v = idx >> 10, k = idx & 1023;
    // (2v+1)*(2k+1) <= 2047*2047 < 2^22: exact in fp32
    float ae = (float)((2 * v + 1) * (2 * k)) * (1.0f / 4096.0f);
    float ao = (float)((2 * v + 1) * (2 * k + 1)) * (1.0f / 4096.0f);
    float ce, se, co, so;
    sincospif(ae, &se, &ce);
    sincospif(ao, &so, &co);
    g_Ce[idx] = __float2half(ce);
    g_Co[idx] = __float2half(co);
    g_Se[idx] = __float2half(se);
    g_So[idx] = __float2half(so);
}

__global__ void split_x(const float* __restrict__ x) {
    size_t i = (size_t)blockIdx.x * blockDim.x + threadIdx.x;  // 8 floats / thread
    const size_t total = (size_t)NB * NQ * NQ / 8;
    if (i >= total) return;
    float4 v0 = ((const float4*)x)[2 * i];
    float4 v1 = ((const float4*)x)[2 * i + 1];
    __half2 e01 = __floats2half2_rn(v0.x, v0.z);
    __half2 e23 = __floats2half2_rn(v1.x, v1.z);
    __half2 o01 = __floats2half2_rn(v0.y, v0.w);
    __half2 o23 = __floats2half2_rn(v1.y, v1.w);
    uint2 ue, uo;
    ue.x = *(uint32_t*)&e01; ue.y = *(uint32_t*)&e23;
    uo.x = *(uint32_t*)&o01; uo.y = *(uint32_t*)&o23;
    ((uint2*)g_Xe)[i] = ue;
    ((uint2*)g_Xo)[i] = uo;
}

// ---------------- main GEMM kernel ----------------
// Block tile 128x128, BK=64 per parity per iteration.
// SMEM stage (64KB) = [A_e | B_e | A_o | B_o], each 128x64 fp16 SW128.
// 3 stages = 192KB. 16 iterations. E-stash (64KB fp32) aliases stage buffer 1
// (dead by then: last compute reads stage 0 (iter 15) / stage 2 (iter 14);
// stage 1's last read is iter 13).
#define TILE_BYTES 16384
#define PAIR_BYTES (4 * TILE_BYTES)                // 65536
#define SMEM_TOTAL (3 * PAIR_BYTES)                // 196608
#define STASH_OFF  PAIR_BYTES
#define NITER      16

__device__ __forceinline__ uint32_t a_addr(uint32_t buf, int mt, int s, int lane) {
    int sub = lane >> 3;
    int r = mt + ((sub & 1) << 3) + (lane & 7);
    int c = 2 * s + (sub >> 1);
    return buf + sw128((uint32_t)(r * 128 + c * 16));
}
__device__ __forceinline__ uint32_t b_addr(uint32_t buf, int nt, int s, int lane) {
    int sub = lane >> 3;
    int r = nt + ((sub >> 1) << 3) + (lane & 7);
    int c = 2 * s + (sub & 1);
    return buf + sw128((uint32_t)(r * 128 + c * 16));
}

template <int STAGE>
__global__ void __launch_bounds__(256, 1)
idsct_fold_kernel(const h16* __restrict__ Ae, const h16* __restrict__ Ao,
                  const h16* __restrict__ Be, const h16* __restrict__ Bo,
                  h16* __restrict__ Te, h16* __restrict__ To,
                  float* __restrict__ OutF) {
    extern __shared__ char smem[];
    const uint32_t sbase = smem_u32(smem);
    const int tid = threadIdx.x, wid = tid >> 5, lane = tid & 31;
    const int grp = wid >> 2;        // 0 = E-GEMM warps, 1 = O-GEMM warps
    const int gw  = wid & 3;         // warp within group: 2x2 grid
    const int wm  = gw & 1;          // 64 M rows per warp
    const int wn  = gw >> 1;         // 64 N cols per warp
    const int m0 = blockIdx.y * 128; // [0,1024)
    const int n0 = blockIdx.x * 128; // [0,2048)
    const int b  = blockIdx.z;
    const size_t plane = (size_t)NQ * KH;
    const h16* pBe = Be + (size_t)b * plane;
    const h16* pBo = Bo + (size_t)b * plane;

    float acc[4][8][4];              // 64x64 warp tile: mi x ni x quad = 128 regs
#pragma unroll
    for (int i = 0; i < 4; ++i)
#pragma unroll
        for (int j = 0; j < 8; ++j)
#pragma unroll
            for (int q = 0; q < 4; ++q) acc[i][j][q] = 0.0f;

    // 64KB pair load with 256 threads: 4096 16B chunks, 16 per thread.
    // tile index = j>>2 is compile-time.
#define LOAD_PAIR(SBUF, K0)                                                     \
    do {                                                                        \
        _Pragma("unroll")                                                       \
        for (int j = 0; j < 16; ++j) {                                          \
            const int within = tid + (j & 3) * 256;                             \
            const int r = within >> 3, c = within & 7;                          \
            const uint32_t soff = (uint32_t)((j >> 2) * TILE_BYTES) +           \
                                  sw128((uint32_t)(r * 128 + c * 16));          \
            const h16* g;                                                       \
            if ((j >> 2) == 0)      g = Ae  + (size_t)(m0 + r) * KH + (K0) + c * 8; \
            else if ((j >> 2) == 1) g = pBe + (size_t)(n0 + r) * KH + (K0) + c * 8; \
            else if ((j >> 2) == 2) g = Ao  + (size_t)(m0 + r) * KH + (K0) + c * 8; \
            else                    g = pBo + (size_t)(n0 + r) * KH + (K0) + c * 8; \
            CP16((SBUF) + soff, g);                                             \
        }                                                                       \
    } while (0)

    LOAD_PAIR(sbase, 0);
    CP_COMMIT();
    LOAD_PAIR(sbase + PAIR_BYTES, 64);
    CP_COMMIT();

    for (int ci = 0; ci < NITER; ++ci) {
        if (ci == NITER - 1) { CP_WAIT0(); } else { CP_WAIT1(); }
        __syncthreads();

        const int nc = ci + 2;
        if (nc < NITER) {
            LOAD_PAIR(sbase + (uint32_t)(nc % 3) * PAIR_BYTES, nc * 64);
            CP_COMMIT();
        }

        // this group's operand tiles within the current stage
        const uint32_t bA = sbase + (uint32_t)(ci % 3) * PAIR_BYTES
                          + (uint32_t)grp * (2 * TILE_BYTES);
        const uint32_t bB = bA + TILE_BYTES;

#pragma unroll
        for (int s = 0; s < 4; ++s) {
            uint32_t ah[4][4], bb[4][4];
#pragma unroll
            for (int mi = 0; mi < 4; ++mi)
                LDM4(ah[mi], a_addr(bA, wm * 64 + mi * 16, s, lane));
#pragma unroll
            for (int nj = 0; nj < 4; ++nj)
                LDM4(bb[nj], b_addr(bB, wn * 64 + nj * 16, s, lane));
#pragma unroll
            for (int mi = 0; mi < 4; ++mi)
#pragma unroll
                for (int ni = 0; ni < 8; ++ni) {
                    const int nj = ni >> 1, nh = (ni & 1) * 2;
                    MMA16816(acc[mi][ni], ah[mi], bb[nj][nh], bb[nj][nh + 1]);
                }
        }
    }

    // ---- combine: E warps stash, O warps read + store ----
    float4* stash4 = (float4*)(smem + STASH_OFF);
    const int slot = gw * 32 + lane;     // 0..127, matched across groups
    if (grp == 0) {
#pragma unroll
        for (int mi = 0; mi < 4; ++mi)
#pragma unroll
            for (int ni = 0; ni < 8; ++ni)
                stash4[(mi * 8 + ni) * 128 + slot] =
                    make_float4(acc[mi][ni][0], acc[mi][ni][1],
                                acc[mi][ni][2], acc[mi][ni][3]);
    }
    __syncthreads();
    if (grp == 1) {
        const int rq = lane >> 2, cq = (lane & 3) * 2;
        const int rbase = m0 + wm * 64;   // row in [0,1024)
        const int cbase = n0 + wn * 64;
#pragma unroll
        for (int mi = 0; mi < 4; ++mi)
#pragma unroll
            for (int ni = 0; ni < 8; ++ni) {
                const float4 e4 = stash4[(mi * 8 + ni) * 128 + slot];
                const float o0 = acc[mi][ni][0], o1 = acc[mi][ni][1];
                const float o2 = acc[mi][ni][2], o3 = acc[mi][ni][3];
                const int r0 = rbase + mi * 16 + rq;
                const int r1 = r0 + 8;
                const int p0 = cbase + ni * 8 + cq;
                if (STAGE == 1) {
                    // T'[v,p]: top v=r, bottom v=2047-r; parity-pack over p.
                    const size_t pe = (size_t)(p0 >> 1);
                    const size_t tb = (size_t)b * plane;
                    const size_t t0 = tb + (size_t)r0 * KH + pe;
                    const size_t b0 = tb + (size_t)(2047 - r0) * KH + pe;
                    const size_t t1 = tb + (size_t)r1 * KH + pe;
                    const size_t b1 = tb + (size_t)(2047 - r1) * KH + pe;
                    Te[t0] = __float2half(e4.x + o0);
                    To[t0] = __float2half(e4.y + o1);
                    Te[b0] = __float2half(e4.x - o0);
                    To[b0] = __float2half(e4.y - o1);
                    Te[t1] = __float2half(e4.z + o2);
                    To[t1] = __float2half(e4.w + o3);
                    Te[b1] = __float2half(e4.z - o2);
                    To[b1] = __float2half(e4.w - o3);
                } else {
                    // out[u,v]: top u=r -> E+O; bottom u=2047-r -> O-E.
                    const size_t ob = (size_t)b * NQ * NQ;
                    const size_t c = (size_t)p0;
                    float2 vt0 = make_float2(e4.x + o0, e4.y + o1);
                    float2 vb0 = make_float2(o0 - e4.x, o1 - e4.y);
                    float2 vt1 = make_float2(e4.z + o2, e4.w + o3);
                    float2 vb1 = make_float2(o2 - e4.z, o3 - e4.w);
                    *(float2*)(OutF + ob + (size_t)r0 * NQ + c) = vt0;
                    *(float2*)(OutF + ob + (size_t)(2047 - r0) * NQ + c) = vb0;
                    *(float2*)(OutF + ob + (size_t)r1 * NQ + c) = vt1;
                    *(float2*)(OutF + ob + (size_t)(2047 - r1) * NQ + c) = vb1;
                }
            }
    }
#undef LOAD_PAIR
}

// ---------------- launch ----------------
extern "C" void kernel_launch(void* const* d_in, const int* in_sizes, int n_in,
                              void* d_out, int out_size) {
    const float* x = (const float*)d_in[0];
    float* out = (float*)d_out;

    h16 *pCe, *pCo, *pSe, *pSo, *pXe, *pXo, *pTe, *pTo;
    cudaGetSymbolAddress((void**)&pCe, g_Ce);
    cudaGetSymbolAddress((void**)&pCo, g_Co);
    cudaGetSymbolAddress((void**)&pSe, g_Se);
    cudaGetSymbolAddress((void**)&pSo, g_So);
    cudaGetSymbolAddress((void**)&pXe, g_Xe);
    cudaGetSymbolAddress((void**)&pXo, g_Xo);
    cudaGetSymbolAddress((void**)&pTe, g_Te);
    cudaGetSymbolAddress((void**)&pTo, g_To);

    cudaFuncSetAttribute(idsct_fold_kernel<1>, cudaFuncAttributeMaxDynamicSharedMemorySize, SMEM_TOTAL);
    cudaFuncSetAttribute(idsct_fold_kernel<2>, cudaFuncAttributeMaxDynamicSharedMemorySize, SMEM_TOTAL);

    // 1) parity-packed basis + input split
    gen_basis<<<(KH * KH + 255) / 256, 256>>>();
    split_x<<<(int)(((size_t)NB * NQ * NQ / 8 + 255) / 256), 256>>>(x);

    // 2) Stage 1: A = Ce/Co [1024x1024], B = Xe/Xo [b,2048,1024] -> Te/To
    idsct_fold_kernel<1><<<dim3(16, 8, NB), 256, SMEM_TOTAL>>>(
        pCe, pCo, pXe, pXo, pTe, pTo, nullptr);

    // 3) Stage 2: A = Se/So, B = Te/To -> out fp32
    idsct_fold_kernel<2><<<dim3(16, 8, NB), 256, SMEM_TOTAL>>>(
        pSe, pSo, pTe, pTo, nullptr, nullptr, out);
}

// round 13
// speedup vs baseline: 2.4122x; 1.0355x over previous
#include <cuda_runtime.h>
#include <cuda_fp16.h>
#include <stdint.h>
#include <math.h>

// x: [B=4, 2048, 2048] fp32.
// out[b,u,v] = sum_{p,q} x[b,p,q] * sin(pi*(2u+1)*p/4096) * cos(pi*(2v+1)*q/4096)
//
// Parity fold: C[2047-v,q] = (-1)^q C[v,q],  S[2047-u,p] = -(-1)^p S[u,p]
// Stage 1: E1 = Ce.Xe^T, O1 = Co.Xo^T; T'[v']=E1+O1, T'[2047-v']=E1-O1
// Stage 2: E2 = Se.Te^T, O2 = So.To^T; out[u']=E2+O2, out[2047-u']=O2-E2
// Pure fp16 operands, fp32 accumulate (single HMMA term).
//
// R13: E and O are SEPARATE kernels (1 acc set -> 128-thread CTAs, 96KB smem,
// 2 CTAs/SM so barriers of one CTA are covered by the other's mainloop).
// E kernel stores its fp32 tile to scratch; O kernel's epilogue combines.

#define NQ 2048
#define KH 1024
#define NB 4
typedef __half h16;

// ---------------- device scratch (allocation-free rule) ----------------
__device__ __align__(256) h16 g_Ce[KH * KH];
__device__ __align__(256) h16 g_Co[KH * KH];
__device__ __align__(256) h16 g_Se[KH * KH];
__device__ __align__(256) h16 g_So[KH * KH];
__device__ __align__(256) h16 g_Xe[(size_t)NB * NQ * KH];
__device__ __align__(256) h16 g_Xo[(size_t)NB * NQ * KH];
__device__ __align__(256) h16 g_Te[(size_t)NB * NQ * KH];
__device__ __align__(256) h16 g_To[(size_t)NB * NQ * KH];
__device__ __align__(256) float g_E32[(size_t)NB * KH * NQ];   // E-tile scratch

// ---------------- helpers ----------------
__device__ __forceinline__ uint32_t smem_u32(const void* p) {
    uint32_t a;
    asm("{ .reg .u64 t; cvta.to.shared.u64 t, %1; cvt.u32.u64 %0, t; }"
        : "=r"(a) : "l"(p));
    return a;
}
__device__ __forceinline__ uint32_t sw128(uint32_t off) { return off ^ ((off >> 3) & 0x70); }

#define CP16(saddr, gptr) \
    asm volatile("cp.async.cg.shared.global [%0], [%1], 16;" \
                 :: "r"(saddr), "l"(gptr) : "memory")
#define CP_COMMIT() asm volatile("cp.async.commit_group;" ::: "memory")
#define CP_WAIT1() asm volatile("cp.async.wait_group 1;" ::: "memory")
#define CP_WAIT0() asm volatile("cp.async.wait_group 0;" ::: "memory")

#define LDM4(d, addr) \
    asm volatile("ldmatrix.sync.aligned.m8n8.x4.shared.b16 {%0,%1,%2,%3}, [%4];" \
                 : "=r"((d)[0]), "=r"((d)[1]), "=r"((d)[2]), "=r"((d)[3]) : "r"(addr))

#define MMA16816(c, a, b0v, b1v) \
    asm volatile("mma.sync.aligned.m16n8k16.row.col.f32.f16.f16.f32 " \
                 "{%0,%1,%2,%3}, {%4,%5,%6,%7}, {%8,%9}, {%0,%1,%2,%3};" \
                 : "+f"((c)[0]), "+f"((c)[1]), "+f"((c)[2]), "+f"((c)[3]) \
                 : "r"((a)[0]), "r"((a)[1]), "r"((a)[2]), "r"((a)[3]), \
                   "r"(b0v), "r"(b1v))

// ---------------- prologue kernels ----------------
__global__ void gen_basis() {
    int idx = blockIdx.x * blockDim.x + threadIdx.x;
    if (idx >= KH * KH) return;
    int v = idx >> 10, k = idx & 1023;
    // (2v+1)*(2k+1) <= 2047*2047 < 2^22: exact in fp32
    float ae = (float)((2 * v + 1) * (2 * k)) * (1.0f / 4096.0f);
    float ao = (float)((2 * v + 1) * (2 * k + 1)) * (1.0f / 4096.0f);
    float ce, se, co, so;
    sincospif(ae, &se, &ce);
    sincospif(ao, &so, &co);
    g_Ce[idx] = __float2half(ce);
    g_Co[idx] = __float2half(co);
    g_Se[idx] = __float2half(se);
    g_So[idx] = __float2half(so);
}

__global__ void split_x(const float* __restrict__ x) {
    size_t i = (size_t)blockIdx.x * blockDim.x + threadIdx.x;  // 8 floats / thread
    const size_t total = (size_t)NB * NQ * NQ / 8;
    if (i >= total) return;
    float4 v0 = ((const float4*)x)[2 * i];
    float4 v1 = ((const float4*)x)[2 * i + 1];
    __half2 e01 = __floats2half2_rn(v0.x, v0.z);
    __half2 e23 = __floats2half2_rn(v1.x, v1.z);
    __half2 o01 = __floats2half2_rn(v0.y, v0.w);
    __half2 o23 = __floats2half2_rn(v1.y, v1.w);
    uint2 ue, uo;
    ue.x = *(uint32_t*)&e01; ue.y = *(uint32_t*)&e23;
    uo.x = *(uint32_t*)&o01; uo.y = *(uint32_t*)&o23;
    ((uint2*)g_Xe)[i] = ue;
    ((uint2*)g_Xo)[i] = uo;
}

// ---------------- main GEMM kernel ----------------
// CTA: 128x128 output tile, 128 threads = 4 warps of 64x64 (2x2).
// BK=64, 3-stage cp.async pipeline: stage = [A | B] = 32KB, total 96KB
// -> 2 CTAs/SM (barrier stagger). 16 K-iterations.
#define TILE_BYTES 16384
#define STG_BYTES  (2 * TILE_BYTES)                // 32768
#define SMEM_TOTAL (3 * STG_BYTES)                 // 98304
#define NITER      16

__device__ __forceinline__ uint32_t a_addr(uint32_t buf, int mt, int s, int lane) {
    int sub = lane >> 3;
    int r = mt + ((sub & 1) << 3) + (lane & 7);
    int c = 2 * s + (sub >> 1);
    return buf + sw128((uint32_t)(r * 128 + c * 16));
}
__device__ __forceinline__ uint32_t b_addr(uint32_t buf, int nt, int s, int lane) {
    int sub = lane >> 3;
    int r = nt + ((sub >> 1) << 3) + (lane & 7);
    int c = 2 * s + (sub & 1);
    return buf + sw128((uint32_t)(r * 128 + c * 16));
}

// PAR: 0 = E pass (write fp32 tile to E32), 1 = O pass (combine with E32).
template <int STAGE, int PAR>
__global__ void __launch_bounds__(128, 2)
gemm_eo_kernel(const h16* __restrict__ A, const h16* __restrict__ Bg,
               float* __restrict__ E32,
               h16* __restrict__ Te, h16* __restrict__ To,
               float* __restrict__ OutF) {
    extern __shared__ char smem[];
    const uint32_t sbase = smem_u32(smem);
    const int tid = threadIdx.x, wid = tid >> 5, lane = tid & 31;
    const int wm = wid & 1;          // 64 M rows per warp
    const int wn = wid >> 1;         // 64 N cols per warp
    const int m0 = blockIdx.y * 128; // [0,1024)
    const int n0 = blockIdx.x * 128; // [0,2048)
    const int b  = blockIdx.z;
    const size_t plane = (size_t)NQ * KH;
    const h16* pB = Bg + (size_t)b * plane;

    float acc[4][8][4];              // 64x64 warp tile
#pragma unroll
    for (int i = 0; i < 4; ++i)
#pragma unroll
        for (int j = 0; j < 8; ++j)
#pragma unroll
            for (int q = 0; q < 4; ++q) acc[i][j][q] = 0.0f;

    // stage load: A tile (128x64) + B tile (128x64), 16 CP16/thread.
#define LOAD_STG(SBUF, K0)                                                      \
    do {                                                                        \
        _Pragma("unroll")                                                       \
        for (int j = 0; j < 8; ++j) {                                           \
            const int e = tid + 128 * j;       /* 0..1023 */                    \
            const int r = e >> 3, c = e & 7;                                    \
            const uint32_t soff = sw128((uint32_t)(r * 128 + c * 16));          \
            CP16((SBUF) + soff,              A  + (size_t)(m0 + r) * KH + (K0) + c * 8); \
            CP16((SBUF) + TILE_BYTES + soff, pB + (size_t)(n0 + r) * KH + (K0) + c * 8); \
        }                                                                       \
    } while (0)

    LOAD_STG(sbase, 0);
    CP_COMMIT();
    LOAD_STG(sbase + STG_BYTES, 64);
    CP_COMMIT();

    for (int ci = 0; ci < NITER; ++ci) {
        if (ci == NITER - 1) { CP_WAIT0(); } else { CP_WAIT1(); }
        __syncthreads();

        const int nc = ci + 2;
        if (nc < NITER) {
            LOAD_STG(sbase + (uint32_t)(nc % 3) * STG_BYTES, nc * 64);
            CP_COMMIT();
        }

        const uint32_t bA = sbase + (uint32_t)(ci % 3) * STG_BYTES;
        const uint32_t bB = bA + TILE_BYTES;

#pragma unroll
        for (int s = 0; s < 4; ++s) {
            uint32_t ah[4][4], bb[4][4];
#pragma unroll
            for (int mi = 0; mi < 4; ++mi)
                LDM4(ah[mi], a_addr(bA, wm * 64 + mi * 16, s, lane));
#pragma unroll
            for (int nj = 0; nj < 4; ++nj)
                LDM4(bb[nj], b_addr(bB, wn * 64 + nj * 16, s, lane));
#pragma unroll
            for (int mi = 0; mi < 4; ++mi)
#pragma unroll
                for (int ni = 0; ni < 8; ++ni) {
                    const int nj = ni >> 1, nh = (ni & 1) * 2;
                    MMA16816(acc[mi][ni], ah[mi], bb[nj][nh], bb[nj][nh + 1]);
                }
        }
    }

    // ---- epilogue ----
    const int rq = lane >> 2, cq = (lane & 3) * 2;
    const int rbase = m0 + wm * 64;   // row in [0,1024)
    const int cbase = n0 + wn * 64;
    const size_t eb = (size_t)b * KH * NQ;   // E32 plane [1024 x 2048]
#pragma unroll
    for (int mi = 0; mi < 4; ++mi)
#pragma unroll
        for (int ni = 0; ni < 8; ++ni) {
            const int r0 = rbase + mi * 16 + rq;
            const int r1 = r0 + 8;
            const int p0 = cbase + ni * 8 + cq;
            const size_t eo0 = eb + (size_t)r0 * NQ + p0;
            const size_t eo1 = eb + (size_t)r1 * NQ + p0;
            if (PAR == 0) {
                // E pass: store raw fp32 tile
                *(float2*)(E32 + eo0) = make_float2(acc[mi][ni][0], acc[mi][ni][1]);
                *(float2*)(E32 + eo1) = make_float2(acc[mi][ni][2], acc[mi][ni][3]);
            } else {
                const float2 ld0 = *(const float2*)(E32 + eo0);
                const float2 ld1 = *(const float2*)(E32 + eo1);
                const float e0 = ld0.x, e1 = ld0.y, e2 = ld1.x, e3 = ld1.y;
                const float o0 = acc[mi][ni][0], o1 = acc[mi][ni][1];
                const float o2 = acc[mi][ni][2], o3 = acc[mi][ni][3];
                if (STAGE == 1) {
                    // T'[v,p]: top v=r, bottom v=2047-r; parity-pack over p.
                    const size_t pe = (size_t)(p0 >> 1);
                    const size_t tb = (size_t)b * plane;
                    const size_t t0 = tb + (size_t)r0 * KH + pe;
                    const size_t b0 = tb + (size_t)(2047 - r0) * KH + pe;
                    const size_t t1 = tb + (size_t)r1 * KH + pe;
                    const size_t b1 = tb + (size_t)(2047 - r1) * KH + pe;
                    Te[t0] = __float2half(e0 + o0);
                    To[t0] = __float2half(e1 + o1);
                    Te[b0] = __float2half(e0 - o0);
                    To[b0] = __float2half(e1 - o1);
                    Te[t1] = __float2half(e2 + o2);
                    To[t1] = __float2half(e3 + o3);
                    Te[b1] = __float2half(e2 - o2);
                    To[b1] = __float2half(e3 - o3);
                } else {
                    // out[u,v]: top u=r -> E+O; bottom u=2047-r -> O-E.
                    const size_t ob = (size_t)b * NQ * NQ;
                    const size_t c = (size_t)p0;
                    *(float2*)(OutF + ob + (size_t)r0 * NQ + c) =
                        make_float2(e0 + o0, e1 + o1);
                    *(float2*)(OutF + ob + (size_t)(2047 - r0) * NQ + c) =
                        make_float2(o0 - e0, o1 - e1);
                    *(float2*)(OutF + ob + (size_t)r1 * NQ + c) =
                        make_float2(e2 + o2, e3 + o3);
                    *(float2*)(OutF + ob + (size_t)(2047 - r1) * NQ + c) =
                        make_float2(o2 - e2, o3 - e3);
                }
            }
        }
#undef LOAD_STG
}

// ---------------- launch ----------------
extern "C" void kernel_launch(void* const* d_in, const int* in_sizes, int n_in,
                              void* d_out, int out_size) {
    const float* x = (const float*)d_in[0];
    float* out = (float*)d_out;

    h16 *pCe, *pCo, *pSe, *pSo, *pXe, *pXo, *pTe, *pTo;
    float* pE;
    cudaGetSymbolAddress((void**)&pCe, g_Ce);
    cudaGetSymbolAddress((void**)&pCo, g_Co);
    cudaGetSymbolAddress((void**)&pSe, g_Se);
    cudaGetSymbolAddress((void**)&pSo, g_So);
    cudaGetSymbolAddress((void**)&pXe, g_Xe);
    cudaGetSymbolAddress((void**)&pXo, g_Xo);
    cudaGetSymbolAddress((void**)&pTe, g_Te);
    cudaGetSymbolAddress((void**)&pTo, g_To);
    cudaGetSymbolAddress((void**)&pE,  g_E32);

    cudaFuncSetAttribute(gemm_eo_kernel<1, 0>, cudaFuncAttributeMaxDynamicSharedMemorySize, SMEM_TOTAL);
    cudaFuncSetAttribute(gemm_eo_kernel<1, 1>, cudaFuncAttributeMaxDynamicSharedMemorySize, SMEM_TOTAL);
    cudaFuncSetAttribute(gemm_eo_kernel<2, 0>, cudaFuncAttributeMaxDynamicSharedMemorySize, SMEM_TOTAL);
    cudaFuncSetAttribute(gemm_eo_kernel<2, 1>, cudaFuncAttributeMaxDynamicSharedMemorySize, SMEM_TOTAL);

    const dim3 grid(16, 8, NB);   // 512 CTAs per GEMM kernel, 2 CTAs/SM

    // 1) parity-packed basis + input split
    gen_basis<<<(KH * KH + 255) / 256, 256>>>();
    split_x<<<(int)(((size_t)NB * NQ * NQ / 8 + 255) / 256), 256>>>(x);

    // 2) Stage 1: E1 = Ce.Xe^T -> E32;  O1 = Co.Xo^T, combine -> Te/To
    gemm_eo_kernel<1, 0><<<grid, 128, SMEM_TOTAL>>>(pCe, pXe, pE, nullptr, nullptr, nullptr);
    gemm_eo_kernel<1, 1><<<grid, 128, SMEM_TOTAL>>>(pCo, pXo, pE, pTe, pTo, nullptr);

    // 3) Stage 2: E2 = Se.Te^T -> E32;  O2 = So.To^T, combine -> out
    gemm_eo_kernel<2, 0><<<grid, 128, SMEM_TOTAL>>>(pSe, pTe, pE, nullptr, nullptr, nullptr);
    gemm_eo_kernel<2, 1><<<grid, 128, SMEM_TOTAL>>>(pSo, pTo, pE, nullptr, nullptr, out);
}

// round 14
// speedup vs baseline: 2.5562x; 1.0597x over previous
#include <cuda_runtime.h>
#include <cuda_fp16.h>
#include <stdint.h>
#include <math.h>

// x: [B=4, 2048, 2048] fp32.
// out[b,u,v] = sum_{p,q} x[b,p,q] * sin(pi*(2u+1)*p/4096) * cos(pi*(2v+1)*q/4096)
//
// Parity fold: C[2047-v,q] = (-1)^q C[v,q],  S[2047-u,p] = -(-1)^p S[u,p]
// Stage 1: E1 = Ce.Xe^T, O1 = Co.Xo^T; T'[v']=E1+O1, T'[2047-v']=E1-O1
// Stage 2: E2 = Se.Te^T, O2 = So.To^T; out[u']=E2+O2, out[2047-u']=O2-E2
// Pure fp16 operands, fp32 accumulate (single HMMA term).
//
// R14 (on top of R13's 4-kernel split, 128-thread CTAs, 2 CTAs/SM):
//  - combine kernels prefetch the E32 tile into dead pipeline buffers via
//    cp.async during iters 14/15, so the epilogue reads smem not gmem;
//  - stage-1 combine routes Te/To through an smem transpose (buffer 0) and
//    stores coalesced 16B chunks instead of 256 scattered 2B stores/thread.

#define NQ 2048
#define KH 1024
#define NB 4
typedef __half h16;

// ---------------- device scratch (allocation-free rule) ----------------
__device__ __align__(256) h16 g_Ce[KH * KH];
__device__ __align__(256) h16 g_Co[KH * KH];
__device__ __align__(256) h16 g_Se[KH * KH];
__device__ __align__(256) h16 g_So[KH * KH];
__device__ __align__(256) h16 g_Xe[(size_t)NB * NQ * KH];
__device__ __align__(256) h16 g_Xo[(size_t)NB * NQ * KH];
__device__ __align__(256) h16 g_Te[(size_t)NB * NQ * KH];
__device__ __align__(256) h16 g_To[(size_t)NB * NQ * KH];
__device__ __align__(256) float g_E32[(size_t)NB * KH * NQ];   // E-tile scratch

// ---------------- helpers ----------------
__device__ __forceinline__ uint32_t smem_u32(const void* p) {
    uint32_t a;
    asm("{ .reg .u64 t; cvta.to.shared.u64 t, %1; cvt.u32.u64 %0, t; }"
        : "=r"(a) : "l"(p));
    return a;
}
__device__ __forceinline__ uint32_t sw128(uint32_t off) { return off ^ ((off >> 3) & 0x70); }

#define CP16(saddr, gptr) \
    asm volatile("cp.async.cg.shared.global [%0], [%1], 16;" \
                 :: "r"(saddr), "l"(gptr) : "memory")
#define CP_COMMIT() asm volatile("cp.async.commit_group;" ::: "memory")
#define CP_WAIT1() asm volatile("cp.async.wait_group 1;" ::: "memory")
#define CP_WAIT0() asm volatile("cp.async.wait_group 0;" ::: "memory")

#define LDM4(d, addr) \
    asm volatile("ldmatrix.sync.aligned.m8n8.x4.shared.b16 {%0,%1,%2,%3}, [%4];" \
                 : "=r"((d)[0]), "=r"((d)[1]), "=r"((d)[2]), "=r"((d)[3]) : "r"(addr))

#define MMA16816(c, a, b0v, b1v) \
    asm volatile("mma.sync.aligned.m16n8k16.row.col.f32.f16.f16.f32 " \
                 "{%0,%1,%2,%3}, {%4,%5,%6,%7}, {%8,%9}, {%0,%1,%2,%3};" \
                 : "+f"((c)[0]), "+f"((c)[1]), "+f"((c)[2]), "+f"((c)[3]) \
                 : "r"((a)[0]), "r"((a)[1]), "r"((a)[2]), "r"((a)[3]), \
                   "r"(b0v), "r"(b1v))

// ---------------- prologue kernels ----------------
__global__ void gen_basis() {
    int idx = blockIdx.x * blockDim.x + threadIdx.x;
    if (idx >= KH * KH) return;
    int v = idx >> 10, k = idx & 1023;
    float ae = (float)((2 * v + 1) * (2 * k)) * (1.0f / 4096.0f);
    float ao = (float)((2 * v + 1) * (2 * k + 1)) * (1.0f / 4096.0f);
    float ce, se, co, so;
    sincospif(ae, &se, &ce);
    sincospif(ao, &so, &co);
    g_Ce[idx] = __float2half(ce);
    g_Co[idx] = __float2half(co);
    g_Se[idx] = __float2half(se);
    g_So[idx] = __float2half(so);
}

__global__ void split_x(const float* __restrict__ x) {
    size_t i = (size_t)blockIdx.x * blockDim.x + threadIdx.x;  // 8 floats / thread
    const size_t total = (size_t)NB * NQ * NQ / 8;
    if (i >= total) return;
    float4 v0 = ((const float4*)x)[2 * i];
    float4 v1 = ((const float4*)x)[2 * i + 1];
    __half2 e01 = __floats2half2_rn(v0.x, v0.z);
    __half2 e23 = __floats2half2_rn(v1.x, v1.z);
    __half2 o01 = __floats2half2_rn(v0.y, v0.w);
    __half2 o23 = __floats2half2_rn(v1.y, v1.w);
    uint2 ue, uo;
    ue.x = *(uint32_t*)&e01; ue.y = *(uint32_t*)&e23;
    uo.x = *(uint32_t*)&o01; uo.y = *(uint32_t*)&o23;
    ((uint2*)g_Xe)[i] = ue;
    ((uint2*)g_Xo)[i] = uo;
}

// ---------------- main GEMM kernel ----------------
// CTA: 128x128 output tile, 128 threads = 4 warps of 64x64 (2x2).
// BK=64, 3-stage cp.async pipeline: stage = [A | B] = 32KB, total 96KB
// -> 2 CTAs/SM. 16 K-iterations.
#define TILE_BYTES 16384
#define STG_BYTES  (2 * TILE_BYTES)                // 32768
#define SMEM_TOTAL (3 * STG_BYTES)                 // 98304
#define NITER      16

__device__ __forceinline__ uint32_t a_addr(uint32_t buf, int mt, int s, int lane) {
    int sub = lane >> 3;
    int r = mt + ((sub & 1) << 3) + (lane & 7);
    int c = 2 * s + (sub >> 1);
    return buf + sw128((uint32_t)(r * 128 + c * 16));
}
__device__ __forceinline__ uint32_t b_addr(uint32_t buf, int nt, int s, int lane) {
    int sub = lane >> 3;
    int r = nt + ((sub >> 1) << 3) + (lane & 7);
    int c = 2 * s + (sub & 1);
    return buf + sw128((uint32_t)(r * 128 + c * 16));
}

// PAR: 0 = E pass (write fp32 tile to E32), 1 = O pass (combine with E32).
template <int STAGE, int PAR>
__global__ void __launch_bounds__(128, 2)
gemm_eo_kernel(const h16* __restrict__ A, const h16* __restrict__ Bg,
               float* __restrict__ E32,
               h16* __restrict__ Te, h16* __restrict__ To,
               float* __restrict__ OutF) {
    extern __shared__ char smem[];
    const uint32_t sbase = smem_u32(smem);
    const int tid = threadIdx.x, wid = tid >> 5, lane = tid & 31;
    const int wm = wid & 1;          // 64 M rows per warp
    const int wn = wid >> 1;         // 64 N cols per warp
    const int m0 = blockIdx.y * 128; // [0,1024)
    const int n0 = blockIdx.x * 128; // [0,2048)
    const int b  = blockIdx.z;
    const size_t planeT = (size_t)NQ * KH;
    const h16* pB = Bg + (size_t)b * planeT;
    const size_t eb = (size_t)b * KH * NQ;   // E32 plane [1024 x 2048]

    float acc[4][8][4];              // 64x64 warp tile
#pragma unroll
    for (int i = 0; i < 4; ++i)
#pragma unroll
        for (int j = 0; j < 8; ++j)
#pragma unroll
            for (int q = 0; q < 4; ++q) acc[i][j][q] = 0.0f;

    // stage load: A tile (128x64) + B tile (128x64), 16 CP16/thread.
#define LOAD_STG(SBUF, K0)                                                      \
    do {                                                                        \
        _Pragma("unroll")                                                       \
        for (int j = 0; j < 8; ++j) {                                           \
            const int e = tid + 128 * j;       /* 0..1023 */                    \
            const int r = e >> 3, c = e & 7;                                    \
            const uint32_t soff = sw128((uint32_t)(r * 128 + c * 16));          \
            CP16((SBUF) + soff,              A  + (size_t)(m0 + r) * KH + (K0) + c * 8); \
            CP16((SBUF) + TILE_BYTES + soff, pB + (size_t)(n0 + r) * KH + (K0) + c * 8); \
        }                                                                       \
    } while (0)

    // E32 prefetch: 32KB (64 rows x 128 f32) into one stage buffer, swizzled.
#define PREF_E32(SBUF, ROW0)                                                    \
    do {                                                                        \
        _Pragma("unroll")                                                       \
        for (int j = 0; j < 16; ++j) {                                          \
            const int g = tid + 128 * j;       /* 0..2047 */                    \
            const int r = g >> 5, c = g & 31;  /* row 0..63, 16B chunk 0..31 */ \
            const uint32_t doff = (uint32_t)r * 512 +                           \
                                  (uint32_t)((c ^ (r & 7)) << 4);               \
            const float* src = E32 + eb + (size_t)(m0 + (ROW0) + r) * NQ        \
                             + n0 + c * 4;                                      \
            CP16((SBUF) + doff, src);                                           \
        }                                                                       \
    } while (0)

    LOAD_STG(sbase, 0);
    CP_COMMIT();
    LOAD_STG(sbase + STG_BYTES, 64);
    CP_COMMIT();

    for (int ci = 0; ci < NITER; ++ci) {
        if (PAR == 0 && ci == NITER - 1) { CP_WAIT0(); } else { CP_WAIT1(); }
        __syncthreads();

        const int nc = ci + 2;
        if (nc < NITER) {
            LOAD_STG(sbase + (uint32_t)(nc % 3) * STG_BYTES, nc * 64);
            CP_COMMIT();
        } else if (PAR == 1) {
            // free load slots at ci = 14, 15: prefetch E32 into dead buffers
            if (ci == NITER - 2) { PREF_E32(sbase + 1 * STG_BYTES, 0);  CP_COMMIT(); }
            else                 { PREF_E32(sbase + 2 * STG_BYTES, 64); CP_COMMIT(); }
        }

        const uint32_t bA = sbase + (uint32_t)(ci % 3) * STG_BYTES;
        const uint32_t bB = bA + TILE_BYTES;

#pragma unroll
        for (int s = 0; s < 4; ++s) {
            uint32_t ah[4][4], bb[4][4];
#pragma unroll
            for (int mi = 0; mi < 4; ++mi)
                LDM4(ah[mi], a_addr(bA, wm * 64 + mi * 16, s, lane));
#pragma unroll
            for (int nj = 0; nj < 4; ++nj)
                LDM4(bb[nj], b_addr(bB, wn * 64 + nj * 16, s, lane));
#pragma unroll
            for (int mi = 0; mi < 4; ++mi)
#pragma unroll
                for (int ni = 0; ni < 8; ++ni) {
                    const int nj = ni >> 1, nh = (ni & 1) * 2;
                    MMA16816(acc[mi][ni], ah[mi], bb[nj][nh], bb[nj][nh + 1]);
                }
        }
    }

    const int rq = lane >> 2, cq = (lane & 3) * 2;

    if (PAR == 0) {
        // E pass: store raw fp32 tile (coalesced-ish float2 runs)
#pragma unroll
        for (int mi = 0; mi < 4; ++mi)
#pragma unroll
            for (int ni = 0; ni < 8; ++ni) {
                const int r0 = m0 + wm * 64 + mi * 16 + rq;
                const int p0 = n0 + wn * 64 + ni * 8 + cq;
                *(float2*)(E32 + eb + (size_t)r0 * NQ + p0) =
                    make_float2(acc[mi][ni][0], acc[mi][ni][1]);
                *(float2*)(E32 + eb + (size_t)(r0 + 8) * NQ + p0) =
                    make_float2(acc[mi][ni][2], acc[mi][ni][3]);
            }
        return;
    }

    // ---- combine epilogue (PAR == 1) ----
    CP_WAIT0();          // E32 prefetch landed
    __syncthreads();     // visible to all threads; buf0 also free now

    // read E from swizzled smem (buffers 1 and 2)
#define RDE(lr, lc) \
    (*(const float2*)(smem + (uint32_t)(1 + ((lr) >> 6)) * STG_BYTES \
                     + (uint32_t)((lr) & 63) * 512 \
                     + (uint32_t)(((((lc) >> 2) ^ ((lr) & 7))) << 4) \
                     + (uint32_t)(((lc) & 3) << 2)))

    if (STAGE == 2) {
        // out[u,v]: top u=r -> E+O; bottom u=2047-r -> O-E.
        const size_t ob = (size_t)b * NQ * NQ;
#pragma unroll
        for (int mi = 0; mi < 4; ++mi)
#pragma unroll
            for (int ni = 0; ni < 8; ++ni) {
                const int lr0 = wm * 64 + mi * 16 + rq, lr1 = lr0 + 8;
                const int lc = wn * 64 + ni * 8 + cq;
                const float2 eA = RDE(lr0, lc);
                const float2 eB = RDE(lr1, lc);
                const float o0 = acc[mi][ni][0], o1 = acc[mi][ni][1];
                const float o2 = acc[mi][ni][2], o3 = acc[mi][ni][3];
                const int r0 = m0 + lr0, r1 = m0 + lr1;
                const size_t c = (size_t)(n0 + lc);
                *(float2*)(OutF + ob + (size_t)r0 * NQ + c) =
                    make_float2(eA.x + o0, eA.y + o1);
                *(float2*)(OutF + ob + (size_t)(2047 - r0) * NQ + c) =
                    make_float2(o0 - eA.x, o1 - eA.y);
                *(float2*)(OutF + ob + (size_t)r1 * NQ + c) =
                    make_float2(eB.x + o2, eB.y + o3);
                *(float2*)(OutF + ob + (size_t)(2047 - r1) * NQ + c) =
                    make_float2(o2 - eB.x, o3 - eB.y);
            }
        return;
    }

    // STAGE == 1: T'[v,p] parity-packed into Te/To via smem transpose (buf0).
    // Planes in buf0: Te plane [128 rows x 64 pe] at 0, To plane at 16KB.
    // Seg-level XOR swizzle: seg' = seg ^ (row & 7).
    const size_t tb = (size_t)b * planeT;
#pragma unroll
    for (int half = 0; half < 2; ++half) {   // 0 = top rows, 1 = bottom rows
#pragma unroll
        for (int mi = 0; mi < 4; ++mi)
#pragma unroll
            for (int ni = 0; ni < 8; ++ni) {
                const int lr0 = wm * 64 + mi * 16 + rq, lr1 = lr0 + 8;
                const int lc = wn * 64 + ni * 8 + cq;
                const float2 eA = RDE(lr0, lc);
                const float2 eB = RDE(lr1, lc);
                const float o0 = acc[mi][ni][0], o1 = acc[mi][ni][1];
                const float o2 = acc[mi][ni][2], o3 = acc[mi][ni][3];
                float teA, toA, teB, toB;
                if (half == 0) { teA = eA.x + o0; toA = eA.y + o1;
                                 teB = eB.x + o2; toB = eB.y + o3; }
                else           { teA = eA.x - o0; toA = eA.y - o1;
                                 teB = eB.x - o2; toB = eB.y - o3; }
                const int pe_l = wn * 32 + ni * 4 + (lane & 3);
                const int seg = pe_l >> 3, wi = pe_l & 7;
                const uint32_t o_lr0 = (uint32_t)lr0 * 128 +
                    (uint32_t)((seg ^ (lr0 & 7)) << 4) + (uint32_t)(wi << 1);
                const uint32_t o_lr1 = (uint32_t)lr1 * 128 +
                    (uint32_t)((seg ^ (lr1 & 7)) << 4) + (uint32_t)(wi << 1);
                *(h16*)(smem + o_lr0)         = __float2half(teA);
                *(h16*)(smem + 16384 + o_lr0) = __float2half(toA);
                *(h16*)(smem + o_lr1)         = __float2half(teB);
                *(h16*)(smem + 16384 + o_lr1) = __float2half(toB);
            }
        __syncthreads();
        // cooperative coalesced store: 2048 16B chunks, 16 per thread
#pragma unroll
        for (int j = 0; j < 16; ++j) {
            const int cg = tid + 128 * j;          // 0..2047
            const int pl = cg >> 10;               // 0 = Te, 1 = To
            const int within = cg & 1023;
            const int row = within >> 3, s = within & 7;
            const uint32_t soff = (uint32_t)pl * 16384 + (uint32_t)row * 128 +
                                  (uint32_t)((s ^ (row & 7)) << 4);
            const uint4 v = *(const uint4*)(smem + soff);
            const int vg = (half == 0) ? (m0 + row) : (2047 - (m0 + row));
            h16* dst = (pl == 0 ? Te : To) + tb + (size_t)vg * KH
                     + (n0 >> 1) + s * 8;
            *(uint4*)dst = v;
        }
        if (half == 0) __syncthreads();
    }
#undef RDE
#undef PREF_E32
#undef LOAD_STG
}

// ---------------- launch ----------------
extern "C" void kernel_launch(void* const* d_in, const int* in_sizes, int n_in,
                              void* d_out, int out_size) {
    const float* x = (const float*)d_in[0];
    float* out = (float*)d_out;

    h16 *pCe, *pCo, *pSe, *pSo, *pXe, *pXo, *pTe, *pTo;
    float* pE;
    cudaGetSymbolAddress((void**)&pCe, g_Ce);
    cudaGetSymbolAddress((void**)&pCo, g_Co);
    cudaGetSymbolAddress((void**)&pSe, g_Se);
    cudaGetSymbolAddress((void**)&pSo, g_So);
    cudaGetSymbolAddress((void**)&pXe, g_Xe);
    cudaGetSymbolAddress((void**)&pXo, g_Xo);
    cudaGetSymbolAddress((void**)&pTe, g_Te);
    cudaGetSymbolAddress((void**)&pTo, g_To);
    cudaGetSymbolAddress((void**)&pE,  g_E32);

    cudaFuncSetAttribute(gemm_eo_kernel<1, 0>, cudaFuncAttributeMaxDynamicSharedMemorySize, SMEM_TOTAL);
    cudaFuncSetAttribute(gemm_eo_kernel<1, 1>, cudaFuncAttributeMaxDynamicSharedMemorySize, SMEM_TOTAL);
    cudaFuncSetAttribute(gemm_eo_kernel<2, 0>, cudaFuncAttributeMaxDynamicSharedMemorySize, SMEM_TOTAL);
    cudaFuncSetAttribute(gemm_eo_kernel<2, 1>, cudaFuncAttributeMaxDynamicSharedMemorySize, SMEM_TOTAL);

    const dim3 grid(16, 8, NB);   // 512 CTAs per GEMM kernel, 2 CTAs/SM

    // 1) parity-packed basis + input split
    gen_basis<<<(KH * KH + 255) / 256, 256>>>();
    split_x<<<(int)(((size_t)NB * NQ * NQ / 8 + 255) / 256), 256>>>(x);

    // 2) Stage 1: E1 = Ce.Xe^T -> E32;  O1 = Co.Xo^T, combine -> Te/To
    gemm_eo_kernel<1, 0><<<grid, 128, SMEM_TOTAL>>>(pCe, pXe, pE, nullptr, nullptr, nullptr);
    gemm_eo_kernel<1, 1><<<grid, 128, SMEM_TOTAL>>>(pCo, pXo, pE, pTe, pTo, nullptr);

    // 3) Stage 2: E2 = Se.Te^T -> E32;  O2 = So.To^T, combine -> out
    gemm_eo_kernel<2, 0><<<grid, 128, SMEM_TOTAL>>>(pSe, pTe, pE, nullptr, nullptr, nullptr);
    gemm_eo_kernel<2, 1><<<grid, 128, SMEM_TOTAL>>>(pSo, pTo, pE, nullptr, nullptr, out);
}

// round 15
// speedup vs baseline: 2.6983x; 1.0556x over previous
#include <cuda_runtime.h>
#include <cuda_fp16.h>
#include <stdint.h>
#include <math.h>

// x: [B=4, 2048, 2048] fp32.
// out[b,u,v] = sum_{p,q} x[b,p,q] * sin(pi*(2u+1)*p/4096) * cos(pi*(2v+1)*q/4096)
//
// Parity fold: C[2047-v,q] = (-1)^q C[v,q],  S[2047-u,p] = -(-1)^p S[u,p]
// Stage 1: E1 = Ce.Xe^T, O1 = Co.Xo^T; T'[v']=E1+O1, T'[2047-v']=E1-O1
// Stage 2: E2 = Se.Te^T, O2 = So.To^T; out[u']=E2+O2, out[2047-u']=O2-E2
// Pure fp16 operands, fp32 accumulate (single HMMA term).
//
// R15 (on R13/R14's 4-kernel split, 128-thread CTAs, 2 CTAs/SM):
//  - fused prologue: basis generated with 2 sincospif + 15 rotations per
//    16 angles (8x fewer MUFU), fused into the split_x kernel;
//  - E scratch stored fp16 (halves E traffic; prefetch = one 32KB buffer);
//  - stage-1 combine transpose done in a single pass (buffers 0+2).

#define NQ 2048
#define KH 1024
#define NB 4
typedef __half h16;

// ---------------- device scratch (allocation-free rule) ----------------
__device__ __align__(256) h16 g_Ce[KH * KH];
__device__ __align__(256) h16 g_Co[KH * KH];
__device__ __align__(256) h16 g_Se[KH * KH];
__device__ __align__(256) h16 g_So[KH * KH];
__device__ __align__(256) h16 g_Xe[(size_t)NB * NQ * KH];
__device__ __align__(256) h16 g_Xo[(size_t)NB * NQ * KH];
__device__ __align__(256) h16 g_Te[(size_t)NB * NQ * KH];
__device__ __align__(256) h16 g_To[(size_t)NB * NQ * KH];
__device__ __align__(256) h16 g_E16[(size_t)NB * KH * NQ];   // E-tile scratch (fp16)

// ---------------- helpers ----------------
__device__ __forceinline__ uint32_t smem_u32(const void* p) {
    uint32_t a;
    asm("{ .reg .u64 t; cvta.to.shared.u64 t, %1; cvt.u32.u64 %0, t; }"
        : "=r"(a) : "l"(p));
    return a;
}
__device__ __forceinline__ uint32_t sw128(uint32_t off) { return off ^ ((off >> 3) & 0x70); }

#define CP16(saddr, gptr) \
    asm volatile("cp.async.cg.shared.global [%0], [%1], 16;" \
                 :: "r"(saddr), "l"(gptr) : "memory")
#define CP_COMMIT() asm volatile("cp.async.commit_group;" ::: "memory")
#define CP_WAIT1() asm volatile("cp.async.wait_group 1;" ::: "memory")
#define CP_WAIT0() asm volatile("cp.async.wait_group 0;" ::: "memory")

#define LDM4(d, addr) \
    asm volatile("ldmatrix.sync.aligned.m8n8.x4.shared.b16 {%0,%1,%2,%3}, [%4];" \
                 : "=r"((d)[0]), "=r"((d)[1]), "=r"((d)[2]), "=r"((d)[3]) : "r"(addr))

#define MMA16816(c, a, b0v, b1v) \
    asm volatile("mma.sync.aligned.m16n8k16.row.col.f32.f16.f16.f32 " \
                 "{%0,%1,%2,%3}, {%4,%5,%6,%7}, {%8,%9}, {%0,%1,%2,%3};" \
                 : "+f"((c)[0]), "+f"((c)[1]), "+f"((c)[2]), "+f"((c)[3]) \
                 : "r"((a)[0]), "r"((a)[1]), "r"((a)[2]), "r"((a)[3]), \
                   "r"(b0v), "r"(b1v))

// ---------------- fused prologue kernel ----------------
// Blocks [0, SPLIT_BLOCKS): x split into Xe/Xo fp16.
// Blocks [SPLIT_BLOCKS, +BASIS_BLOCKS): basis via rotation recurrence.
#define SPLIT_BLOCKS ((int)(((size_t)NB * NQ * NQ / 8 + 255) / 256))   // 8192
#define BASIS_BLOCKS ((KH * (KH / 8) + 255) / 256)                      // 512

__global__ void prologue_kernel(const float* __restrict__ x) {
    if (blockIdx.x < SPLIT_BLOCKS) {
        size_t i = (size_t)blockIdx.x * blockDim.x + threadIdx.x;  // 8 floats/thread
        const size_t total = (size_t)NB * NQ * NQ / 8;
        if (i >= total) return;
        float4 v0 = ((const float4*)x)[2 * i];
        float4 v1 = ((const float4*)x)[2 * i + 1];
        __half2 e01 = __floats2half2_rn(v0.x, v0.z);
        __half2 e23 = __floats2half2_rn(v1.x, v1.z);
        __half2 o01 = __floats2half2_rn(v0.y, v0.w);
        __half2 o23 = __floats2half2_rn(v1.y, v1.w);
        uint2 ue, uo;
        ue.x = *(uint32_t*)&e01; ue.y = *(uint32_t*)&e23;
        uo.x = *(uint32_t*)&o01; uo.y = *(uint32_t*)&o23;
        ((uint2*)g_Xe)[i] = ue;
        ((uint2*)g_Xo)[i] = uo;
    } else {
        int idx = (blockIdx.x - SPLIT_BLOCKS) * blockDim.x + threadIdx.x;
        if (idx >= KH * (KH / 8)) return;
        const int v  = idx >> 7;            // 0..1023
        const int k0 = (idx & 127) * 8;     // 8 consecutive k per thread
        // angles (pi units): alpha_j = (2v+1)*(2*k0 + j)/4096, j = 0..15
        // (2v+1)*2k0 <= 2047*2046 < 2^23: exact fp32. delta exact (pow2 denom).
        float cd, sd;                        // rotation by delta
        sincospif((float)(2 * v + 1) * (1.0f / 4096.0f), &sd, &cd);
        float c, s;
        sincospif((float)((2 * v + 1) * (2 * k0)) * (1.0f / 4096.0f), &s, &c);
        h16 __align__(16) ce8[8], se8[8], co8[8], so8[8];
#pragma unroll
        for (int j = 0; j < 8; ++j) {
            ce8[j] = __float2half(c);
            se8[j] = __float2half(s);
            const float c1 = c * cd - s * sd;    // odd angle
            const float s1 = s * cd + c * sd;
            co8[j] = __float2half(c1);
            so8[j] = __float2half(s1);
            const float c2 = c1 * cd - s1 * sd;  // next even angle
            const float s2 = s1 * cd + c1 * sd;
            c = c2; s = s2;
        }
        const size_t off = (size_t)v * KH + k0;
        *(uint4*)(g_Ce + off) = *(const uint4*)ce8;
        *(uint4*)(g_Se + off) = *(const uint4*)se8;
        *(uint4*)(g_Co + off) = *(const uint4*)co8;
        *(uint4*)(g_So + off) = *(const uint4*)so8;
    }
}

// ---------------- main GEMM kernel ----------------
// CTA: 128x128 output tile, 128 threads = 4 warps of 64x64 (2x2).
// BK=64, 3-stage cp.async pipeline: stage = [A | B] = 32KB, total 96KB
// -> 2 CTAs/SM. 16 K-iterations.
#define TILE_BYTES 16384
#define STG_BYTES  (2 * TILE_BYTES)                // 32768
#define SMEM_TOTAL (3 * STG_BYTES)                 // 98304
#define NITER      16

__device__ __forceinline__ uint32_t a_addr(uint32_t buf, int mt, int s, int lane) {
    int sub = lane >> 3;
    int r = mt + ((sub & 1) << 3) + (lane & 7);
    int c = 2 * s + (sub >> 1);
    return buf + sw128((uint32_t)(r * 128 + c * 16));
}
__device__ __forceinline__ uint32_t b_addr(uint32_t buf, int nt, int s, int lane) {
    int sub = lane >> 3;
    int r = nt + ((sub >> 1) << 3) + (lane & 7);
    int c = 2 * s + (sub & 1);
    return buf + sw128((uint32_t)(r * 128 + c * 16));
}

// PAR: 0 = E pass (write fp16 tile to E16), 1 = O pass (combine with E16).
template <int STAGE, int PAR>
__global__ void __launch_bounds__(128, 2)
gemm_eo_kernel(const h16* __restrict__ A, const h16* __restrict__ Bg,
               h16* __restrict__ E16,
               h16* __restrict__ Te, h16* __restrict__ To,
               float* __restrict__ OutF) {
    extern __shared__ char smem[];
    const uint32_t sbase = smem_u32(smem);
    const int tid = threadIdx.x, wid = tid >> 5, lane = tid & 31;
    const int wm = wid & 1;          // 64 M rows per warp
    const int wn = wid >> 1;         // 64 N cols per warp
    const int m0 = blockIdx.y * 128; // [0,1024)
    const int n0 = blockIdx.x * 128; // [0,2048)
    const int b  = blockIdx.z;
    const size_t planeT = (size_t)NQ * KH;
    const h16* pB = Bg + (size_t)b * planeT;
    const size_t eb = (size_t)b * KH * NQ;   // E16 plane [1024 x 2048]

    float acc[4][8][4];              // 64x64 warp tile
#pragma unroll
    for (int i = 0; i < 4; ++i)
#pragma unroll
        for (int j = 0; j < 8; ++j)
#pragma unroll
            for (int q = 0; q < 4; ++q) acc[i][j][q] = 0.0f;

    // stage load: A tile (128x64) + B tile (128x64), 16 CP16/thread.
#define LOAD_STG(SBUF, K0)                                                      \
    do {                                                                        \
        _Pragma("unroll")                                                       \
        for (int j = 0; j < 8; ++j) {                                           \
            const int e = tid + 128 * j;       /* 0..1023 */                    \
            const int r = e >> 3, c = e & 7;                                    \
            const uint32_t soff = sw128((uint32_t)(r * 128 + c * 16));          \
            CP16((SBUF) + soff,              A  + (size_t)(m0 + r) * KH + (K0) + c * 8); \
            CP16((SBUF) + TILE_BYTES + soff, pB + (size_t)(n0 + r) * KH + (K0) + c * 8); \
        }                                                                       \
    } while (0)

    // E16 prefetch: full 32KB tile (128 rows x 128 fp16) into buffer 1.
    // Per-row XOR swizzle keeps epilogue half2 reads conflict-free.
#define PREF_E16()                                                              \
    do {                                                                        \
        _Pragma("unroll")                                                       \
        for (int j = 0; j < 16; ++j) {                                          \
            const int g = tid + 128 * j;       /* 0..2047 */                    \
            const int r = g >> 4, c = g & 15;  /* row, 16B chunk */             \
            const uint32_t doff = (uint32_t)r * 256 +                           \
                                  (uint32_t)((c ^ ((r & 7) << 1)) << 4);        \
            const h16* src = E16 + eb + (size_t)(m0 + r) * NQ + n0 + c * 8;     \
            CP16(sbase + STG_BYTES + doff, src);                                \
        }                                                                       \
    } while (0)

    LOAD_STG(sbase, 0);
    CP_COMMIT();
    LOAD_STG(sbase + STG_BYTES, 64);
    CP_COMMIT();

    for (int ci = 0; ci < NITER; ++ci) {
        if (PAR == 0 && ci == NITER - 1) { CP_WAIT0(); } else { CP_WAIT1(); }
        __syncthreads();

        const int nc = ci + 2;
        if (nc < NITER) {
            LOAD_STG(sbase + (uint32_t)(nc % 3) * STG_BYTES, nc * 64);
            CP_COMMIT();
        } else if (PAR == 1 && ci == NITER - 2) {
            // buffer 1's last chunk-read was iter 13: dead -> prefetch E16
            PREF_E16();
            CP_COMMIT();
        }

        const uint32_t bA = sbase + (uint32_t)(ci % 3) * STG_BYTES;
        const uint32_t bB = bA + TILE_BYTES;

#pragma unroll
        for (int s = 0; s < 4; ++s) {
            uint32_t ah[4][4], bb[4][4];
#pragma unroll
            for (int mi = 0; mi < 4; ++mi)
                LDM4(ah[mi], a_addr(bA, wm * 64 + mi * 16, s, lane));
#pragma unroll
            for (int nj = 0; nj < 4; ++nj)
                LDM4(bb[nj], b_addr(bB, wn * 64 + nj * 16, s, lane));
#pragma unroll
            for (int mi = 0; mi < 4; ++mi)
#pragma unroll
                for (int ni = 0; ni < 8; ++ni) {
                    const int nj = ni >> 1, nh = (ni & 1) * 2;
                    MMA16816(acc[mi][ni], ah[mi], bb[nj][nh], bb[nj][nh + 1]);
                }
        }
    }

    const int rq = lane >> 2, cq = (lane & 3) * 2;

    if (PAR == 0) {
        // E pass: store fp16 tile (half2 runs; rounding covered by err budget)
#pragma unroll
        for (int mi = 0; mi < 4; ++mi)
#pragma unroll
            for (int ni = 0; ni < 8; ++ni) {
                const int r0 = m0 + wm * 64 + mi * 16 + rq;
                const int p0 = n0 + wn * 64 + ni * 8 + cq;
                *(__half2*)(E16 + eb + (size_t)r0 * NQ + p0) =
                    __floats2half2_rn(acc[mi][ni][0], acc[mi][ni][1]);
                *(__half2*)(E16 + eb + (size_t)(r0 + 8) * NQ + p0) =
                    __floats2half2_rn(acc[mi][ni][2], acc[mi][ni][3]);
            }
        return;
    }

    // ---- combine epilogue (PAR == 1) ----
    CP_WAIT0();          // E16 prefetch landed
    __syncthreads();     // visible to all; buffers 0 and 2 now dead too

    // read E (half2) from swizzled smem buffer 1
#define RDE16(lr, lc) \
    (*(const __half2*)(smem + STG_BYTES + (uint32_t)(lr) * 256 \
                      + (uint32_t)(((((lc) >> 3) ^ (((lr) & 7) << 1))) << 4) \
                      + (uint32_t)(((lc) & 7) << 1)))

    if (STAGE == 2) {
        // out[u,v]: top u=r -> E+O; bottom u=2047-r -> O-E.
        const size_t ob = (size_t)b * NQ * NQ;
#pragma unroll
        for (int mi = 0; mi < 4; ++mi)
#pragma unroll
            for (int ni = 0; ni < 8; ++ni) {
                const int lr0 = wm * 64 + mi * 16 + rq, lr1 = lr0 + 8;
                const int lc = wn * 64 + ni * 8 + cq;
                const float2 eA = __half22float2(RDE16(lr0, lc));
                const float2 eB = __half22float2(RDE16(lr1, lc));
                const float o0 = acc[mi][ni][0], o1 = acc[mi][ni][1];
                const float o2 = acc[mi][ni][2], o3 = acc[mi][ni][3];
                const int r0 = m0 + lr0, r1 = m0 + lr1;
                const size_t c = (size_t)(n0 + lc);
                *(float2*)(OutF + ob + (size_t)r0 * NQ + c) =
                    make_float2(eA.x + o0, eA.y + o1);
                *(float2*)(OutF + ob + (size_t)(2047 - r0) * NQ + c) =
                    make_float2(o0 - eA.x, o1 - eA.y);
                *(float2*)(OutF + ob + (size_t)r1 * NQ + c) =
                    make_float2(eB.x + o2, eB.y + o3);
                *(float2*)(OutF + ob + (size_t)(2047 - r1) * NQ + c) =
                    make_float2(o2 - eB.x, o3 - eB.y);
            }
        return;
    }

    // STAGE == 1: T'[v,p] parity-packed into Te/To via smem transpose.
    // Planes: buf0 = top rows (Te at 0, To at +16KB); buf2 = bottom rows.
    // Seg-level XOR swizzle: seg' = seg ^ (row & 7). Single pass, one sync.
    const size_t tb = (size_t)b * planeT;
#pragma unroll
    for (int mi = 0; mi < 4; ++mi)
#pragma unroll
        for (int ni = 0; ni < 8; ++ni) {
            const int lr0 = wm * 64 + mi * 16 + rq, lr1 = lr0 + 8;
            const int lc = wn * 64 + ni * 8 + cq;
            const float2 eA = __half22float2(RDE16(lr0, lc));
            const float2 eB = __half22float2(RDE16(lr1, lc));
            const float o0 = acc[mi][ni][0], o1 = acc[mi][ni][1];
            const float o2 = acc[mi][ni][2], o3 = acc[mi][ni][3];
            const int pe_l = wn * 32 + ni * 4 + (lane & 3);
            const int seg = pe_l >> 3, wi = pe_l & 7;
            const uint32_t o_lr0 = (uint32_t)lr0 * 128 +
                (uint32_t)((seg ^ (lr0 & 7)) << 4) + (uint32_t)(wi << 1);
            const uint32_t o_lr1 = (uint32_t)lr1 * 128 +
                (uint32_t)((seg ^ (lr1 & 7)) << 4) + (uint32_t)(wi << 1);
            // top half (E + O) -> buffer 0
            *(h16*)(smem + o_lr0)         = __float2half(eA.x + o0);
            *(h16*)(smem + 16384 + o_lr0) = __float2half(eA.y + o1);
            *(h16*)(smem + o_lr1)         = __float2half(eB.x + o2);
            *(h16*)(smem + 16384 + o_lr1) = __float2half(eB.y + o3);
            // bottom half (E - O) -> buffer 2
            *(h16*)(smem + 2 * STG_BYTES + o_lr0)         = __float2half(eA.x - o0);
            *(h16*)(smem + 2 * STG_BYTES + 16384 + o_lr0) = __float2half(eA.y - o1);
            *(h16*)(smem + 2 * STG_BYTES + o_lr1)         = __float2half(eB.x - o2);
            *(h16*)(smem + 2 * STG_BYTES + 16384 + o_lr1) = __float2half(eB.y - o3);
        }
    __syncthreads();
    // cooperative coalesced store: 4096 16B chunks, 32 per thread
#pragma unroll
    for (int j = 0; j < 32; ++j) {
        const int cg = tid + 128 * j;              // 0..4095
        const int halfsel = cg >> 11;              // 0 = top, 1 = bottom
        const int pl = (cg >> 10) & 1;             // 0 = Te, 1 = To
        const int within = cg & 1023;
        const int row = within >> 3, s = within & 7;
        const uint32_t soff = (halfsel ? 2u * STG_BYTES : 0u) +
                              (uint32_t)pl * 16384 + (uint32_t)row * 128 +
                              (uint32_t)((s ^ (row & 7)) << 4);
        const uint4 v = *(const uint4*)(smem + soff);
        const int vg = (halfsel == 0) ? (m0 + row) : (2047 - (m0 + row));
        h16* dst = (pl == 0 ? Te : To) + tb + (size_t)vg * KH
                 + (n0 >> 1) + s * 8;
        *(uint4*)dst = v;
    }
#undef RDE16
#undef PREF_E16
#undef LOAD_STG
}

// ---------------- launch ----------------
extern "C" void kernel_launch(void* const* d_in, const int* in_sizes, int n_in,
                              void* d_out, int out_size) {
    const float* x = (const float*)d_in[0];
    float* out = (float*)d_out;

    h16 *pCe, *pCo, *pSe, *pSo, *pXe, *pXo, *pTe, *pTo, *pE;
    cudaGetSymbolAddress((void**)&pCe, g_Ce);
    cudaGetSymbolAddress((void**)&pCo, g_Co);
    cudaGetSymbolAddress((void**)&pSe, g_Se);
    cudaGetSymbolAddress((void**)&pSo, g_So);
    cudaGetSymbolAddress((void**)&pXe, g_Xe);
    cudaGetSymbolAddress((void**)&pXo, g_Xo);
    cudaGetSymbolAddress((void**)&pTe, g_Te);
    cudaGetSymbolAddress((void**)&pTo, g_To);
    cudaGetSymbolAddress((void**)&pE,  g_E16);

    cudaFuncSetAttribute(gemm_eo_kernel<1, 0>, cudaFuncAttributeMaxDynamicSharedMemorySize, SMEM_TOTAL);
    cudaFuncSetAttribute(gemm_eo_kernel<1, 1>, cudaFuncAttributeMaxDynamicSharedMemorySize, SMEM_TOTAL);
    cudaFuncSetAttribute(gemm_eo_kernel<2, 0>, cudaFuncAttributeMaxDynamicSharedMemorySize, SMEM_TOTAL);
    cudaFuncSetAttribute(gemm_eo_kernel<2, 1>, cudaFuncAttributeMaxDynamicSharedMemorySize, SMEM_TOTAL);

    const dim3 grid(16, 8, NB);   // 512 CTAs per GEMM kernel, 2 CTAs/SM

    // 1) fused prologue: x split + rotation-recurrence basis
    prologue_kernel<<<SPLIT_BLOCKS + BASIS_BLOCKS, 256>>>(x);

    // 2) Stage 1: E1 = Ce.Xe^T -> E16;  O1 = Co.Xo^T, combine -> Te/To
    gemm_eo_kernel<1, 0><<<grid, 128, SMEM_TOTAL>>>(pCe, pXe, pE, nullptr, nullptr, nullptr);
    gemm_eo_kernel<1, 1><<<grid, 128, SMEM_TOTAL>>>(pCo, pXo, pE, pTe, pTo, nullptr);

    // 3) Stage 2: E2 = Se.Te^T -> E16;  O2 = So.To^T, combine -> out
    gemm_eo_kernel<2, 0><<<grid, 128, SMEM_TOTAL>>>(pSe, pTe, pE, nullptr, nullptr, nullptr);
    gemm_eo_kernel<2, 1><<<grid, 128, SMEM_TOTAL>>>(pSo, pTo, pE, nullptr, nullptr, out);
}

// round 16
// speedup vs baseline: 3.0472x; 1.1293x over previous
#include <cuda_runtime.h>
#include <cuda_fp16.h>
#include <stdint.h>
#include <math.h>

// x: [B=4, 2048, 2048] fp32.
// out[b,u,v] = sum_{p,q} x[b,p,q] * sin(pi*(2u+1)*p/4096) * cos(pi*(2v+1)*q/4096)
//
// Level-1 parity fold: T'[v']=E1+O1, T'[2047-v']=E1-O1;
//                      out[u']=E2+O2, out[2047-u']=O2-E2.
// Level-2 fold on the E GEMMs (even-parity bases fold again):
//   E1[v'] = EE1+EO1, E1[1023-v'] = EE1-EO1   (v' in [0,512))
//       EE1 = Cee.Xee^T, EO1 = Ceo.Xeo^T      (M=512, K=512)
//   E2[u'] = EE2+EO2, E2[1023-u'] = EO2-EE2
//       EE2 = See.Tee^T, EO2 = Seo.Teo^T
// O GEMMs stay K=1024:  O1 = Co.Xo^T,  O2 = So.To^T.
// Pure fp16 operands, fp32 accumulate (single HMMA term).

#define NQ 2048
#define KH 1024
#define KQ 512
#define NB 4
typedef __half h16;

// ---------------- device scratch (allocation-free rule) ----------------
__device__ __align__(256) h16 g_Cee[KQ * KQ];
__device__ __align__(256) h16 g_Ceo[KQ * KQ];
__device__ __align__(256) h16 g_See[KQ * KQ];
__device__ __align__(256) h16 g_Seo[KQ * KQ];
__device__ __align__(256) h16 g_Co[KH * KH];
__device__ __align__(256) h16 g_So[KH * KH];
__device__ __align__(256) h16 g_Xee[(size_t)NB * NQ * KQ];
__device__ __align__(256) h16 g_Xeo[(size_t)NB * NQ * KQ];
__device__ __align__(256) h16 g_Xo[(size_t)NB * NQ * KH];
__device__ __align__(256) h16 g_Tee[(size_t)NB * NQ * KQ];
__device__ __align__(256) h16 g_Teo[(size_t)NB * NQ * KQ];
__device__ __align__(256) h16 g_To[(size_t)NB * NQ * KH];
__device__ __align__(256) h16 g_E16[(size_t)NB * KH * NQ];    // level-1 E scratch
__device__ __align__(256) h16 g_EE16[(size_t)NB * KQ * NQ];   // level-2 EE scratch

// ---------------- helpers ----------------
__device__ __forceinline__ uint32_t smem_u32(const void* p) {
    uint32_t a;
    asm("{ .reg .u64 t; cvta.to.shared.u64 t, %1; cvt.u32.u64 %0, t; }"
        : "=r"(a) : "l"(p));
    return a;
}
__device__ __forceinline__ uint32_t sw128(uint32_t off) { return off ^ ((off >> 3) & 0x70); }

#define CP16(saddr, gptr) \
    asm volatile("cp.async.cg.shared.global [%0], [%1], 16;" \
                 :: "r"(saddr), "l"(gptr) : "memory")
#define CP_COMMIT() asm volatile("cp.async.commit_group;" ::: "memory")
#define CP_WAIT1() asm volatile("cp.async.wait_group 1;" ::: "memory")
#define CP_WAIT0() asm volatile("cp.async.wait_group 0;" ::: "memory")

#define LDM4(d, addr) \
    asm volatile("ldmatrix.sync.aligned.m8n8.x4.shared.b16 {%0,%1,%2,%3}, [%4];" \
                 : "=r"((d)[0]), "=r"((d)[1]), "=r"((d)[2]), "=r"((d)[3]) : "r"(addr))

#define MMA16816(c, a, b0v, b1v) \
    asm volatile("mma.sync.aligned.m16n8k16.row.col.f32.f16.f16.f32 " \
                 "{%0,%1,%2,%3}, {%4,%5,%6,%7}, {%8,%9}, {%0,%1,%2,%3};" \
                 : "+f"((c)[0]), "+f"((c)[1]), "+f"((c)[2]), "+f"((c)[3]) \
                 : "r"((a)[0]), "r"((a)[1]), "r"((a)[2]), "r"((a)[3]), \
                   "r"(b0v), "r"(b1v))

// ---------------- fused prologue ----------------
// Blocks [0, SPLIT_BLOCKS): x -> Xee/Xeo/Xo fp16 (q mod 4 = 0 / 2 / odd).
// Blocks [SPLIT_BLOCKS, +BASIS_BLOCKS): all six basis matrices.
#define SPLIT_BLOCKS ((int)(((size_t)NB * NQ * NQ / 8 + 255) / 256))   // 8192
#define BASIS_BLOCKS ((KH * KH + 255) / 256)                            // 4096

__global__ void prologue_kernel(const float* __restrict__ x) {
    if (blockIdx.x < SPLIT_BLOCKS) {
        size_t i = (size_t)blockIdx.x * blockDim.x + threadIdx.x;  // 8 floats/thread
        const size_t total = (size_t)NB * NQ * NQ / 8;
        if (i >= total) return;
        float4 v0 = ((const float4*)x)[2 * i];
        float4 v1 = ((const float4*)x)[2 * i + 1];
        // q = 8t..8t+7:  ee: q=8t,8t+4 (j=2t,2t+1); eo: q=8t+2,8t+6;
        //                o: q odd -> k=4t..4t+3
        __half2 ee = __floats2half2_rn(v0.x, v1.x);
        __half2 eo = __floats2half2_rn(v0.z, v1.z);
        __half2 o01 = __floats2half2_rn(v0.y, v0.w);
        __half2 o23 = __floats2half2_rn(v1.y, v1.w);
        ((__half2*)g_Xee)[i] = ee;
        ((__half2*)g_Xeo)[i] = eo;
        uint2 uo;
        uo.x = *(uint32_t*)&o01; uo.y = *(uint32_t*)&o23;
        ((uint2*)g_Xo)[i] = uo;
    } else {
        int idx = (blockIdx.x - SPLIT_BLOCKS) * blockDim.x + threadIdx.x;
        if (idx >= KH * KH) return;
        int v = idx >> 10, k = idx & 1023;
        // (2v+1)(2k+1) <= 2047*2047 < 2^22: exact fp32
        float a = (float)((2 * v + 1) * (2 * k + 1)) * (1.0f / 4096.0f);
        float c, s;
        sincospif(a, &s, &c);
        g_Co[idx] = __float2half(c);
        g_So[idx] = __float2half(s);
        if (v < KQ && k < KQ) {
            const int j = k, i2 = v * KQ + j;
            float ae = (float)((2 * v + 1) * j) * (1.0f / 1024.0f);
            float ao = (float)((2 * v + 1) * (2 * j + 1)) * (1.0f / 2048.0f);
            float ce, se, co2, so2;
            sincospif(ae, &se, &ce);
            sincospif(ao, &so2, &co2);
            g_Cee[i2] = __float2half(ce);
            g_See[i2] = __float2half(se);
            g_Ceo[i2] = __float2half(co2);
            g_Seo[i2] = __float2half(so2);
        }
    }
}

// ---------------- main GEMM kernel ----------------
// CTA: 128x128 output tile, 128 threads = 4 warps of 64x64 (2x2).
// BK=64, 3-stage cp.async pipeline, 96KB smem -> 2 CTAs/SM.
// KDIM in {512, 1024}; NITER = KDIM/64.
// EPI: 0 = write EE16; 1 = EO-combine (read EE16, write mirrored E16);
//      2 = O1-combine (read E16, transpose, write Tee/Teo/To);
//      3 = O2-combine (read E16, write out).
#define TILE_BYTES 16384
#define STG_BYTES  (2 * TILE_BYTES)                // 32768
#define SMEM_TOTAL (3 * STG_BYTES)                 // 98304

__device__ __forceinline__ uint32_t a_addr(uint32_t buf, int mt, int s, int lane) {
    int sub = lane >> 3;
    int r = mt + ((sub & 1) << 3) + (lane & 7);
    int c = 2 * s + (sub >> 1);
    return buf + sw128((uint32_t)(r * 128 + c * 16));
}
__device__ __forceinline__ uint32_t b_addr(uint32_t buf, int nt, int s, int lane) {
    int sub = lane >> 3;
    int r = nt + ((sub >> 1) << 3) + (lane & 7);
    int c = 2 * s + (sub & 1);
    return buf + sw128((uint32_t)(r * 128 + c * 16));
}
// E-tile smem read (matches PREF swizzle below)
__device__ __forceinline__ __half2 rde16(const char* smem, uint32_t pbufoff,
                                         int lr, int lc) {
    return *(const __half2*)(smem + pbufoff + (uint32_t)lr * 256
                             + (uint32_t)(((lc >> 3) ^ ((lr & 7) << 1)) << 4)
                             + (uint32_t)((lc & 7) << 1));
}

template <int KDIM, int EPI, int BOTNEG>
__global__ void __launch_bounds__(128, 2)
gemm_k(const h16* __restrict__ A, const h16* __restrict__ Bg,
       h16* __restrict__ EEsc, h16* __restrict__ Esc,
       h16* __restrict__ Tee, h16* __restrict__ Teo, h16* __restrict__ To,
       float* __restrict__ OutF) {
    constexpr int NITER = KDIM / 64;
    constexpr int PBUF = (NITER - 3) % 3;          // dead buffer for E prefetch
    extern __shared__ char smem[];
    const uint32_t sbase = smem_u32(smem);
    const int tid = threadIdx.x, wid = tid >> 5, lane = tid & 31;
    const int wm = wid & 1;          // 64 M rows per warp
    const int wn = wid >> 1;         // 64 N cols per warp
    const int m0 = blockIdx.y * 128;
    const int n0 = blockIdx.x * 128;
    const int b  = blockIdx.z;
    const size_t planeB = (size_t)NQ * KDIM;
    const h16* pB = Bg + (size_t)b * planeB;
    // E prefetch source: EPI1 reads EE16 (512-row plane), EPI2/3 read E16 (1024)
    const h16* Esrc = (EPI == 1) ? EEsc + (size_t)b * KQ * NQ
                                 : Esc + (size_t)b * KH * NQ;

    float acc[4][8][4];
#pragma unroll
    for (int i = 0; i < 4; ++i)
#pragma unroll
        for (int j = 0; j < 8; ++j)
#pragma unroll
            for (int q = 0; q < 4; ++q) acc[i][j][q] = 0.0f;

#define LOAD_STG(SBUF, K0)                                                      \
    do {                                                                        \
        _Pragma("unroll")                                                       \
        for (int j = 0; j < 8; ++j) {                                           \
            const int e = tid + 128 * j;                                        \
            const int r = e >> 3, c = e & 7;                                    \
            const uint32_t soff = sw128((uint32_t)(r * 128 + c * 16));          \
            CP16((SBUF) + soff,              A  + (size_t)(m0 + r) * KDIM + (K0) + c * 8); \
            CP16((SBUF) + TILE_BYTES + soff, pB + (size_t)(n0 + r) * KDIM + (K0) + c * 8); \
        }                                                                       \
    } while (0)

#define PREF_E()                                                                \
    do {                                                                        \
        _Pragma("unroll")                                                       \
        for (int j = 0; j < 16; ++j) {                                          \
            const int g = tid + 128 * j;                                        \
            const int r = g >> 4, c = g & 15;                                   \
            const uint32_t doff = (uint32_t)r * 256 +                           \
                                  (uint32_t)((c ^ ((r & 7) << 1)) << 4);        \
            CP16(sbase + PBUF * STG_BYTES + doff,                               \
                 Esrc + (size_t)(m0 + r) * NQ + n0 + c * 8);                    \
        }                                                                       \
    } while (0)

    LOAD_STG(sbase, 0);
    CP_COMMIT();
    LOAD_STG(sbase + STG_BYTES, 64);
    CP_COMMIT();

    for (int ci = 0; ci < NITER; ++ci) {
        if (EPI == 0 && ci == NITER - 1) { CP_WAIT0(); } else { CP_WAIT1(); }
        __syncthreads();

        const int nc = ci + 2;
        if (nc < NITER) {
            LOAD_STG(sbase + (uint32_t)(nc % 3) * STG_BYTES, nc * 64);
            CP_COMMIT();
        } else if (EPI != 0 && ci == NITER - 2) {
            PREF_E();
            CP_COMMIT();
        }

        const uint32_t bA = sbase + (uint32_t)(ci % 3) * STG_BYTES;
        const uint32_t bB = bA + TILE_BYTES;

#pragma unroll
        for (int s = 0; s < 4; ++s) {
            uint32_t ah[4][4], bb[4][4];
#pragma unroll
            for (int mi = 0; mi < 4; ++mi)
                LDM4(ah[mi], a_addr(bA, wm * 64 + mi * 16, s, lane));
#pragma unroll
            for (int nj = 0; nj < 4; ++nj)
                LDM4(bb[nj], b_addr(bB, wn * 64 + nj * 16, s, lane));
#pragma unroll
            for (int mi = 0; mi < 4; ++mi)
#pragma unroll
                for (int ni = 0; ni < 8; ++ni) {
                    const int nj = ni >> 1, nh = (ni & 1) * 2;
                    MMA16816(acc[mi][ni], ah[mi], bb[nj][nh], bb[nj][nh + 1]);
                }
        }
    }

    const int rq = lane >> 2, cq = (lane & 3) * 2;

    if (EPI == 0) {
        // write EE tile fp16 (plane [512 x 2048])
        const size_t ebq = (size_t)b * KQ * NQ;
#pragma unroll
        for (int mi = 0; mi < 4; ++mi)
#pragma unroll
            for (int ni = 0; ni < 8; ++ni) {
                const int r0 = m0 + wm * 64 + mi * 16 + rq;
                const int p0 = n0 + wn * 64 + ni * 8 + cq;
                *(__half2*)(EEsc + ebq + (size_t)r0 * NQ + p0) =
                    __floats2half2_rn(acc[mi][ni][0], acc[mi][ni][1]);
                *(__half2*)(EEsc + ebq + (size_t)(r0 + 8) * NQ + p0) =
                    __floats2half2_rn(acc[mi][ni][2], acc[mi][ni][3]);
            }
        return;
    }

    CP_WAIT0();          // E prefetch landed
    __syncthreads();

    const uint32_t pboff = (uint32_t)PBUF * STG_BYTES;

    if (EPI == 1) {
        // EO-combine: E[v'] = EE + EO; E[1023-v'] = BOTNEG ? EO-EE : EE-EO
        const size_t ebh = (size_t)b * KH * NQ;
#pragma unroll
        for (int mi = 0; mi < 4; ++mi)
#pragma unroll
            for (int ni = 0; ni < 8; ++ni) {
                const int lr0 = wm * 64 + mi * 16 + rq, lr1 = lr0 + 8;
                const int lc = wn * 64 + ni * 8 + cq;
                const float2 eA = __half22float2(rde16(smem, pboff, lr0, lc));
                const float2 eB = __half22float2(rde16(smem, pboff, lr1, lc));
                const float o0 = acc[mi][ni][0], o1 = acc[mi][ni][1];
                const float o2 = acc[mi][ni][2], o3 = acc[mi][ni][3];
                const int v0 = m0 + lr0, v1 = m0 + lr1;
                const size_t c = (size_t)(n0 + lc);
                *(__half2*)(Esc + ebh + (size_t)v0 * NQ + c) =
                    __floats2half2_rn(eA.x + o0, eA.y + o1);
                *(__half2*)(Esc + ebh + (size_t)v1 * NQ + c) =
                    __floats2half2_rn(eB.x + o2, eB.y + o3);
                const float b0x = BOTNEG ? (o0 - eA.x) : (eA.x - o0);
                const float b0y = BOTNEG ? (o1 - eA.y) : (eA.y - o1);
                const float b1x = BOTNEG ? (o2 - eB.x) : (eB.x - o2);
                const float b1y = BOTNEG ? (o3 - eB.y) : (eB.y - o3);
                *(__half2*)(Esc + ebh + (size_t)(1023 - v0) * NQ + c) =
                    __floats2half2_rn(b0x, b0y);
                *(__half2*)(Esc + ebh + (size_t)(1023 - v1) * NQ + c) =
                    __floats2half2_rn(b1x, b1y);
            }
        return;
    }

    if (EPI == 3) {
        // out[u,v]: top u -> E+O; bottom 2047-u -> O-E.
        const size_t ob = (size_t)b * NQ * NQ;
#pragma unroll
        for (int mi = 0; mi < 4; ++mi)
#pragma unroll
            for (int ni = 0; ni < 8; ++ni) {
                const int lr0 = wm * 64 + mi * 16 + rq, lr1 = lr0 + 8;
                const int lc = wn * 64 + ni * 8 + cq;
                const float2 eA = __half22float2(rde16(smem, pboff, lr0, lc));
                const float2 eB = __half22float2(rde16(smem, pboff, lr1, lc));
                const float o0 = acc[mi][ni][0], o1 = acc[mi][ni][1];
                const float o2 = acc[mi][ni][2], o3 = acc[mi][ni][3];
                const int r0 = m0 + lr0, r1 = m0 + lr1;
                const size_t c = (size_t)(n0 + lc);
                *(float2*)(OutF + ob + (size_t)r0 * NQ + c) =
                    make_float2(eA.x + o0, eA.y + o1);
                *(float2*)(OutF + ob + (size_t)(2047 - r0) * NQ + c) =
                    make_float2(o0 - eA.x, o1 - eA.y);
                *(float2*)(OutF + ob + (size_t)r1 * NQ + c) =
                    make_float2(eB.x + o2, eB.y + o3);
                *(float2*)(OutF + ob + (size_t)(2047 - r1) * NQ + c) =
                    make_float2(o2 - eB.x, o3 - eB.y);
            }
        return;
    }

    // EPI == 2: O1-combine. T'[v,p]: top v, bottom 2047-v.
    // Even-p values parity-split over pe into Tee/Teo; odd-p values into To.
    // smem regions: top half in buffer 0 (offset 0), bottom in buffer 2.
    // Region layout: Tee[128x32] at 0 (row 64B), Teo at 8192, To[128x64] at 16384.
#pragma unroll
    for (int mi = 0; mi < 4; ++mi)
#pragma unroll
        for (int ni = 0; ni < 8; ++ni) {
            const int lr0 = wm * 64 + mi * 16 + rq, lr1 = lr0 + 8;
            const int lc = wn * 64 + ni * 8 + cq;
            const float2 eA = __half22float2(rde16(smem, pboff, lr0, lc));
            const float2 eB = __half22float2(rde16(smem, pboff, lr1, lc));
            const float o0 = acc[mi][ni][0], o1 = acc[mi][ni][1];
            const float o2 = acc[mi][ni][2], o3 = acc[mi][ni][3];
            const int pe_l = (lc >> 1);            // 0..63
            const int par = pe_l & 1;              // 0=Tee, 1=Teo
            const int jl = pe_l >> 1;              // 0..31
            const uint32_t te0 = (uint32_t)(par ? 8192 : 0) + (uint32_t)lr0 * 64 +
                (uint32_t)(((jl >> 3) ^ (lr0 & 3)) << 4) + (uint32_t)((jl & 7) << 1);
            const uint32_t te1 = (uint32_t)(par ? 8192 : 0) + (uint32_t)lr1 * 64 +
                (uint32_t)(((jl >> 3) ^ (lr1 & 3)) << 4) + (uint32_t)((jl & 7) << 1);
            const uint32_t to0 = 16384u + (uint32_t)lr0 * 128 +
                (uint32_t)(((pe_l >> 3) ^ (lr0 & 7)) << 4) + (uint32_t)((pe_l & 7) << 1);
            const uint32_t to1 = 16384u + (uint32_t)lr1 * 128 +
                (uint32_t)(((pe_l >> 3) ^ (lr1 & 7)) << 4) + (uint32_t)((pe_l & 7) << 1);
            // top half -> region at 0
            *(h16*)(smem + te0) = __float2half(eA.x + o0);
            *(h16*)(smem + to0) = __float2half(eA.y + o1);
            *(h16*)(smem + te1) = __float2half(eB.x + o2);
            *(h16*)(smem + to1) = __float2half(eB.y + o3);
            // bottom half (E - O) -> region at 2*STG_BYTES
            *(h16*)(smem + 2 * STG_BYTES + te0) = __float2half(eA.x - o0);
            *(h16*)(smem + 2 * STG_BYTES + to0) = __float2half(eA.y - o1);
            *(h16*)(smem + 2 * STG_BYTES + te1) = __float2half(eB.x - o2);
            *(h16*)(smem + 2 * STG_BYTES + to1) = __float2half(eB.y - o3);
        }
    __syncthreads();
    // cooperative store: 4096 16B chunks (2 halves x (512 + 512 + 1024))
    {
        const size_t tbq = (size_t)b * NQ * KQ;
        const size_t tbh = (size_t)b * NQ * KH;
#pragma unroll
        for (int j = 0; j < 32; ++j) {
            const int cg = tid + 128 * j;              // 0..4095
            const int halfsel = cg >> 11;
            const int within = cg & 2047;
            const uint32_t hbase = halfsel ? 2u * STG_BYTES : 0u;
            if (within < 1024) {
                const int pl = within >> 9;            // 0=Tee, 1=Teo
                const int w2 = within & 511;
                const int row = w2 >> 2, s = w2 & 3;
                const uint32_t soff = hbase + (uint32_t)(pl ? 8192 : 0) +
                    (uint32_t)row * 64 + (uint32_t)((s ^ (row & 3)) << 4);
                const uint4 v = *(const uint4*)(smem + soff);
                const int vg = halfsel ? (2047 - (m0 + row)) : (m0 + row);
                h16* dst = (pl ? Teo : Tee) + tbq + (size_t)vg * KQ
                         + (n0 >> 2) + s * 8;
                *(uint4*)dst = v;
            } else {
                const int w2 = within - 1024;
                const int row = w2 >> 3, s = w2 & 7;
                const uint32_t soff = hbase + 16384u +
                    (uint32_t)row * 128 + (uint32_t)((s ^ (row & 7)) << 4);
                const uint4 v = *(const uint4*)(smem + soff);
                const int vg = halfsel ? (2047 - (m0 + row)) : (m0 + row);
                h16* dst = To + tbh + (size_t)vg * KH + (n0 >> 1) + s * 8;
                *(uint4*)dst = v;
            }
        }
    }
#undef PREF_E
#undef LOAD_STG
}

// ---------------- launch ----------------
extern "C" void kernel_launch(void* const* d_in, const int* in_sizes, int n_in,
                              void* d_out, int out_size) {
    const float* x = (const float*)d_in[0];
    float* out = (float*)d_out;

    h16 *pCee, *pCeo, *pSee, *pSeo, *pCo, *pSo;
    h16 *pXee, *pXeo, *pXo, *pTee, *pTeo, *pTo, *pE, *pEE;
    cudaGetSymbolAddress((void**)&pCee, g_Cee);
    cudaGetSymbolAddress((void**)&pCeo, g_Ceo);
    cudaGetSymbolAddress((void**)&pSee, g_See);
    cudaGetSymbolAddress((void**)&pSeo, g_Seo);
    cudaGetSymbolAddress((void**)&pCo,  g_Co);
    cudaGetSymbolAddress((void**)&pSo,  g_So);
    cudaGetSymbolAddress((void**)&pXee, g_Xee);
    cudaGetSymbolAddress((void**)&pXeo, g_Xeo);
    cudaGetSymbolAddress((void**)&pXo,  g_Xo);
    cudaGetSymbolAddress((void**)&pTee, g_Tee);
    cudaGetSymbolAddress((void**)&pTeo, g_Teo);
    cudaGetSymbolAddress((void**)&pTo,  g_To);
    cudaGetSymbolAddress((void**)&pE,   g_E16);
    cudaGetSymbolAddress((void**)&pEE,  g_EE16);

    cudaFuncSetAttribute(gemm_k<512, 0, 0>,  cudaFuncAttributeMaxDynamicSharedMemorySize, SMEM_TOTAL);
    cudaFuncSetAttribute(gemm_k<512, 1, 0>,  cudaFuncAttributeMaxDynamicSharedMemorySize, SMEM_TOTAL);
    cudaFuncSetAttribute(gemm_k<512, 1, 1>,  cudaFuncAttributeMaxDynamicSharedMemorySize, SMEM_TOTAL);
    cudaFuncSetAttribute(gemm_k<1024, 2, 0>, cudaFuncAttributeMaxDynamicSharedMemorySize, SMEM_TOTAL);
    cudaFuncSetAttribute(gemm_k<1024, 3, 0>, cudaFuncAttributeMaxDynamicSharedMemorySize, SMEM_TOTAL);

    const dim3 gridQ(16, 4, NB);   // M=512 kernels: 256 CTAs (single wave)
    const dim3 gridH(16, 8, NB);   // M=1024 kernels: 512 CTAs

    // 1) fused prologue: x 3-way split + six basis matrices
    prologue_kernel<<<SPLIT_BLOCKS + BASIS_BLOCKS, 256>>>(x);

    // 2) Stage 1
    gemm_k<512, 0, 0><<<gridQ, 128, SMEM_TOTAL>>>(      // EE1 = Cee.Xee -> EE16
        pCee, pXee, pEE, nullptr, nullptr, nullptr, nullptr, nullptr);
    gemm_k<512, 1, 0><<<gridQ, 128, SMEM_TOTAL>>>(      // EO1; E1 = EE±EO -> E16
        pCeo, pXeo, pEE, pE, nullptr, nullptr, nullptr, nullptr);
    gemm_k<1024, 2, 0><<<gridH, 128, SMEM_TOTAL>>>(     // O1 = Co.Xo; -> Tee/Teo/To
        pCo, pXo, nullptr, pE, pTee, pTeo, pTo, nullptr);

    // 3) Stage 2
    gemm_k<512, 0, 0><<<gridQ, 128, SMEM_TOTAL>>>(      // EE2 = See.Tee -> EE16
        pSee, pTee, pEE, nullptr, nullptr, nullptr, nullptr, nullptr);
    gemm_k<512, 1, 1><<<gridQ, 128, SMEM_TOTAL>>>(      // EO2; E2 = EO±EE -> E16
        pSeo, pTeo, pEE, pE, nullptr, nullptr, nullptr, nullptr);
    gemm_k<1024, 3, 0><<<gridH, 128, SMEM_TOTAL>>>(     // O2 = So.To; -> out
        pSo, pTo, nullptr, pE, nullptr, nullptr, nullptr, out);
}

// round 17
// speedup vs baseline: 3.1800x; 1.0436x over previous
#include <cuda_runtime.h>
#include <cuda_fp16.h>
#include <stdint.h>
#include <math.h>

// x: [B=4, 2048, 2048] fp32.
// out[b,u,v] = sum_{p,q} x[b,p,q] * sin(pi*(2u+1)*p/4096) * cos(pi*(2v+1)*q/4096)
//
// Level-1 parity fold: T'[v']=E1+O1, T'[2047-v']=E1-O1;
//                      out[u']=E2+O2, out[2047-u']=O2-E2.
// Level-2 fold on the E GEMMs:
//   E1[v'] = EE1+EO1, E1[1023-v'] = EE1-EO1   (EE1=Cee.Xee^T, EO1=Ceo.Xeo^T)
//   E2[u'] = EE2+EO2, E2[1023-u'] = EO2-EE2   (EE2=See.Tee^T, EO2=Seo.Teo^T)
// O GEMMs K=1024: O1 = Co.Xo^T, O2 = So.To^T.
// Pure fp16 operands, fp32 accumulate (single HMMA term).
//
// R17: mbarrier producer/consumer rings replace per-chunk __syncthreads in
// the GEMM mainloop -> warps skew up to 2-3 chunks, covering LDSM/issue
// bubbles with other warps' MMA phases.

#define NQ 2048
#define KH 1024
#define KQ 512
#define NB 4
typedef __half h16;

// ---------------- device scratch (allocation-free rule) ----------------
__device__ __align__(256) h16 g_Cee[KQ * KQ];
__device__ __align__(256) h16 g_Ceo[KQ * KQ];
__device__ __align__(256) h16 g_See[KQ * KQ];
__device__ __align__(256) h16 g_Seo[KQ * KQ];
__device__ __align__(256) h16 g_Co[KH * KH];
__device__ __align__(256) h16 g_So[KH * KH];
__device__ __align__(256) h16 g_Xee[(size_t)NB * NQ * KQ];
__device__ __align__(256) h16 g_Xeo[(size_t)NB * NQ * KQ];
__device__ __align__(256) h16 g_Xo[(size_t)NB * NQ * KH];
__device__ __align__(256) h16 g_Tee[(size_t)NB * NQ * KQ];
__device__ __align__(256) h16 g_Teo[(size_t)NB * NQ * KQ];
__device__ __align__(256) h16 g_To[(size_t)NB * NQ * KH];
__device__ __align__(256) h16 g_E16[(size_t)NB * KH * NQ];    // level-1 E scratch
__device__ __align__(256) h16 g_EE16[(size_t)NB * KQ * NQ];   // level-2 EE scratch

// ---------------- helpers ----------------
__device__ __forceinline__ uint32_t smem_u32(const void* p) {
    uint32_t a;
    asm("{ .reg .u64 t; cvta.to.shared.u64 t, %1; cvt.u32.u64 %0, t; }"
        : "=r"(a) : "l"(p));
    return a;
}
__device__ __forceinline__ uint32_t sw128(uint32_t off) { return off ^ ((off >> 3) & 0x70); }

#define CP16(saddr, gptr) \
    asm volatile("cp.async.cg.shared.global [%0], [%1], 16;" \
                 :: "r"(saddr), "l"(gptr) : "memory")

#define LDM4(d, addr) \
    asm volatile("ldmatrix.sync.aligned.m8n8.x4.shared.b16 {%0,%1,%2,%3}, [%4];" \
                 : "=r"((d)[0]), "=r"((d)[1]), "=r"((d)[2]), "=r"((d)[3]) : "r"(addr))

#define MMA16816(c, a, b0v, b1v) \
    asm volatile("mma.sync.aligned.m16n8k16.row.col.f32.f16.f16.f32 " \
                 "{%0,%1,%2,%3}, {%4,%5,%6,%7}, {%8,%9}, {%0,%1,%2,%3};" \
                 : "+f"((c)[0]), "+f"((c)[1]), "+f"((c)[2]), "+f"((c)[3]) \
                 : "r"((a)[0]), "r"((a)[1]), "r"((a)[2]), "r"((a)[3]), \
                   "r"(b0v), "r"(b1v))

// ---- mbarrier ops ----
#define MBAR_INIT(addr, cnt) \
    asm volatile("mbarrier.init.shared.b64 [%0], %1;" :: "r"(addr), "r"(cnt) : "memory")
#define MBAR_ARRIVE(addr) \
    asm volatile("mbarrier.arrive.shared.b64 _, [%0];" :: "r"(addr) : "memory")
#define CPASYNC_MBAR_ARRIVE(addr) \
    asm volatile("cp.async.mbarrier.arrive.noinc.shared.b64 [%0];" :: "r"(addr) : "memory")
#define MBAR_WAIT(addr, par) do {                                               \
    uint32_t _m = (addr), _p = (par), _d;                                       \
    asm volatile("{\n\t.reg .pred p;\n\t"                                       \
        "mbarrier.try_wait.parity.acquire.cta.shared::cta.b64 p, [%1], %2;\n\t" \
        "selp.b32 %0, 1, 0, p;\n\t}"                                            \
        : "=r"(_d) : "r"(_m), "r"(_p) : "memory");                              \
    if (!_d) {                                                                  \
        asm volatile("{\n\t.reg .pred P1;\n\t"                                  \
            "WL_%=:\n\t"                                                        \
            "mbarrier.try_wait.parity.acquire.cta.shared::cta.b64 P1, [%0], %1, 0x989680;\n\t" \
            "@P1 bra.uni WD_%=;\n\t"                                            \
            "bra.uni WL_%=;\n\t"                                                \
            "WD_%=:\n\t}" :: "r"(_m), "r"(_p) : "memory");                      \
    } } while (0)

// ---------------- fused prologue ----------------
#define SPLIT_BLOCKS ((int)(((size_t)NB * NQ * NQ / 8 + 255) / 256))   // 8192
#define BASIS_BLOCKS ((KH * KH + 255) / 256)                            // 4096

__global__ void prologue_kernel(const float* __restrict__ x) {
    if (blockIdx.x < SPLIT_BLOCKS) {
        size_t i = (size_t)blockIdx.x * blockDim.x + threadIdx.x;  // 8 floats/thread
        const size_t total = (size_t)NB * NQ * NQ / 8;
        if (i >= total) return;
        float4 v0 = ((const float4*)x)[2 * i];
        float4 v1 = ((const float4*)x)[2 * i + 1];
        __half2 ee = __floats2half2_rn(v0.x, v1.x);
        __half2 eo = __floats2half2_rn(v0.z, v1.z);
        __half2 o01 = __floats2half2_rn(v0.y, v0.w);
        __half2 o23 = __floats2half2_rn(v1.y, v1.w);
        ((__half2*)g_Xee)[i] = ee;
        ((__half2*)g_Xeo)[i] = eo;
        uint2 uo;
        uo.x = *(uint32_t*)&o01; uo.y = *(uint32_t*)&o23;
        ((uint2*)g_Xo)[i] = uo;
    } else {
        int idx = (blockIdx.x - SPLIT_BLOCKS) * blockDim.x + threadIdx.x;
        if (idx >= KH * KH) return;
        int v = idx >> 10, k = idx & 1023;
        float a = (float)((2 * v + 1) * (2 * k + 1)) * (1.0f / 4096.0f);
        float c, s;
        sincospif(a, &s, &c);
        g_Co[idx] = __float2half(c);
        g_So[idx] = __float2half(s);
        if (v < KQ && k < KQ) {
            const int j = k, i2 = v * KQ + j;
            float ae = (float)((2 * v + 1) * j) * (1.0f / 1024.0f);
            float ao = (float)((2 * v + 1) * (2 * j + 1)) * (1.0f / 2048.0f);
            float ce, se, co2, so2;
            sincospif(ae, &se, &ce);
            sincospif(ao, &so2, &co2);
            g_Cee[i2] = __float2half(ce);
            g_See[i2] = __float2half(se);
            g_Ceo[i2] = __float2half(co2);
            g_Seo[i2] = __float2half(so2);
        }
    }
}

// ---------------- main GEMM kernel ----------------
// CTA: 128x128 output tile, 128 threads = 4 warps of 64x64 (2x2).
// BK=64, 3-stage ring with mbarrier full/empty pairs; 2 CTAs/SM.
// EPI: 0 = write EE16; 1 = EO-combine -> E16 (mirrored);
//      2 = O1-combine -> Tee/Teo/To; 3 = O2-combine -> out.
#define TILE_BYTES 16384
#define STG_BYTES  (2 * TILE_BYTES)                // 32768
#define MBAR_OFF   (3 * STG_BYTES)                 // 98304
#define SMEM_TOTAL (3 * STG_BYTES + 128)           // 98432

__device__ __forceinline__ uint32_t a_addr(uint32_t buf, int mt, int s, int lane) {
    int sub = lane >> 3;
    int r = mt + ((sub & 1) << 3) + (lane & 7);
    int c = 2 * s + (sub >> 1);
    return buf + sw128((uint32_t)(r * 128 + c * 16));
}
__device__ __forceinline__ uint32_t b_addr(uint32_t buf, int nt, int s, int lane) {
    int sub = lane >> 3;
    int r = nt + ((sub >> 1) << 3) + (lane & 7);
    int c = 2 * s + (sub & 1);
    return buf + sw128((uint32_t)(r * 128 + c * 16));
}
__device__ __forceinline__ __half2 rde16(const char* smem, uint32_t pbufoff,
                                         int lr, int lc) {
    return *(const __half2*)(smem + pbufoff + (uint32_t)lr * 256
                             + (uint32_t)(((lc >> 3) ^ ((lr & 7) << 1)) << 4)
                             + (uint32_t)((lc & 7) << 1));
}

template <int KDIM, int EPI, int BOTNEG>
__global__ void __launch_bounds__(128, 2)
gemm_k(const h16* __restrict__ A, const h16* __restrict__ Bg,
       h16* __restrict__ EEsc, h16* __restrict__ Esc,
       h16* __restrict__ Tee, h16* __restrict__ Teo, h16* __restrict__ To,
       float* __restrict__ OutF) {
    constexpr int NITER = KDIM / 64;
    constexpr int PBUF = (NITER - 3) % 3;          // buffer reused for E prefetch
    constexpr int FP = (NITER - 3) / 3 + 1;        // E-prefetch fill index
    extern __shared__ char smem[];
    const uint32_t sbase = smem_u32(smem);
    const uint32_t mb = sbase + MBAR_OFF;          // full[s]=mb+8s, empty[s]=mb+24+8s
    const int tid = threadIdx.x, wid = tid >> 5, lane = tid & 31;
    const int wm = wid & 1;
    const int wn = wid >> 1;
    const int m0 = blockIdx.y * 128;
    const int n0 = blockIdx.x * 128;
    const int b  = blockIdx.z;
    const size_t planeB = (size_t)NQ * KDIM;
    const h16* pB = Bg + (size_t)b * planeB;
    const h16* Esrc = (EPI == 1) ? EEsc + (size_t)b * KQ * NQ
                                 : Esc + (size_t)b * KH * NQ;

    float acc[4][8][4];
#pragma unroll
    for (int i = 0; i < 4; ++i)
#pragma unroll
        for (int j = 0; j < 8; ++j)
#pragma unroll
            for (int q = 0; q < 4; ++q) acc[i][j][q] = 0.0f;

#define LOAD_STG(SBUF, K0)                                                      \
    do {                                                                        \
        _Pragma("unroll")                                                       \
        for (int j = 0; j < 8; ++j) {                                           \
            const int e = tid + 128 * j;                                        \
            const int r = e >> 3, c = e & 7;                                    \
            const uint32_t soff = sw128((uint32_t)(r * 128 + c * 16));          \
            CP16((SBUF) + soff,              A  + (size_t)(m0 + r) * KDIM + (K0) + c * 8); \
            CP16((SBUF) + TILE_BYTES + soff, pB + (size_t)(n0 + r) * KDIM + (K0) + c * 8); \
        }                                                                       \
    } while (0)

#define PREF_E()                                                                \
    do {                                                                        \
        _Pragma("unroll")                                                       \
        for (int j = 0; j < 16; ++j) {                                          \
            const int g = tid + 128 * j;                                        \
            const int r = g >> 4, c = g & 15;                                   \
            const uint32_t doff = (uint32_t)r * 256 +                           \
                                  (uint32_t)((c ^ ((r & 7) << 1)) << 4);        \
            CP16(sbase + PBUF * STG_BYTES + doff,                               \
                 Esrc + (size_t)(m0 + r) * NQ + n0 + c * 8);                    \
        }                                                                       \
    } while (0)

    // ring init: full/empty pairs, 128 arrivals each
    if (tid == 0) {
#pragma unroll
        for (int s = 0; s < 3; ++s) {
            MBAR_INIT(mb + 8u * s, 128);
            MBAR_INIT(mb + 24u + 8u * s, 128);
        }
    }
    __syncthreads();
    // initial empty round: completes phase 0 of every empty barrier
    MBAR_ARRIVE(mb + 24u);
    MBAR_ARRIVE(mb + 32u);
    MBAR_ARRIVE(mb + 40u);

    // prologue fills: chunks 0,1 (fill 0 of stages 0,1 — no empty wait needed)
    LOAD_STG(sbase, 0);
    CPASYNC_MBAR_ARRIVE(mb);
    LOAD_STG(sbase + STG_BYTES, 64);
    CPASYNC_MBAR_ARRIVE(mb + 8u);

    for (int ci = 0; ci < NITER; ++ci) {
        // producer: fill chunk ci+2 (fill f2 of stage s2)
        const int c2 = ci + 2;
        if (c2 < NITER) {
            const int s2 = c2 % 3, f2 = c2 / 3;
            MBAR_WAIT(mb + 24u + 8u * s2, (uint32_t)(f2 & 1));
            LOAD_STG(sbase + (uint32_t)s2 * STG_BYTES, c2 * 64);
            CPASYNC_MBAR_ARRIVE(mb + 8u * s2);
        } else if (EPI != 0 && ci == NITER - 2) {
            // E prefetch = fill FP of stage PBUF
            MBAR_WAIT(mb + 24u + 8u * PBUF, (uint32_t)(FP & 1));
            PREF_E();
            CPASYNC_MBAR_ARRIVE(mb + 8u * PBUF);
        }

        // consumer: chunk ci = fill ci/3 of stage ci%3
        const int s = ci % 3, f = ci / 3;
        MBAR_WAIT(mb + 8u * s, (uint32_t)(f & 1));

        const uint32_t bA = sbase + (uint32_t)s * STG_BYTES;
        const uint32_t bB = bA + TILE_BYTES;
#pragma unroll
        for (int st = 0; st < 4; ++st) {
            uint32_t ah[4][4], bb[4][4];
#pragma unroll
            for (int mi = 0; mi < 4; ++mi)
                LDM4(ah[mi], a_addr(bA, wm * 64 + mi * 16, st, lane));
#pragma unroll
            for (int nj = 0; nj < 4; ++nj)
                LDM4(bb[nj], b_addr(bB, wn * 64 + nj * 16, st, lane));
#pragma unroll
            for (int mi = 0; mi < 4; ++mi)
#pragma unroll
                for (int ni = 0; ni < 8; ++ni) {
                    const int nj = ni >> 1, nh = (ni & 1) * 2;
                    MMA16816(acc[mi][ni], ah[mi], bb[nj][nh], bb[nj][nh + 1]);
                }
        }
        // reads done (MMA issue implies LDSM writeback): release the stage
        MBAR_ARRIVE(mb + 24u + 8u * s);
    }

    const int rq = lane >> 2, cq = (lane & 3) * 2;

    if (EPI == 0) {
        const size_t ebq = (size_t)b * KQ * NQ;
#pragma unroll
        for (int mi = 0; mi < 4; ++mi)
#pragma unroll
            for (int ni = 0; ni < 8; ++ni) {
                const int r0 = m0 + wm * 64 + mi * 16 + rq;
                const int p0 = n0 + wn * 64 + ni * 8 + cq;
                *(__half2*)(EEsc + ebq + (size_t)r0 * NQ + p0) =
                    __floats2half2_rn(acc[mi][ni][0], acc[mi][ni][1]);
                *(__half2*)(EEsc + ebq + (size_t)(r0 + 8) * NQ + p0) =
                    __floats2half2_rn(acc[mi][ni][2], acc[mi][ni][3]);
            }
        return;
    }

    // wait E prefetch (fill FP of stage PBUF)
    MBAR_WAIT(mb + 8u * PBUF, (uint32_t)(FP & 1));
    const uint32_t pboff = (uint32_t)PBUF * STG_BYTES;

    if (EPI == 1) {
        const size_t ebh = (size_t)b * KH * NQ;
#pragma unroll
        for (int mi = 0; mi < 4; ++mi)
#pragma unroll
            for (int ni = 0; ni < 8; ++ni) {
                const int lr0 = wm * 64 + mi * 16 + rq, lr1 = lr0 + 8;
                const int lc = wn * 64 + ni * 8 + cq;
                const float2 eA = __half22float2(rde16(smem, pboff, lr0, lc));
                const float2 eB = __half22float2(rde16(smem, pboff, lr1, lc));
                const float o0 = acc[mi][ni][0], o1 = acc[mi][ni][1];
                const float o2 = acc[mi][ni][2], o3 = acc[mi][ni][3];
                const int v0 = m0 + lr0, v1 = m0 + lr1;
                const size_t c = (size_t)(n0 + lc);
                *(__half2*)(Esc + ebh + (size_t)v0 * NQ + c) =
                    __floats2half2_rn(eA.x + o0, eA.y + o1);
                *(__half2*)(Esc + ebh + (size_t)v1 * NQ + c) =
                    __floats2half2_rn(eB.x + o2, eB.y + o3);
                const float b0x = BOTNEG ? (o0 - eA.x) : (eA.x - o0);
                const float b0y = BOTNEG ? (o1 - eA.y) : (eA.y - o1);
                const float b1x = BOTNEG ? (o2 - eB.x) : (eB.x - o2);
                const float b1y = BOTNEG ? (o3 - eB.y) : (eB.y - o3);
                *(__half2*)(Esc + ebh + (size_t)(1023 - v0) * NQ + c) =
                    __floats2half2_rn(b0x, b0y);
                *(__half2*)(Esc + ebh + (size_t)(1023 - v1) * NQ + c) =
                    __floats2half2_rn(b1x, b1y);
            }
        return;
    }

    if (EPI == 3) {
        const size_t ob = (size_t)b * NQ * NQ;
#pragma unroll
        for (int mi = 0; mi < 4; ++mi)
#pragma unroll
            for (int ni = 0; ni < 8; ++ni) {
                const int lr0 = wm * 64 + mi * 16 + rq, lr1 = lr0 + 8;
                const int lc = wn * 64 + ni * 8 + cq;
                const float2 eA = __half22float2(rde16(smem, pboff, lr0, lc));
                const float2 eB = __half22float2(rde16(smem, pboff, lr1, lc));
                const float o0 = acc[mi][ni][0], o1 = acc[mi][ni][1];
                const float o2 = acc[mi][ni][2], o3 = acc[mi][ni][3];
                const int r0 = m0 + lr0, r1 = m0 + lr1;
                const size_t c = (size_t)(n0 + lc);
                *(float2*)(OutF + ob + (size_t)r0 * NQ + c) =
                    make_float2(eA.x + o0, eA.y + o1);
                *(float2*)(OutF + ob + (size_t)(2047 - r0) * NQ + c) =
                    make_float2(o0 - eA.x, o1 - eA.y);
                *(float2*)(OutF + ob + (size_t)r1 * NQ + c) =
                    make_float2(eB.x + o2, eB.y + o3);
                *(float2*)(OutF + ob + (size_t)(2047 - r1) * NQ + c) =
                    make_float2(o2 - eB.x, o3 - eB.y);
            }
        return;
    }

    // EPI == 2: O1-combine. Transpose staging reuses buffers 0 and 2 —
    // must be globally dead, so one block barrier here.
    __syncthreads();
#pragma unroll
    for (int mi = 0; mi < 4; ++mi)
#pragma unroll
        for (int ni = 0; ni < 8; ++ni) {
            const int lr0 = wm * 64 + mi * 16 + rq, lr1 = lr0 + 8;
            const int lc = wn * 64 + ni * 8 + cq;
            const float2 eA = __half22float2(rde16(smem, pboff, lr0, lc));
            const float2 eB = __half22float2(rde16(smem, pboff, lr1, lc));
            const float o0 = acc[mi][ni][0], o1 = acc[mi][ni][1];
            const float o2 = acc[mi][ni][2], o3 = acc[mi][ni][3];
            const int pe_l = (lc >> 1);
            const int par = pe_l & 1;
            const int jl = pe_l >> 1;
            const uint32_t te0 = (uint32_t)(par ? 8192 : 0) + (uint32_t)lr0 * 64 +
                (uint32_t)(((jl >> 3) ^ (lr0 & 3)) << 4) + (uint32_t)((jl & 7) << 1);
            const uint32_t te1 = (uint32_t)(par ? 8192 : 0) + (uint32_t)lr1 * 64 +
                (uint32_t)(((jl >> 3) ^ (lr1 & 3)) << 4) + (uint32_t)((jl & 7) << 1);
            const uint32_t to0 = 16384u + (uint32_t)lr0 * 128 +
                (uint32_t)(((pe_l >> 3) ^ (lr0 & 7)) << 4) + (uint32_t)((pe_l & 7) << 1);
            const uint32_t to1 = 16384u + (uint32_t)lr1 * 128 +
                (uint32_t)(((pe_l >> 3) ^ (lr1 & 7)) << 4) + (uint32_t)((pe_l & 7) << 1);
            *(h16*)(smem + te0) = __float2half(eA.x + o0);
            *(h16*)(smem + to0) = __float2half(eA.y + o1);
            *(h16*)(smem + te1) = __float2half(eB.x + o2);
            *(h16*)(smem + to1) = __float2half(eB.y + o3);
            *(h16*)(smem + 2 * STG_BYTES + te0) = __float2half(eA.x - o0);
            *(h16*)(smem + 2 * STG_BYTES + to0) = __float2half(eA.y - o1);
            *(h16*)(smem + 2 * STG_BYTES + te1) = __float2half(eB.x - o2);
            *(h16*)(smem + 2 * STG_BYTES + to1) = __float2half(eB.y - o3);
        }
    __syncthreads();
    {
        const size_t tbq = (size_t)b * NQ * KQ;
        const size_t tbh = (size_t)b * NQ * KH;
#pragma unroll
        for (int j = 0; j < 32; ++j) {
            const int cg = tid + 128 * j;
            const int halfsel = cg >> 11;
            const int within = cg & 2047;
            const uint32_t hbase = halfsel ? 2u * STG_BYTES : 0u;
            if (within < 1024) {
                const int pl = within >> 9;
                const int w2 = within & 511;
                const int row = w2 >> 2, s = w2 & 3;
                const uint32_t soff = hbase + (uint32_t)(pl ? 8192 : 0) +
                    (uint32_t)row * 64 + (uint32_t)((s ^ (row & 3)) << 4);
                const uint4 v = *(const uint4*)(smem + soff);
                const int vg = halfsel ? (2047 - (m0 + row)) : (m0 + row);
                h16* dst = (pl ? Teo : Tee) + tbq + (size_t)vg * KQ
                         + (n0 >> 2) + s * 8;
                *(uint4*)dst = v;
            } else {
                const int w2 = within - 1024;
                const int row = w2 >> 3, s = w2 & 7;
                const uint32_t soff = hbase + 16384u +
                    (uint32_t)row * 128 + (uint32_t)((s ^ (row & 7)) << 4);
                const uint4 v = *(const uint4*)(smem + soff);
                const int vg = halfsel ? (2047 - (m0 + row)) : (m0 + row);
                h16* dst = To + tbh + (size_t)vg * KH + (n0 >> 1) + s * 8;
                *(uint4*)dst = v;
            }
        }
    }
#undef PREF_E
#undef LOAD_STG
}

// ---------------- launch ----------------
extern "C" void kernel_launch(void* const* d_in, const int* in_sizes, int n_in,
                              void* d_out, int out_size) {
    const float* x = (const float*)d_in[0];
    float* out = (float*)d_out;

    h16 *pCee, *pCeo, *pSee, *pSeo, *pCo, *pSo;
    h16 *pXee, *pXeo, *pXo, *pTee, *pTeo, *pTo, *pE, *pEE;
    cudaGetSymbolAddress((void**)&pCee, g_Cee);
    cudaGetSymbolAddress((void**)&pCeo, g_Ceo);
    cudaGetSymbolAddress((void**)&pSee, g_See);
    cudaGetSymbolAddress((void**)&pSeo, g_Seo);
    cudaGetSymbolAddress((void**)&pCo,  g_Co);
    cudaGetSymbolAddress((void**)&pSo,  g_So);
    cudaGetSymbolAddress((void**)&pXee, g_Xee);
    cudaGetSymbolAddress((void**)&pXeo, g_Xeo);
    cudaGetSymbolAddress((void**)&pXo,  g_Xo);
    cudaGetSymbolAddress((void**)&pTee, g_Tee);
    cudaGetSymbolAddress((void**)&pTeo, g_Teo);
    cudaGetSymbolAddress((void**)&pTo,  g_To);
    cudaGetSymbolAddress((void**)&pE,   g_E16);
    cudaGetSymbolAddress((void**)&pEE,  g_EE16);

    cudaFuncSetAttribute(gemm_k<512, 0, 0>,  cudaFuncAttributeMaxDynamicSharedMemorySize, SMEM_TOTAL);
    cudaFuncSetAttribute(gemm_k<512, 1, 0>,  cudaFuncAttributeMaxDynamicSharedMemorySize, SMEM_TOTAL);
    cudaFuncSetAttribute(gemm_k<512, 1, 1>,  cudaFuncAttributeMaxDynamicSharedMemorySize, SMEM_TOTAL);
    cudaFuncSetAttribute(gemm_k<1024, 2, 0>, cudaFuncAttributeMaxDynamicSharedMemorySize, SMEM_TOTAL);
    cudaFuncSetAttribute(gemm_k<1024, 3, 0>, cudaFuncAttributeMaxDynamicSharedMemorySize, SMEM_TOTAL);

    const dim3 gridQ(16, 4, NB);   // M=512 kernels: 256 CTAs (single wave)
    const dim3 gridH(16, 8, NB);   // M=1024 kernels: 512 CTAs

    // 1) fused prologue: x 3-way split + six basis matrices
    prologue_kernel<<<SPLIT_BLOCKS + BASIS_BLOCKS, 256>>>(x);

    // 2) Stage 1
    gemm_k<512, 0, 0><<<gridQ, 128, SMEM_TOTAL>>>(      // EE1 -> EE16
        pCee, pXee, pEE, nullptr, nullptr, nullptr, nullptr, nullptr);
    gemm_k<512, 1, 0><<<gridQ, 128, SMEM_TOTAL>>>(      // EO1; E1 = EE±EO -> E16
        pCeo, pXeo, pEE, pE, nullptr, nullptr, nullptr, nullptr);
    gemm_k<1024, 2, 0><<<gridH, 128, SMEM_TOTAL>>>(     // O1; -> Tee/Teo/To
        pCo, pXo, nullptr, pE, pTee, pTeo, pTo, nullptr);

    // 3) Stage 2
    gemm_k<512, 0, 0><<<gridQ, 128, SMEM_TOTAL>>>(      // EE2 -> EE16
        pSee, pTee, pEE, nullptr, nullptr, nullptr, nullptr, nullptr);
    gemm_k<512, 1, 1><<<gridQ, 128, SMEM_TOTAL>>>(      // EO2; E2 = EO±EE -> E16
        pSeo, pTeo, pEE, pE, nullptr, nullptr, nullptr, nullptr);
    gemm_k<1024, 3, 0><<<gridH, 128, SMEM_TOTAL>>>(     // O2; -> out
        pSo, pTo, nullptr, pE, nullptr, nullptr, nullptr, out);
}